// round 1
// baseline (speedup 1.0000x reference)
#include <cuda_runtime.h>
#include <math.h>

#define TT   32768
#define HH   1024
#define DIN  16
#define ACD  32
#define NHH  12
#define KDIM 768
#define VDIM 1536
#define HKD  64
#define HVD  128
#define NSEG 16

// ---------------- scratch (static device globals; no allocation) ----------------
static __device__ float  d_hn   [TT * HH];     // normalized hidden, 134MB
static __device__ float  d_kpre [TT * KDIM];   // hn@Wk pre-conv
static __device__ float  d_vpre [TT * VDIM];   // hn@Wv pre-conv
static __device__ float  d_k    [TT * KDIM];   // post conv+silu+l2norm
static __device__ float  d_v    [TT * VDIM];   // post conv+silu
static __device__ float2 d_db   [TT * NHH];    // (decay=exp(g), beta)
static __device__ int    d_seg  [TT];
static __device__ int    d_flags[TT];          // bit0 = segment start, bits>=1 = pooled index+1
static __device__ float  d_hrows[NSEG * HH];   // residual rows at pooled positions
static __device__ float  d_q    [NSEG * KDIM]; // q (l2normed * scale) at pooled positions
static __device__ float  d_o    [NSEG * VDIM]; // scan outputs at pooled positions
static __device__ float  d_og   [NSEG * VDIM]; // o after norm+gating
static __device__ float  d_wowh [VDIM];        // Wo @ W_head

__device__ __forceinline__ float sigmoidf_(float x) { return 1.f / (1.f + expf(-x)); }

// ---------------- seg ids + flags ----------------
__global__ void k_prep(const int* __restrict__ cu) {
    int t = blockIdx.x * 256 + threadIdx.x;
    if (t >= TT) return;
    int seg = 0;
#pragma unroll
    for (int s = 1; s <= NSEG; ++s) if (t >= cu[s]) seg = s;
    d_seg[t] = seg;
    int fl = (t == cu[seg]) ? 1 : 0;
#pragma unroll
    for (int s = 0; s < NSEG; ++s) if (t == cu[s + 1] - 1) fl |= ((s + 1) << 1);
    d_flags[t] = fl;
}

// ---------------- embed ([x|ac] @ W_in + b) + rmsnorm, 8 rows / block ----------------
__global__ void k_embed(const float* __restrict__ x, const int* __restrict__ acidx,
                        const float* __restrict__ actab, const float* __restrict__ Win,
                        const float* __restrict__ bin, const float* __restrict__ nw) {
    __shared__ float sx[8][48];
    __shared__ float sps[8][256];
    __shared__ float srms[8];
    int t0 = blockIdx.x * 8;
    int tid = threadIdx.x;
    for (int idx = tid; idx < 8 * 48; idx += 256) {
        int r = idx / 48, i = idx % 48;
        int t = t0 + r;
        float v;
        if (i < DIN) v = x[t * DIN + i];
        else v = actab[acidx[d_seg[t]] * ACD + (i - DIN)];
        sx[r][i] = v;
    }
    __syncthreads();

    float hreg[4][8];
    float ps[8];
#pragma unroll
    for (int r = 0; r < 8; ++r) ps[r] = 0.f;

#pragma unroll
    for (int jj = 0; jj < 4; ++jj) {
        int j = tid + jj * 256;
        float acc[8];
        float bb = bin[j];
#pragma unroll
        for (int r = 0; r < 8; ++r) acc[r] = bb;
        for (int i = 0; i < 48; ++i) {
            float w = Win[i * HH + j];
#pragma unroll
            for (int r = 0; r < 8; ++r) acc[r] = fmaf(sx[r][i], w, acc[r]);
        }
#pragma unroll
        for (int r = 0; r < 8; ++r) { hreg[jj][r] = acc[r]; ps[r] = fmaf(acc[r], acc[r], ps[r]); }
    }
#pragma unroll
    for (int r = 0; r < 8; ++r) sps[r][tid] = ps[r];
    __syncthreads();
    int w = tid >> 5, lane = tid & 31;
    float s = sps[w][lane];
#pragma unroll
    for (int i = 1; i < 8; ++i) s += sps[w][lane + 32 * i];
#pragma unroll
    for (int off = 16; off; off >>= 1) s += __shfl_xor_sync(0xffffffffu, s, off);
    if (lane == 0) srms[w] = rsqrtf(s / (float)HH + 1e-6f);
    __syncthreads();

    int needr[8];
#pragma unroll
    for (int r = 0; r < 8; ++r) needr[r] = d_flags[t0 + r] >> 1;

#pragma unroll
    for (int jj = 0; jj < 4; ++jj) {
        int j = tid + jj * 256;
        float nwj = 1.0f + nw[j];
#pragma unroll
        for (int r = 0; r < 8; ++r) {
            int t = t0 + r;
            d_hn[t * HH + j] = hreg[jj][r] * srms[r] * nwj;
            if (needr[r]) d_hrows[(needr[r] - 1) * HH + j] = hreg[jj][r];
        }
    }
}

// ---------------- fp32 SIMT GEMM: C[T x N] = d_hn[T x 1024] @ B[1024 x N] ----------------
// 128x128 tile, BK=8, 256 threads, 8x8 per thread.  which: 0 -> d_kpre, 1 -> d_vpre
__global__ void __launch_bounds__(256) k_sgemm(const float* __restrict__ B, int N, int which) {
    __shared__ float As[8][132];
    __shared__ float Bs[8][128];
    const float* A = d_hn;
    float* C = which ? d_vpre : d_kpre;
    const int K = HH;
    int tid = threadIdx.x;
    int rowBase = blockIdx.y * 128;
    int colBase = blockIdx.x * 128;
    int aRow = tid >> 1;
    int aCol = (tid & 1) << 2;
    int bRow = tid >> 5;
    int bCol = (tid & 31) << 2;
    int ty = tid >> 4, tx = tid & 15;
    float acc[8][8];
#pragma unroll
    for (int i = 0; i < 8; i++)
#pragma unroll
        for (int j = 0; j < 8; j++) acc[i][j] = 0.f;

    const float* Aptr = A + (size_t)(rowBase + aRow) * K + aCol;
    const float* Bptr = B + (size_t)bRow * N + colBase + bCol;

    for (int k0 = 0; k0 < K; k0 += 8) {
        float4 av = *(const float4*)(Aptr + k0);
        float4 bv = *(const float4*)(Bptr + (size_t)k0 * N);
        __syncthreads();
        As[aCol + 0][aRow] = av.x;
        As[aCol + 1][aRow] = av.y;
        As[aCol + 2][aRow] = av.z;
        As[aCol + 3][aRow] = av.w;
        *(float4*)&Bs[bRow][bCol] = bv;
        __syncthreads();
#pragma unroll
        for (int kk = 0; kk < 8; kk++) {
            float a[8], b[8];
#pragma unroll
            for (int i = 0; i < 8; i++) a[i] = As[kk][ty * 8 + i];
#pragma unroll
            for (int j = 0; j < 8; j++) b[j] = Bs[kk][tx * 8 + j];
#pragma unroll
            for (int i = 0; i < 8; i++)
#pragma unroll
                for (int j = 0; j < 8; j++) acc[i][j] = fmaf(a[i], b[j], acc[i][j]);
        }
    }
#pragma unroll
    for (int i = 0; i < 8; i++) {
        int r = rowBase + ty * 8 + i;
        float* cp = C + (size_t)r * N + colBase + tx * 8;
        float4 v0 = make_float4(acc[i][0], acc[i][1], acc[i][2], acc[i][3]);
        float4 v1 = make_float4(acc[i][4], acc[i][5], acc[i][6], acc[i][7]);
        *(float4*)cp = v0;
        *(float4*)(cp + 4) = v1;
    }
}

// ---------------- hn@Wa, hn@Wb -> decay/beta (one warp per token) ----------------
__global__ void k_ab(const float* __restrict__ Wa, const float* __restrict__ Wb,
                     const float* __restrict__ Alog, const float* __restrict__ dtb) {
    int row = blockIdx.x * 8 + (threadIdx.x >> 5);
    int lane = threadIdx.x & 31;
    float aA[NHH], aB[NHH];
#pragma unroll
    for (int c = 0; c < NHH; ++c) { aA[c] = 0.f; aB[c] = 0.f; }
    for (int kk = lane; kk < HH; kk += 32) {
        float hv = d_hn[(size_t)row * HH + kk];
        const float* wa = Wa + kk * NHH;
        const float* wb = Wb + kk * NHH;
#pragma unroll
        for (int c = 0; c < NHH; ++c) {
            aA[c] = fmaf(hv, wa[c], aA[c]);
            aB[c] = fmaf(hv, wb[c], aB[c]);
        }
    }
#pragma unroll
    for (int c = 0; c < NHH; ++c) {
#pragma unroll
        for (int off = 16; off; off >>= 1) {
            aA[c] += __shfl_xor_sync(0xffffffffu, aA[c], off);
            aB[c] += __shfl_xor_sync(0xffffffffu, aB[c], off);
        }
    }
    if (lane < NHH) {
        float xx = aA[lane] + dtb[lane];
        float sp = (xx > 20.f) ? xx : log1pf(expf(xx));
        float g = -expf(Alog[lane]) * sp;
        float2 db;
        db.x = expf(g);                 // decay
        db.y = sigmoidf_(aB[lane]);     // beta
        d_db[(size_t)row * NHH + lane] = db;
    }
}

// ---------------- short conv + silu (+ per-head l2norm for k) ----------------
// which: 0 -> k path (C=768, HD=64, norm), 1 -> v path (C=1536, HD=128, no norm)
__global__ void k_conv(const float* __restrict__ cw, int which) {
    __shared__ float sv[VDIM];
    const float* in = which ? d_vpre : d_kpre;
    float* out = which ? d_v : d_k;
    const int C = which ? VDIM : KDIM;
    const int HD = which ? HVD : HKD;
    const int doNorm = which ? 0 : 1;

    int t = blockIdx.x;
    int tid = threadIdx.x;
    int seg = d_seg[t];
    int m1 = (t >= 1 && d_seg[t - 1] == seg);
    int m2 = (t >= 2 && d_seg[t - 2] == seg);
    int m3 = (t >= 3 && d_seg[t - 3] == seg);

    for (int c = tid; c < C; c += 256) {
        float w0 = cw[c * 4 + 0], w1 = cw[c * 4 + 1], w2 = cw[c * 4 + 2], w3 = cw[c * 4 + 3];
        float acc = in[(size_t)t * C + c] * w3;
        if (m1) acc = fmaf(in[(size_t)(t - 1) * C + c], w2, acc);
        if (m2) acc = fmaf(in[(size_t)(t - 2) * C + c], w1, acc);
        if (m3) acc = fmaf(in[(size_t)(t - 3) * C + c], w0, acc);
        float val = acc * sigmoidf_(acc);
        if (doNorm) sv[c] = val;
        else out[(size_t)t * C + c] = val;
    }
    if (doNorm) {
        __syncthreads();
        int w = tid >> 5, lane = tid & 31;
        for (int h = w; h < NHH; h += 8) {
            float ssq = 0.f;
            for (int i = lane; i < HD; i += 32) { float v = sv[h * HD + i]; ssq = fmaf(v, v, ssq); }
#pragma unroll
            for (int off = 16; off; off >>= 1) ssq += __shfl_xor_sync(0xffffffffu, ssq, off);
            float r = rsqrtf(ssq + 1e-6f);
            for (int i = lane; i < HD; i += 32)
                out[(size_t)t * C + h * HD + i] = sv[h * HD + i] * r;
        }
    }
}

// ---------------- q at the 16 pooled positions: hn@Wq (4 rows) -> conv -> silu -> l2norm -> *scale ----------------
__global__ void k_q16(const int* __restrict__ cu, const float* __restrict__ Wq,
                      const float* __restrict__ cw) {
    __shared__ float shn[4][HH];
    __shared__ float sq[KDIM];
    int s = blockIdx.x;
    int pos = cu[s + 1] - 1;
    int seg = d_seg[pos];
    int tid = threadIdx.x;
    int valid[4];
#pragma unroll
    for (int r = 0; r < 4; ++r) {
        int t = pos - r;
        valid[r] = (t >= 0 && d_seg[t] == seg);
    }
#pragma unroll
    for (int r = 0; r < 4; ++r) {
        int t = pos - r;
        if (valid[r]) for (int i = tid; i < HH; i += 256) shn[r][i] = d_hn[(size_t)t * HH + i];
        else          for (int i = tid; i < HH; i += 256) shn[r][i] = 0.f;
    }
    __syncthreads();
    for (int c = tid; c < KDIM; c += 256) {
        float a0 = 0.f, a1 = 0.f, a2 = 0.f, a3 = 0.f;
        for (int i = 0; i < HH; ++i) {
            float wv = Wq[(size_t)i * KDIM + c];
            a0 = fmaf(shn[0][i], wv, a0);
            a1 = fmaf(shn[1][i], wv, a1);
            a2 = fmaf(shn[2][i], wv, a2);
            a3 = fmaf(shn[3][i], wv, a3);
        }
        float acc = a0 * cw[c * 4 + 3] + a1 * cw[c * 4 + 2] + a2 * cw[c * 4 + 1] + a3 * cw[c * 4 + 0];
        sq[c] = acc * sigmoidf_(acc);
    }
    __syncthreads();
    int w = tid >> 5, lane = tid & 31;
    for (int h = w; h < NHH; h += 8) {
        float ssq = 0.f;
        for (int i = lane; i < HKD; i += 32) { float v = sq[h * HKD + i]; ssq = fmaf(v, v, ssq); }
#pragma unroll
        for (int off = 16; off; off >>= 1) ssq += __shfl_xor_sync(0xffffffffu, ssq, off);
        float r = rsqrtf(ssq + 1e-6f) * 0.125f;   // l2norm * HK^-0.5
        for (int i = lane; i < HKD; i += 32)
            d_q[s * KDIM + h * HKD + i] = sq[h * HKD + i] * r;
    }
}

// ---------------- sequential scan; 48 blocks = 12 heads x 4 column-groups ----------------
// block: 256 threads = 32 columns x 8 lanes; each lane owns 8 of the 64 k-rows of its column
__global__ void __launch_bounds__(256, 1) k_scan() {
    int h = blockIdx.x >> 2;
    int cg = blockIdx.x & 3;
    int tid = threadIdx.x;
    int colL = tid >> 3;
    int e = tid & 7;
    int col = cg * 32 + colL;

    float S[8];
#pragma unroll
    for (int i = 0; i < 8; ++i) S[i] = 0.f;

    const float4* kb = (const float4*)d_k;
    const int kstep = KDIM / 4;          // 192 float4 per row
    const int kidx = h * (HKD / 4) + e * 2;

    float4 ka = kb[kidx];
    float4 ka2 = kb[kidx + 1];
    float vv = d_v[(size_t)h * HVD + col];
    float2 db = d_db[h];
    int fl = d_flags[0];

    for (int t = 0; t < TT; ++t) {
        int tn = (t + 1 < TT) ? t + 1 : t;
        float4 na = kb[(size_t)tn * kstep + kidx];
        float4 na2 = kb[(size_t)tn * kstep + kidx + 1];
        float nv = d_v[(size_t)tn * VDIM + h * HVD + col];
        float2 ndb = d_db[(size_t)tn * NHH + h];
        int nfl = d_flags[tn];

        float lam = (fl & 1) ? 0.f : db.x;

        float dot = S[0] * ka.x;
        dot = fmaf(S[1], ka.y, dot);
        dot = fmaf(S[2], ka.z, dot);
        dot = fmaf(S[3], ka.w, dot);
        float dot2 = S[4] * ka2.x;
        dot2 = fmaf(S[5], ka2.y, dot2);
        dot2 = fmaf(S[6], ka2.z, dot2);
        dot2 = fmaf(S[7], ka2.w, dot2);
        dot += dot2;
        dot += __shfl_xor_sync(0xffffffffu, dot, 1);
        dot += __shfl_xor_sync(0xffffffffu, dot, 2);
        dot += __shfl_xor_sync(0xffffffffu, dot, 4);

        float delta = db.y * (vv - lam * dot);

        S[0] = fmaf(lam, S[0], ka.x * delta);
        S[1] = fmaf(lam, S[1], ka.y * delta);
        S[2] = fmaf(lam, S[2], ka.z * delta);
        S[3] = fmaf(lam, S[3], ka.w * delta);
        S[4] = fmaf(lam, S[4], ka2.x * delta);
        S[5] = fmaf(lam, S[5], ka2.y * delta);
        S[6] = fmaf(lam, S[6], ka2.z * delta);
        S[7] = fmaf(lam, S[7], ka2.w * delta);

        int need = fl >> 1;
        if (need) {
            const float4* qb = (const float4*)d_q;
            int qi = (need - 1) * kstep + h * (HKD / 4) + e * 2;
            float4 qa = qb[qi];
            float4 qa2 = qb[qi + 1];
            float od = S[0] * qa.x;
            od = fmaf(S[1], qa.y, od);
            od = fmaf(S[2], qa.z, od);
            od = fmaf(S[3], qa.w, od);
            od = fmaf(S[4], qa2.x, od);
            od = fmaf(S[5], qa2.y, od);
            od = fmaf(S[6], qa2.z, od);
            od = fmaf(S[7], qa2.w, od);
            od += __shfl_xor_sync(0xffffffffu, od, 1);
            od += __shfl_xor_sync(0xffffffffu, od, 2);
            od += __shfl_xor_sync(0xffffffffu, od, 4);
            if (e == 0) d_o[(need - 1) * VDIM + h * HVD + col] = od;
        }

        ka = na; ka2 = na2; vv = nv; db = ndb; fl = nfl;
    }
}

// ---------------- Wo @ W_head (1536-vector) ----------------
__global__ void k_wowh(const float* __restrict__ Wo, const float* __restrict__ Wh) {
    int j = blockIdx.x * 8 + (threadIdx.x >> 5);
    int lane = threadIdx.x & 31;
    float a = 0.f;
    for (int k = lane; k < HH; k += 32) a = fmaf(Wo[(size_t)j * HH + k], Wh[k], a);
#pragma unroll
    for (int off = 16; off; off >>= 1) a += __shfl_xor_sync(0xffffffffu, a, off);
    if (lane == 0) d_wowh[j] = a;
}

// ---------------- per (head, pooled pos): group-rms-norm o, gate = hn@Wg, silu gating ----------------
__global__ void k_gate(const int* __restrict__ cu, const float* __restrict__ Wg,
                       const float* __restrict__ onw) {
    __shared__ float shn[HH];
    __shared__ float sred[128];
    int hd = blockIdx.x;
    int s = blockIdx.y;
    int pos = cu[s + 1] - 1;
    int tid = threadIdx.x;   // 128
    for (int i = tid; i < HH; i += 128) shn[i] = d_hn[(size_t)pos * HH + i];
    __syncthreads();
    float gate = 0.f;
    for (int i = 0; i < HH; ++i)
        gate = fmaf(shn[i], Wg[(size_t)i * VDIM + hd * HVD + tid], gate);
    float ov = d_o[s * VDIM + hd * HVD + tid];
    sred[tid] = ov * ov;
    __syncthreads();
    for (int st = 64; st; st >>= 1) {
        if (tid < st) sred[tid] += sred[tid + st];
        __syncthreads();
    }
    float rms = rsqrtf(sred[0] / (float)HVD + 1e-5f);
    float gs = gate * sigmoidf_(gate);
    d_og[s * VDIM + hd * HVD + tid] = ov * rms * onw[tid] * gs;
}

// ---------------- out[s] = og . wowh + hrow . W_head + b_head ----------------
__global__ void k_final(const float* __restrict__ Wh, const float* __restrict__ bh,
                        float* __restrict__ out) {
    __shared__ float sred[256];
    int s = blockIdx.x;
    int tid = threadIdx.x;
    float a = 0.f;
    for (int j = tid; j < VDIM; j += 256) a = fmaf(d_og[s * VDIM + j], d_wowh[j], a);
    for (int k = tid; k < HH; k += 256) a = fmaf(d_hrows[s * HH + k], Wh[k], a);
    sred[tid] = a;
    __syncthreads();
    for (int st = 128; st; st >>= 1) {
        if (tid < st) sred[tid] += sred[tid + st];
        __syncthreads();
    }
    if (tid == 0) out[s] = sred[0] + bh[0];
}

// ---------------- launch ----------------
extern "C" void kernel_launch(void* const* d_in, const int* in_sizes, int n_in,
                              void* d_out, int out_size) {
    const float* x     = (const float*)d_in[0];
    const int*   cu    = (const int*)d_in[1];
    const int*   acidx = (const int*)d_in[2];
    const float* actab = (const float*)d_in[3];
    const float* Win   = (const float*)d_in[4];
    const float* bin   = (const float*)d_in[5];
    const float* nw    = (const float*)d_in[6];
    const float* Wq    = (const float*)d_in[7];
    const float* Wk    = (const float*)d_in[8];
    const float* Wv    = (const float*)d_in[9];
    const float* cqw   = (const float*)d_in[10];
    const float* ckw   = (const float*)d_in[11];
    const float* cvw   = (const float*)d_in[12];
    const float* Wb    = (const float*)d_in[13];
    const float* Wa    = (const float*)d_in[14];
    const float* Alog  = (const float*)d_in[15];
    const float* dtb   = (const float*)d_in[16];
    const float* Wg    = (const float*)d_in[17];
    const float* onw   = (const float*)d_in[18];
    const float* Wo    = (const float*)d_in[19];
    const float* Wh    = (const float*)d_in[20];
    const float* bh    = (const float*)d_in[21];
    float* out = (float*)d_out;

    k_prep<<<TT / 256, 256>>>(cu);
    k_embed<<<TT / 8, 256>>>(x, acidx, actab, Win, bin, nw);

    dim3 gk(KDIM / 128, TT / 128);
    k_sgemm<<<gk, 256>>>(Wk, KDIM, 0);
    dim3 gv(VDIM / 128, TT / 128);
    k_sgemm<<<gv, 256>>>(Wv, VDIM, 1);

    k_ab<<<TT / 8, 256>>>(Wa, Wb, Alog, dtb);
    k_conv<<<TT, 256>>>(ckw, 0);
    k_conv<<<TT, 256>>>(cvw, 1);
    k_q16<<<NSEG, 256>>>(cu, Wq, cqw);

    k_scan<<<48, 256>>>();

    k_wowh<<<VDIM / 8, 256>>>(Wo, Wh);
    k_gate<<<dim3(NHH, NSEG), 128>>>(cu, Wg, onw);
    k_final<<<NSEG, 256>>>(Wh, bh, out);
}

// round 2
// speedup vs baseline: 3.4805x; 3.4805x over previous
#include <cuda_runtime.h>
#include <math.h>

#define TT   32768
#define HH   1024
#define DIN  16
#define ACD  32
#define NHH  12
#define KDIM 768
#define VDIM 1536
#define HKD  64
#define HVD  128
#define NSEG 16
#define SCH  40      // scan chunk (timesteps staged per smem buffer)

// ---------------- scratch (static device globals; no allocation) ----------------
static __device__ float  d_hn   [TT * HH];
static __device__ float  d_kpre [TT * KDIM];
static __device__ float  d_vpre [TT * VDIM];
static __device__ float  d_k    [TT * KDIM];
static __device__ float  d_v    [TT * VDIM];
static __device__ float2 d_db   [TT * NHH];
static __device__ int    d_seg  [TT];
static __device__ int    d_flags[TT];
static __device__ float  d_hrows[NSEG * HH];
static __device__ float  d_q    [NSEG * KDIM];
static __device__ float  d_o    [NSEG * VDIM];
static __device__ float  d_og   [NSEG * VDIM];
static __device__ float  d_wowh [VDIM];

__device__ __forceinline__ float sigmoidf_(float x) { return 1.f / (1.f + expf(-x)); }

__device__ __forceinline__ void cpa16(void* s, const void* g) {
    unsigned sa = (unsigned)__cvta_generic_to_shared(s);
    asm volatile("cp.async.ca.shared.global [%0], [%1], 16;" :: "r"(sa), "l"(g));
}
__device__ __forceinline__ void cpa8(void* s, const void* g) {
    unsigned sa = (unsigned)__cvta_generic_to_shared(s);
    asm volatile("cp.async.ca.shared.global [%0], [%1], 8;" :: "r"(sa), "l"(g));
}
__device__ __forceinline__ void cpa4(void* s, const void* g) {
    unsigned sa = (unsigned)__cvta_generic_to_shared(s);
    asm volatile("cp.async.ca.shared.global [%0], [%1], 4;" :: "r"(sa), "l"(g));
}
#define CPA_COMMIT asm volatile("cp.async.commit_group;")
#define CPA_WAIT1  asm volatile("cp.async.wait_group 1;")

// ---------------- seg ids + flags ----------------
__global__ void k_prep(const int* __restrict__ cu) {
    int t = blockIdx.x * 256 + threadIdx.x;
    if (t >= TT) return;
    int seg = 0;
#pragma unroll
    for (int s = 1; s <= NSEG; ++s) if (t >= cu[s]) seg = s;
    d_seg[t] = seg;
    int fl = (t == cu[seg]) ? 1 : 0;
#pragma unroll
    for (int s = 0; s < NSEG; ++s) if (t == cu[s + 1] - 1) fl |= ((s + 1) << 1);
    d_flags[t] = fl;
}

// ---------------- embed ([x|ac] @ W_in + b) + rmsnorm, 8 rows / block ----------------
__global__ void k_embed(const float* __restrict__ x, const int* __restrict__ acidx,
                        const float* __restrict__ actab, const float* __restrict__ Win,
                        const float* __restrict__ bin, const float* __restrict__ nw) {
    __shared__ float sx[8][48];
    __shared__ float sps[8][256];
    __shared__ float srms[8];
    int t0 = blockIdx.x * 8;
    int tid = threadIdx.x;
    for (int idx = tid; idx < 8 * 48; idx += 256) {
        int r = idx / 48, i = idx % 48;
        int t = t0 + r;
        float v;
        if (i < DIN) v = x[t * DIN + i];
        else v = actab[acidx[d_seg[t]] * ACD + (i - DIN)];
        sx[r][i] = v;
    }
    __syncthreads();

    float hreg[4][8];
    float ps[8];
#pragma unroll
    for (int r = 0; r < 8; ++r) ps[r] = 0.f;

#pragma unroll
    for (int jj = 0; jj < 4; ++jj) {
        int j = tid + jj * 256;
        float acc[8];
        float bb = bin[j];
#pragma unroll
        for (int r = 0; r < 8; ++r) acc[r] = bb;
        for (int i = 0; i < 48; ++i) {
            float w = Win[i * HH + j];
#pragma unroll
            for (int r = 0; r < 8; ++r) acc[r] = fmaf(sx[r][i], w, acc[r]);
        }
#pragma unroll
        for (int r = 0; r < 8; ++r) { hreg[jj][r] = acc[r]; ps[r] = fmaf(acc[r], acc[r], ps[r]); }
    }
#pragma unroll
    for (int r = 0; r < 8; ++r) sps[r][tid] = ps[r];
    __syncthreads();
    int w = tid >> 5, lane = tid & 31;
    float s = sps[w][lane];
#pragma unroll
    for (int i = 1; i < 8; ++i) s += sps[w][lane + 32 * i];
#pragma unroll
    for (int off = 16; off; off >>= 1) s += __shfl_xor_sync(0xffffffffu, s, off);
    if (lane == 0) srms[w] = rsqrtf(s / (float)HH + 1e-6f);
    __syncthreads();

    int needr[8];
#pragma unroll
    for (int r = 0; r < 8; ++r) needr[r] = d_flags[t0 + r] >> 1;

#pragma unroll
    for (int jj = 0; jj < 4; ++jj) {
        int j = tid + jj * 256;
        float nwj = 1.0f + nw[j];
#pragma unroll
        for (int r = 0; r < 8; ++r) {
            int t = t0 + r;
            d_hn[t * HH + j] = hreg[jj][r] * srms[r] * nwj;
            if (needr[r]) d_hrows[(needr[r] - 1) * HH + j] = hreg[jj][r];
        }
    }
}

// ---------------- fp32 SIMT GEMM: C[T x N] = d_hn[T x 1024] @ B[1024 x N] ----------------
__global__ void __launch_bounds__(256) k_sgemm(const float* __restrict__ B, int N, int which) {
    __shared__ float As[8][132];
    __shared__ float Bs[8][128];
    const float* A = d_hn;
    float* C = which ? d_vpre : d_kpre;
    const int K = HH;
    int tid = threadIdx.x;
    int rowBase = blockIdx.y * 128;
    int colBase = blockIdx.x * 128;
    int aRow = tid >> 1;
    int aCol = (tid & 1) << 2;
    int bRow = tid >> 5;
    int bCol = (tid & 31) << 2;
    int ty = tid >> 4, tx = tid & 15;
    float acc[8][8];
#pragma unroll
    for (int i = 0; i < 8; i++)
#pragma unroll
        for (int j = 0; j < 8; j++) acc[i][j] = 0.f;

    const float* Aptr = A + (size_t)(rowBase + aRow) * K + aCol;
    const float* Bptr = B + (size_t)bRow * N + colBase + bCol;

    for (int k0 = 0; k0 < K; k0 += 8) {
        float4 av = *(const float4*)(Aptr + k0);
        float4 bv = *(const float4*)(Bptr + (size_t)k0 * N);
        __syncthreads();
        As[aCol + 0][aRow] = av.x;
        As[aCol + 1][aRow] = av.y;
        As[aCol + 2][aRow] = av.z;
        As[aCol + 3][aRow] = av.w;
        *(float4*)&Bs[bRow][bCol] = bv;
        __syncthreads();
#pragma unroll
        for (int kk = 0; kk < 8; kk++) {
            float a[8], b[8];
#pragma unroll
            for (int i = 0; i < 8; i++) a[i] = As[kk][ty * 8 + i];
#pragma unroll
            for (int j = 0; j < 8; j++) b[j] = Bs[kk][tx * 8 + j];
#pragma unroll
            for (int i = 0; i < 8; i++)
#pragma unroll
                for (int j = 0; j < 8; j++) acc[i][j] = fmaf(a[i], b[j], acc[i][j]);
        }
    }
#pragma unroll
    for (int i = 0; i < 8; i++) {
        int r = rowBase + ty * 8 + i;
        float* cp = C + (size_t)r * N + colBase + tx * 8;
        float4 v0 = make_float4(acc[i][0], acc[i][1], acc[i][2], acc[i][3]);
        float4 v1 = make_float4(acc[i][4], acc[i][5], acc[i][6], acc[i][7]);
        *(float4*)cp = v0;
        *(float4*)(cp + 4) = v1;
    }
}

// ---------------- hn@Wa, hn@Wb -> decay/beta (one warp per token) ----------------
__global__ void k_ab(const float* __restrict__ Wa, const float* __restrict__ Wb,
                     const float* __restrict__ Alog, const float* __restrict__ dtb) {
    int row = blockIdx.x * 8 + (threadIdx.x >> 5);
    int lane = threadIdx.x & 31;
    float aA[NHH], aB[NHH];
#pragma unroll
    for (int c = 0; c < NHH; ++c) { aA[c] = 0.f; aB[c] = 0.f; }
    for (int kk = lane; kk < HH; kk += 32) {
        float hv = d_hn[(size_t)row * HH + kk];
        const float* wa = Wa + kk * NHH;
        const float* wb = Wb + kk * NHH;
#pragma unroll
        for (int c = 0; c < NHH; ++c) {
            aA[c] = fmaf(hv, wa[c], aA[c]);
            aB[c] = fmaf(hv, wb[c], aB[c]);
        }
    }
#pragma unroll
    for (int c = 0; c < NHH; ++c) {
#pragma unroll
        for (int off = 16; off; off >>= 1) {
            aA[c] += __shfl_xor_sync(0xffffffffu, aA[c], off);
            aB[c] += __shfl_xor_sync(0xffffffffu, aB[c], off);
        }
    }
    if (lane < NHH) {
        float xx = aA[lane] + dtb[lane];
        float sp = (xx > 20.f) ? xx : log1pf(expf(xx));
        float g = -expf(Alog[lane]) * sp;
        float2 db;
        db.x = expf(g);
        db.y = sigmoidf_(aB[lane]);
        d_db[(size_t)row * NHH + lane] = db;
    }
}

// ---------------- short conv + silu (+ per-head l2norm for k) ----------------
__global__ void k_conv(const float* __restrict__ cw, int which) {
    __shared__ float sv[VDIM];
    const float* in = which ? d_vpre : d_kpre;
    float* out = which ? d_v : d_k;
    const int C = which ? VDIM : KDIM;
    const int HD = which ? HVD : HKD;
    const int doNorm = which ? 0 : 1;

    int t = blockIdx.x;
    int tid = threadIdx.x;
    int seg = d_seg[t];
    int m1 = (t >= 1 && d_seg[t - 1] == seg);
    int m2 = (t >= 2 && d_seg[t - 2] == seg);
    int m3 = (t >= 3 && d_seg[t - 3] == seg);

    for (int c = tid; c < C; c += 256) {
        float w0 = cw[c * 4 + 0], w1 = cw[c * 4 + 1], w2 = cw[c * 4 + 2], w3 = cw[c * 4 + 3];
        float acc = in[(size_t)t * C + c] * w3;
        if (m1) acc = fmaf(in[(size_t)(t - 1) * C + c], w2, acc);
        if (m2) acc = fmaf(in[(size_t)(t - 2) * C + c], w1, acc);
        if (m3) acc = fmaf(in[(size_t)(t - 3) * C + c], w0, acc);
        float val = acc * sigmoidf_(acc);
        if (doNorm) sv[c] = val;
        else out[(size_t)t * C + c] = val;
    }
    if (doNorm) {
        __syncthreads();
        int w = tid >> 5, lane = tid & 31;
        for (int h = w; h < NHH; h += 8) {
            float ssq = 0.f;
            for (int i = lane; i < HD; i += 32) { float v = sv[h * HD + i]; ssq = fmaf(v, v, ssq); }
#pragma unroll
            for (int off = 16; off; off >>= 1) ssq += __shfl_xor_sync(0xffffffffu, ssq, off);
            float r = rsqrtf(ssq + 1e-6f);
            for (int i = lane; i < HD; i += 32)
                out[(size_t)t * C + h * HD + i] = sv[h * HD + i] * r;
        }
    }
}

// ---------------- q at the 16 pooled positions ----------------
__global__ void k_q16(const int* __restrict__ cu, const float* __restrict__ Wq,
                      const float* __restrict__ cw) {
    __shared__ float shn[4][HH];
    __shared__ float sq[KDIM];
    int s = blockIdx.x;
    int pos = cu[s + 1] - 1;
    int seg = d_seg[pos];
    int tid = threadIdx.x;
    int valid[4];
#pragma unroll
    for (int r = 0; r < 4; ++r) {
        int t = pos - r;
        valid[r] = (t >= 0 && d_seg[t] == seg);
    }
#pragma unroll
    for (int r = 0; r < 4; ++r) {
        int t = pos - r;
        if (valid[r]) for (int i = tid; i < HH; i += 256) shn[r][i] = d_hn[(size_t)t * HH + i];
        else          for (int i = tid; i < HH; i += 256) shn[r][i] = 0.f;
    }
    __syncthreads();
    for (int c = tid; c < KDIM; c += 256) {
        float a0 = 0.f, a1 = 0.f, a2 = 0.f, a3 = 0.f;
        for (int i = 0; i < HH; ++i) {
            float wv = Wq[(size_t)i * KDIM + c];
            a0 = fmaf(shn[0][i], wv, a0);
            a1 = fmaf(shn[1][i], wv, a1);
            a2 = fmaf(shn[2][i], wv, a2);
            a3 = fmaf(shn[3][i], wv, a3);
        }
        float acc = a0 * cw[c * 4 + 3] + a1 * cw[c * 4 + 2] + a2 * cw[c * 4 + 1] + a3 * cw[c * 4 + 0];
        sq[c] = acc * sigmoidf_(acc);
    }
    __syncthreads();
    int w = tid >> 5, lane = tid & 31;
    for (int h = w; h < NHH; h += 8) {
        float ssq = 0.f;
        for (int i = lane; i < HKD; i += 32) { float v = sq[h * HKD + i]; ssq = fmaf(v, v, ssq); }
#pragma unroll
        for (int off = 16; off; off >>= 1) ssq += __shfl_xor_sync(0xffffffffu, ssq, off);
        float r = rsqrtf(ssq + 1e-6f) * 0.125f;
        for (int i = lane; i < HKD; i += 32)
            d_q[s * KDIM + h * HKD + i] = sq[h * HKD + i] * r;
    }
}

// ---------------- segment-parallel scan ----------------
// grid (2, 12, 16) = (col-half, head, segment). 256 threads = 64 cols x 4 lanes.
// Each thread owns 16 of the 64 k-rows for one column. cp.async double-buffered
// smem staging of k/v/db/flags, SCH timesteps per chunk.
__global__ void __launch_bounds__(256) k_scan(const int* __restrict__ cu) {
    __shared__ float  sk[2][SCH][64];
    __shared__ float  svv[2][SCH][64];
    __shared__ float2 sdb[2][SCH];
    __shared__ int    sfl[2][SCH];

    int half = blockIdx.x;
    int h    = blockIdx.y;
    int s    = blockIdx.z;
    int tid  = threadIdx.x;
    int colL = tid >> 2;        // 0..63
    int e    = tid & 3;         // lane within column
    int col  = half * 64 + colL;

    int start = cu[s];
    int end   = cu[s + 1];
    int len   = end - start;

    // chunk loader
    auto load_chunk = [&](int buf, int c0) {
        int rem = len - c0; if (rem > SCH) rem = SCH;
        for (int idx = tid; idx < rem * 16; idx += 256) {
            int i = idx >> 4, j = idx & 15;
            cpa16(&sk[buf][i][j * 4], d_k + (size_t)(start + c0 + i) * KDIM + h * HKD + j * 4);
        }
        for (int idx = tid; idx < rem * 16; idx += 256) {
            int i = idx >> 4, j = idx & 15;
            cpa16(&svv[buf][i][j * 4], d_v + (size_t)(start + c0 + i) * VDIM + h * HVD + half * 64 + j * 4);
        }
        if (tid < rem)
            cpa8(&sdb[buf][tid], d_db + (size_t)(start + c0 + tid) * NHH + h);
        if (tid >= 64 && tid - 64 < rem)
            cpa4(&sfl[buf][tid - 64], d_flags + start + c0 + tid - 64);
    };

    float S[16];
#pragma unroll
    for (int i = 0; i < 16; ++i) S[i] = 0.f;

    load_chunk(0, 0);
    CPA_COMMIT;

    int buf = 0;
    for (int c0 = 0; c0 < len; c0 += SCH, buf ^= 1) {
        __syncthreads();                 // all done with buf^1's previous contents
        if (c0 + SCH < len) load_chunk(buf ^ 1, c0 + SCH);
        CPA_COMMIT;
        CPA_WAIT1;                       // current chunk's data landed
        __syncthreads();

        int rem = len - c0; if (rem > SCH) rem = SCH;

        // prime registers for step 0
        float4 nk0 = *(const float4*)&sk[buf][0][e * 16 + 0];
        float4 nk1 = *(const float4*)&sk[buf][0][e * 16 + 4];
        float4 nk2 = *(const float4*)&sk[buf][0][e * 16 + 8];
        float4 nk3 = *(const float4*)&sk[buf][0][e * 16 + 12];
        float  nv  = svv[buf][0][colL];
        float2 ndb = sdb[buf][0];
        int    nfl = sfl[buf][0];

        for (int i = 0; i < rem; ++i) {
            float4 k0 = nk0, k1 = nk1, k2 = nk2, k3 = nk3;
            float  vv = nv;
            float2 db = ndb;
            int    fl = nfl;
            int ip = (i + 1 < rem) ? i + 1 : i;
            nk0 = *(const float4*)&sk[buf][ip][e * 16 + 0];
            nk1 = *(const float4*)&sk[buf][ip][e * 16 + 4];
            nk2 = *(const float4*)&sk[buf][ip][e * 16 + 8];
            nk3 = *(const float4*)&sk[buf][ip][e * 16 + 12];
            nv  = svv[buf][ip][colL];
            ndb = sdb[buf][ip];
            nfl = sfl[buf][ip];

            float lam = (fl & 1) ? 0.f : db.x;

            float a0 = S[0]  * k0.x;
            a0 = fmaf(S[1],  k0.y, a0);
            a0 = fmaf(S[2],  k0.z, a0);
            a0 = fmaf(S[3],  k0.w, a0);
            float a1 = S[4]  * k1.x;
            a1 = fmaf(S[5],  k1.y, a1);
            a1 = fmaf(S[6],  k1.z, a1);
            a1 = fmaf(S[7],  k1.w, a1);
            float a2 = S[8]  * k2.x;
            a2 = fmaf(S[9],  k2.y, a2);
            a2 = fmaf(S[10], k2.z, a2);
            a2 = fmaf(S[11], k2.w, a2);
            float a3 = S[12] * k3.x;
            a3 = fmaf(S[13], k3.y, a3);
            a3 = fmaf(S[14], k3.z, a3);
            a3 = fmaf(S[15], k3.w, a3);
            float dot = (a0 + a1) + (a2 + a3);
            dot += __shfl_xor_sync(0xffffffffu, dot, 1);
            dot += __shfl_xor_sync(0xffffffffu, dot, 2);

            float delta = db.y * fmaf(-lam, dot, vv);

            S[0]  = fmaf(lam, S[0],  k0.x * delta);
            S[1]  = fmaf(lam, S[1],  k0.y * delta);
            S[2]  = fmaf(lam, S[2],  k0.z * delta);
            S[3]  = fmaf(lam, S[3],  k0.w * delta);
            S[4]  = fmaf(lam, S[4],  k1.x * delta);
            S[5]  = fmaf(lam, S[5],  k1.y * delta);
            S[6]  = fmaf(lam, S[6],  k1.z * delta);
            S[7]  = fmaf(lam, S[7],  k1.w * delta);
            S[8]  = fmaf(lam, S[8],  k2.x * delta);
            S[9]  = fmaf(lam, S[9],  k2.y * delta);
            S[10] = fmaf(lam, S[10], k2.z * delta);
            S[11] = fmaf(lam, S[11], k2.w * delta);
            S[12] = fmaf(lam, S[12], k3.x * delta);
            S[13] = fmaf(lam, S[13], k3.y * delta);
            S[14] = fmaf(lam, S[14], k3.z * delta);
            S[15] = fmaf(lam, S[15], k3.w * delta);

            int need = fl >> 1;
            if (need) {
                const float* qp = d_q + (size_t)(need - 1) * KDIM + h * HKD + e * 16;
                float4 q0 = *(const float4*)(qp + 0);
                float4 q1 = *(const float4*)(qp + 4);
                float4 q2 = *(const float4*)(qp + 8);
                float4 q3 = *(const float4*)(qp + 12);
                float od = S[0] * q0.x;
                od = fmaf(S[1],  q0.y, od);
                od = fmaf(S[2],  q0.z, od);
                od = fmaf(S[3],  q0.w, od);
                od = fmaf(S[4],  q1.x, od);
                od = fmaf(S[5],  q1.y, od);
                od = fmaf(S[6],  q1.z, od);
                od = fmaf(S[7],  q1.w, od);
                od = fmaf(S[8],  q2.x, od);
                od = fmaf(S[9],  q2.y, od);
                od = fmaf(S[10], q2.z, od);
                od = fmaf(S[11], q2.w, od);
                od = fmaf(S[12], q3.x, od);
                od = fmaf(S[13], q3.y, od);
                od = fmaf(S[14], q3.z, od);
                od = fmaf(S[15], q3.w, od);
                od += __shfl_xor_sync(0xffffffffu, od, 1);
                od += __shfl_xor_sync(0xffffffffu, od, 2);
                if (e == 0) d_o[(need - 1) * VDIM + h * HVD + col] = od;
            }
        }
    }
}

// ---------------- Wo @ W_head ----------------
__global__ void k_wowh(const float* __restrict__ Wo, const float* __restrict__ Wh) {
    int j = blockIdx.x * 8 + (threadIdx.x >> 5);
    int lane = threadIdx.x & 31;
    float a = 0.f;
    for (int k = lane; k < HH; k += 32) a = fmaf(Wo[(size_t)j * HH + k], Wh[k], a);
#pragma unroll
    for (int off = 16; off; off >>= 1) a += __shfl_xor_sync(0xffffffffu, a, off);
    if (lane == 0) d_wowh[j] = a;
}

// ---------------- gating at pooled positions ----------------
__global__ void k_gate(const int* __restrict__ cu, const float* __restrict__ Wg,
                       const float* __restrict__ onw) {
    __shared__ float shn[HH];
    __shared__ float sred[128];
    int hd = blockIdx.x;
    int s = blockIdx.y;
    int pos = cu[s + 1] - 1;
    int tid = threadIdx.x;
    for (int i = tid; i < HH; i += 128) shn[i] = d_hn[(size_t)pos * HH + i];
    __syncthreads();
    float gate = 0.f;
    for (int i = 0; i < HH; ++i)
        gate = fmaf(shn[i], Wg[(size_t)i * VDIM + hd * HVD + tid], gate);
    float ov = d_o[s * VDIM + hd * HVD + tid];
    sred[tid] = ov * ov;
    __syncthreads();
    for (int st = 64; st; st >>= 1) {
        if (tid < st) sred[tid] += sred[tid + st];
        __syncthreads();
    }
    float rms = rsqrtf(sred[0] / (float)HVD + 1e-5f);
    float gs = gate * sigmoidf_(gate);
    d_og[s * VDIM + hd * HVD + tid] = ov * rms * onw[tid] * gs;
}

// ---------------- final head ----------------
__global__ void k_final(const float* __restrict__ Wh, const float* __restrict__ bh,
                        float* __restrict__ out) {
    __shared__ float sred[256];
    int s = blockIdx.x;
    int tid = threadIdx.x;
    float a = 0.f;
    for (int j = tid; j < VDIM; j += 256) a = fmaf(d_og[s * VDIM + j], d_wowh[j], a);
    for (int k = tid; k < HH; k += 256) a = fmaf(d_hrows[s * HH + k], Wh[k], a);
    sred[tid] = a;
    __syncthreads();
    for (int st = 128; st; st >>= 1) {
        if (tid < st) sred[tid] += sred[tid + st];
        __syncthreads();
    }
    if (tid == 0) out[s] = sred[0] + bh[0];
}

// ---------------- launch ----------------
extern "C" void kernel_launch(void* const* d_in, const int* in_sizes, int n_in,
                              void* d_out, int out_size) {
    const float* x     = (const float*)d_in[0];
    const int*   cu    = (const int*)d_in[1];
    const int*   acidx = (const int*)d_in[2];
    const float* actab = (const float*)d_in[3];
    const float* Win   = (const float*)d_in[4];
    const float* bin   = (const float*)d_in[5];
    const float* nw    = (const float*)d_in[6];
    const float* Wq    = (const float*)d_in[7];
    const float* Wk    = (const float*)d_in[8];
    const float* Wv    = (const float*)d_in[9];
    const float* cqw   = (const float*)d_in[10];
    const float* ckw   = (const float*)d_in[11];
    const float* cvw   = (const float*)d_in[12];
    const float* Wb    = (const float*)d_in[13];
    const float* Wa    = (const float*)d_in[14];
    const float* Alog  = (const float*)d_in[15];
    const float* dtb   = (const float*)d_in[16];
    const float* Wg    = (const float*)d_in[17];
    const float* onw   = (const float*)d_in[18];
    const float* Wo    = (const float*)d_in[19];
    const float* Wh    = (const float*)d_in[20];
    const float* bh    = (const float*)d_in[21];
    float* out = (float*)d_out;

    k_prep<<<TT / 256, 256>>>(cu);
    k_embed<<<TT / 8, 256>>>(x, acidx, actab, Win, bin, nw);

    dim3 gk(KDIM / 128, TT / 128);
    k_sgemm<<<gk, 256>>>(Wk, KDIM, 0);
    dim3 gv(VDIM / 128, TT / 128);
    k_sgemm<<<gv, 256>>>(Wv, VDIM, 1);

    k_ab<<<TT / 8, 256>>>(Wa, Wb, Alog, dtb);
    k_conv<<<TT, 256>>>(ckw, 0);
    k_conv<<<TT, 256>>>(cvw, 1);
    k_q16<<<NSEG, 256>>>(cu, Wq, cqw);

    k_scan<<<dim3(2, NHH, NSEG), 256>>>(cu);

    k_wowh<<<VDIM / 8, 256>>>(Wo, Wh);
    k_gate<<<dim3(NHH, NSEG), 128>>>(cu, Wg, onw);
    k_final<<<NSEG, 256>>>(Wh, bh, out);
}

// round 4
// speedup vs baseline: 5.4734x; 1.5726x over previous
#include <cuda_runtime.h>
#include <cuda_bf16.h>
#include <math.h>
#include <stdint.h>

#define TT   32768
#define HH   1024
#define DIN  16
#define ACD  32
#define NHH  12
#define KDIM 768
#define VDIM 1536
#define HKD  64
#define HVD  128
#define NSEG 16
#define SCH  40

// ---------------- scratch ----------------
static __device__ float  d_hn   [TT * HH];
static __device__ __nv_bfloat16 d_hnb_hi[TT * HH];
static __device__ __nv_bfloat16 d_hnb_lo[TT * HH];
static __device__ __nv_bfloat16 d_wk_hi[KDIM * HH];
static __device__ __nv_bfloat16 d_wk_lo[KDIM * HH];
static __device__ __nv_bfloat16 d_wv_hi[VDIM * HH];
static __device__ __nv_bfloat16 d_wv_lo[VDIM * HH];
static __device__ float  d_kpre [TT * KDIM];
static __device__ float  d_vpre [TT * VDIM];
static __device__ float  d_k    [TT * KDIM];
static __device__ float  d_v    [TT * VDIM];
static __device__ float2 d_db   [TT * NHH];
static __device__ int    d_seg  [TT];
static __device__ int    d_flags[TT];
static __device__ float  d_hrows[NSEG * HH];
static __device__ float  d_q    [NSEG * KDIM];
static __device__ float  d_o    [NSEG * VDIM];
static __device__ float  d_og   [NSEG * VDIM];
static __device__ float  d_wowh [VDIM];

__device__ __forceinline__ float sigmoidf_(float x) { return 1.f / (1.f + expf(-x)); }

// ---------------- PTX helpers (base sm_103 features only) ----------------
__device__ __forceinline__ uint32_t smem_u32(const void* p) {
    uint32_t a;
    asm("{ .reg .u64 t; cvta.to.shared.u64 t, %1; cvt.u32.u64 %0, t; }" : "=r"(a) : "l"(p));
    return a;
}
__device__ __forceinline__ void cpa16s(uint32_t s, const void* g) {
    asm volatile("cp.async.cg.shared.global [%0], [%1], 16;" :: "r"(s), "l"(g));
}
__device__ __forceinline__ void cpa16(void* s, const void* g) { cpa16s(smem_u32(s), g); }
__device__ __forceinline__ void cpa8(void* s, const void* g) {
    asm volatile("cp.async.ca.shared.global [%0], [%1], 8;" :: "r"(smem_u32(s)), "l"(g));
}
__device__ __forceinline__ void cpa4(void* s, const void* g) {
    asm volatile("cp.async.ca.shared.global [%0], [%1], 4;" :: "r"(smem_u32(s)), "l"(g));
}
#define CPA_COMMIT asm volatile("cp.async.commit_group;")
#define CPA_WAIT0  asm volatile("cp.async.wait_group 0;")
#define CPA_WAIT1  asm volatile("cp.async.wait_group 1;")

#define LDM4(r, addr) \
    asm volatile("ldmatrix.sync.aligned.m8n8.x4.shared.b16 {%0,%1,%2,%3}, [%4];" \
        : "=r"((r)[0]), "=r"((r)[1]), "=r"((r)[2]), "=r"((r)[3]) : "r"(addr))

#define MMA16816(d, a, b) \
    asm volatile("mma.sync.aligned.m16n8k16.row.col.f32.bf16.bf16.f32 " \
        "{%0,%1,%2,%3}, {%4,%5,%6,%7}, {%8,%9}, {%0,%1,%2,%3};" \
        : "+f"((d)[0]), "+f"((d)[1]), "+f"((d)[2]), "+f"((d)[3]) \
        : "r"((a)[0]), "r"((a)[1]), "r"((a)[2]), "r"((a)[3]), "r"((b)[0]), "r"((b)[1]))

// ---------------- seg ids + flags ----------------
__global__ void k_prep(const int* __restrict__ cu) {
    int t = blockIdx.x * 256 + threadIdx.x;
    if (t >= TT) return;
    int seg = 0;
#pragma unroll
    for (int s = 1; s <= NSEG; ++s) if (t >= cu[s]) seg = s;
    d_seg[t] = seg;
    int fl = (t == cu[seg]) ? 1 : 0;
#pragma unroll
    for (int s = 0; s < NSEG; ++s) if (t == cu[s + 1] - 1) fl |= ((s + 1) << 1);
    d_flags[t] = fl;
}

// ---------------- embed + rmsnorm + bf16 hi/lo ----------------
__global__ void k_embed(const float* __restrict__ x, const int* __restrict__ acidx,
                        const float* __restrict__ actab, const float* __restrict__ Win,
                        const float* __restrict__ bin, const float* __restrict__ nw) {
    __shared__ float sx[8][48];
    __shared__ float sps[8][256];
    __shared__ float srms[8];
    int t0 = blockIdx.x * 8;
    int tid = threadIdx.x;
    for (int idx = tid; idx < 8 * 48; idx += 256) {
        int r = idx / 48, i = idx % 48;
        int t = t0 + r;
        float v;
        if (i < DIN) v = x[t * DIN + i];
        else v = actab[acidx[d_seg[t]] * ACD + (i - DIN)];
        sx[r][i] = v;
    }
    __syncthreads();

    float hreg[4][8];
    float ps[8];
#pragma unroll
    for (int r = 0; r < 8; ++r) ps[r] = 0.f;

#pragma unroll
    for (int jj = 0; jj < 4; ++jj) {
        int j = tid + jj * 256;
        float acc[8];
        float bb = bin[j];
#pragma unroll
        for (int r = 0; r < 8; ++r) acc[r] = bb;
        for (int i = 0; i < 48; ++i) {
            float w = Win[i * HH + j];
#pragma unroll
            for (int r = 0; r < 8; ++r) acc[r] = fmaf(sx[r][i], w, acc[r]);
        }
#pragma unroll
        for (int r = 0; r < 8; ++r) { hreg[jj][r] = acc[r]; ps[r] = fmaf(acc[r], acc[r], ps[r]); }
    }
#pragma unroll
    for (int r = 0; r < 8; ++r) sps[r][tid] = ps[r];
    __syncthreads();
    int w = tid >> 5, lane = tid & 31;
    float s = sps[w][lane];
#pragma unroll
    for (int i = 1; i < 8; ++i) s += sps[w][lane + 32 * i];
#pragma unroll
    for (int off = 16; off; off >>= 1) s += __shfl_xor_sync(0xffffffffu, s, off);
    if (lane == 0) srms[w] = rsqrtf(s / (float)HH + 1e-6f);
    __syncthreads();

    int needr[8];
#pragma unroll
    for (int r = 0; r < 8; ++r) needr[r] = d_flags[t0 + r] >> 1;

#pragma unroll
    for (int jj = 0; jj < 4; ++jj) {
        int j = tid + jj * 256;
        float nwj = 1.0f + nw[j];
#pragma unroll
        for (int r = 0; r < 8; ++r) {
            int t = t0 + r;
            float val = hreg[jj][r] * srms[r] * nwj;
            d_hn[t * HH + j] = val;
            __nv_bfloat16 h = __float2bfloat16(val);
            d_hnb_hi[(size_t)t * HH + j] = h;
            d_hnb_lo[(size_t)t * HH + j] = __float2bfloat16(val - __bfloat162float(h));
            if (needr[r]) d_hrows[(needr[r] - 1) * HH + j] = hreg[jj][r];
        }
    }
}

// ---------------- weight transpose + bf16 hi/lo split: W[1024,N] -> [N,1024] ----------------
__global__ void k_wcvt(const float* __restrict__ W, __nv_bfloat16* __restrict__ hi,
                       __nv_bfloat16* __restrict__ lo, int N) {
    __shared__ float tile[32][33];
    int n0 = blockIdx.x * 32, k0 = blockIdx.y * 32;
    int tx = threadIdx.x, ty = threadIdx.y;
    for (int i = ty; i < 32; i += 8)
        tile[i][tx] = W[(size_t)(k0 + i) * N + n0 + tx];
    __syncthreads();
    for (int i = ty; i < 32; i += 8) {
        float v = tile[tx][i];
        __nv_bfloat16 h = __float2bfloat16(v);
        size_t o = (size_t)(n0 + i) * HH + k0 + tx;
        hi[o] = h;
        lo[o] = __float2bfloat16(v - __bfloat162float(h));
    }
}

// ---------------- mma.sync bf16-split GEMM: C[T x N] = hn @ W ----------------
// BM=128, BN=128, BK=32, 8 warps (2x4), warp tile 64x32, hi/lo 3-pass.
// smem rows padded to 40 bf16 (80B) -> conflict-free ldmatrix.
#define MM_ROW   40
#define MM_TENS  (128 * MM_ROW)            // 5120 elems per tensor
#define MM_STG   (2 * MM_TENS)             // hi+lo per stage
#define MM_BOFF  (2 * MM_STG)              // B region starts after A's 2 stages
#define MM_SMEM  (4 * MM_STG * 2)          // bytes = 81920

__global__ void __launch_bounds__(256, 1)
k_mma(const __nv_bfloat16* __restrict__ Ah_, const __nv_bfloat16* __restrict__ Al_,
      const __nv_bfloat16* __restrict__ Bh_, const __nv_bfloat16* __restrict__ Bl_,
      float* __restrict__ C, int N) {
    extern __shared__ __align__(128) __nv_bfloat16 sm[];
    uint32_t sb = smem_u32(sm);
    int tid = threadIdx.x, lane = tid & 31, wid = tid >> 5;
    int wm = wid & 1, wn = wid >> 1;
    int ntile = blockIdx.x, mtile = blockIdx.y;

    const __nv_bfloat16* Ah = Ah_ + (size_t)(mtile * 128) * HH;
    const __nv_bfloat16* Al = Al_ + (size_t)(mtile * 128) * HH;
    const __nv_bfloat16* Bh = Bh_ + (size_t)(ntile * 128) * HH;
    const __nv_bfloat16* Bl = Bl_ + (size_t)(ntile * 128) * HH;

    float acc[4][4][4];
#pragma unroll
    for (int m = 0; m < 4; ++m)
#pragma unroll
        for (int n = 0; n < 4; ++n)
#pragma unroll
            for (int i = 0; i < 4; ++i) acc[m][n][i] = 0.f;

    // per-thread ldmatrix offsets (elements)
    int ab[4];
#pragma unroll
    for (int m = 0; m < 4; ++m)
        ab[m] = (wm * 64 + m * 16 + (lane & 15)) * MM_ROW + (lane >> 4) * 8;
    int bb2[2];
#pragma unroll
    for (int p = 0; p < 2; ++p)
        bb2[p] = (wn * 32 + p * 16 + (lane & 7) + ((lane >> 4) & 1) * 8) * MM_ROW + ((lane >> 3) & 1) * 8;

    // stage loader: 1024 A chunks + 1024 B chunks of 16B
    auto load_stage = [&](int stg, int k0) {
        uint32_t abase = sb + 2 * (stg * MM_STG);
        uint32_t bbase = sb + 2 * (MM_BOFF + stg * MM_STG);
#pragma unroll
        for (int it = 0; it < 4; ++it) {
            int idx = tid + it * 256;
            int tz = idx >> 9, r = (idx >> 2) & 127, cc = idx & 3;
            const __nv_bfloat16* src = (tz ? Al : Ah) + (size_t)r * HH + k0 + cc * 8;
            cpa16s(abase + 2 * (tz * MM_TENS + r * MM_ROW + cc * 8), src);
        }
#pragma unroll
        for (int it = 0; it < 4; ++it) {
            int idx = tid + it * 256;
            int tz = idx >> 9, r = (idx >> 2) & 127, cc = idx & 3;
            const __nv_bfloat16* src = (tz ? Bl : Bh) + (size_t)r * HH + k0 + cc * 8;
            cpa16s(bbase + 2 * (tz * MM_TENS + r * MM_ROW + cc * 8), src);
        }
    };

    load_stage(0, 0);
    CPA_COMMIT;

    for (int c = 0; c < HH / 32; ++c) {
        int stg = c & 1;
        __syncthreads();
        if (c + 1 < HH / 32) {
            load_stage(stg ^ 1, (c + 1) * 32);
            CPA_COMMIT;
            CPA_WAIT1;
        } else {
            CPA_WAIT0;
        }
        __syncthreads();

        uint32_t abase = sb + 2 * (stg * MM_STG);
        uint32_t bbase = sb + 2 * (MM_BOFF + stg * MM_STG);
#pragma unroll
        for (int ks = 0; ks < 2; ++ks) {
            uint32_t ah4[4][4], al4[4][4], bh2[4][2], bl2[4][2];
#pragma unroll
            for (int m = 0; m < 4; ++m) LDM4(ah4[m], abase + 2 * (ab[m] + ks * 16));
#pragma unroll
            for (int m = 0; m < 4; ++m) LDM4(al4[m], abase + 2 * (MM_TENS + ab[m] + ks * 16));
#pragma unroll
            for (int p = 0; p < 2; ++p) {
                uint32_t r[4];
                LDM4(r, bbase + 2 * (bb2[p] + ks * 16));
                bh2[2 * p][0] = r[0]; bh2[2 * p][1] = r[1];
                bh2[2 * p + 1][0] = r[2]; bh2[2 * p + 1][1] = r[3];
            }
#pragma unroll
            for (int p = 0; p < 2; ++p) {
                uint32_t r[4];
                LDM4(r, bbase + 2 * (MM_TENS + bb2[p] + ks * 16));
                bl2[2 * p][0] = r[0]; bl2[2 * p][1] = r[1];
                bl2[2 * p + 1][0] = r[2]; bl2[2 * p + 1][1] = r[3];
            }
#pragma unroll
            for (int m = 0; m < 4; ++m)
#pragma unroll
                for (int n = 0; n < 4; ++n) {
                    MMA16816(acc[m][n], ah4[m], bh2[n]);
                    MMA16816(acc[m][n], ah4[m], bl2[n]);
                    MMA16816(acc[m][n], al4[m], bh2[n]);
                }
        }
    }

    // store
#pragma unroll
    for (int m = 0; m < 4; ++m) {
        int row = mtile * 128 + wm * 64 + m * 16 + (lane >> 2);
#pragma unroll
        for (int n = 0; n < 4; ++n) {
            int col = ntile * 128 + wn * 32 + n * 8 + (lane & 3) * 2;
            float2 v0 = make_float2(acc[m][n][0], acc[m][n][1]);
            float2 v1 = make_float2(acc[m][n][2], acc[m][n][3]);
            *(float2*)&C[(size_t)row * N + col] = v0;
            *(float2*)&C[(size_t)(row + 8) * N + col] = v1;
        }
    }
}

// ---------------- hn@Wa, hn@Wb -> decay/beta ----------------
__global__ void k_ab(const float* __restrict__ Wa, const float* __restrict__ Wb,
                     const float* __restrict__ Alog, const float* __restrict__ dtb) {
    int row = blockIdx.x * 8 + (threadIdx.x >> 5);
    int lane = threadIdx.x & 31;
    float aA[NHH], aB[NHH];
#pragma unroll
    for (int c = 0; c < NHH; ++c) { aA[c] = 0.f; aB[c] = 0.f; }
    for (int kk = lane; kk < HH; kk += 32) {
        float hv = d_hn[(size_t)row * HH + kk];
        const float* wa = Wa + kk * NHH;
        const float* wb = Wb + kk * NHH;
#pragma unroll
        for (int c = 0; c < NHH; ++c) {
            aA[c] = fmaf(hv, wa[c], aA[c]);
            aB[c] = fmaf(hv, wb[c], aB[c]);
        }
    }
#pragma unroll
    for (int c = 0; c < NHH; ++c) {
#pragma unroll
        for (int off = 16; off; off >>= 1) {
            aA[c] += __shfl_xor_sync(0xffffffffu, aA[c], off);
            aB[c] += __shfl_xor_sync(0xffffffffu, aB[c], off);
        }
    }
    if (lane < NHH) {
        float xx = aA[lane] + dtb[lane];
        float sp = (xx > 20.f) ? xx : log1pf(expf(xx));
        float g = -expf(Alog[lane]) * sp;
        float2 db;
        db.x = expf(g);
        db.y = sigmoidf_(aB[lane]);
        d_db[(size_t)row * NHH + lane] = db;
    }
}

// ---------------- k-path conv + silu + per-head l2norm ----------------
__global__ void k_conv(const float* __restrict__ cw) {
    __shared__ float sv[KDIM];
    const float* in = d_kpre;
    float* out = d_k;
    int t = blockIdx.x;
    int tid = threadIdx.x;
    int seg = d_seg[t];
    int m1 = (t >= 1 && d_seg[t - 1] == seg);
    int m2 = (t >= 2 && d_seg[t - 2] == seg);
    int m3 = (t >= 3 && d_seg[t - 3] == seg);

    for (int c = tid; c < KDIM; c += 256) {
        float w0 = cw[c * 4 + 0], w1 = cw[c * 4 + 1], w2 = cw[c * 4 + 2], w3 = cw[c * 4 + 3];
        float acc = in[(size_t)t * KDIM + c] * w3;
        if (m1) acc = fmaf(in[(size_t)(t - 1) * KDIM + c], w2, acc);
        if (m2) acc = fmaf(in[(size_t)(t - 2) * KDIM + c], w1, acc);
        if (m3) acc = fmaf(in[(size_t)(t - 3) * KDIM + c], w0, acc);
        sv[c] = acc * sigmoidf_(acc);
    }
    __syncthreads();
    int w = tid >> 5, lane = tid & 31;
    for (int h = w; h < NHH; h += 8) {
        float ssq = 0.f;
        for (int i = lane; i < HKD; i += 32) { float v = sv[h * HKD + i]; ssq = fmaf(v, v, ssq); }
#pragma unroll
        for (int off = 16; off; off >>= 1) ssq += __shfl_xor_sync(0xffffffffu, ssq, off);
        float r = rsqrtf(ssq + 1e-6f);
        for (int i = lane; i < HKD; i += 32)
            out[(size_t)t * KDIM + h * HKD + i] = sv[h * HKD + i] * r;
    }
}

// ---------------- v-path streaming conv + silu ----------------
#define VTCH 16
__global__ void k_conv2(const float* __restrict__ cw) {
    int c = blockIdx.x * 256 + threadIdx.x;
    int t0 = blockIdx.y * VTCH;
    float w0 = cw[c * 4 + 0], w1 = cw[c * 4 + 1], w2 = cw[c * 4 + 2], w3 = cw[c * 4 + 3];
    float xm1 = 0.f, xm2 = 0.f, xm3 = 0.f;
    int st1 = 1, st2 = 1;
    if (t0 >= 1) { xm1 = d_vpre[(size_t)(t0 - 1) * VDIM + c]; st1 = d_flags[t0 - 1] & 1; }
    if (t0 >= 2) { xm2 = d_vpre[(size_t)(t0 - 2) * VDIM + c]; st2 = d_flags[t0 - 2] & 1; }
    if (t0 >= 3) { xm3 = d_vpre[(size_t)(t0 - 3) * VDIM + c]; }
#pragma unroll 4
    for (int t = t0; t < t0 + VTCH; ++t) {
        float xt = d_vpre[(size_t)t * VDIM + c];
        int st = d_flags[t] & 1;
        float acc = xt * w3;
        if (!st) {
            acc = fmaf(xm1, w2, acc);
            if (!st1) {
                acc = fmaf(xm2, w1, acc);
                if (!st2) acc = fmaf(xm3, w0, acc);
            }
        }
        d_v[(size_t)t * VDIM + c] = acc * sigmoidf_(acc);
        xm3 = xm2; xm2 = xm1; xm1 = xt;
        st2 = st1; st1 = st;
    }
}

// ---------------- q at the 16 pooled positions ----------------
__global__ void k_q16(const int* __restrict__ cu, const float* __restrict__ Wq,
                      const float* __restrict__ cw) {
    __shared__ float shn[4][HH];
    __shared__ float sq[KDIM];
    int s = blockIdx.x;
    int pos = cu[s + 1] - 1;
    int seg = d_seg[pos];
    int tid = threadIdx.x;
    int valid[4];
#pragma unroll
    for (int r = 0; r < 4; ++r) {
        int t = pos - r;
        valid[r] = (t >= 0 && d_seg[t] == seg);
    }
#pragma unroll
    for (int r = 0; r < 4; ++r) {
        int t = pos - r;
        if (valid[r]) for (int i = tid; i < HH; i += 256) shn[r][i] = d_hn[(size_t)t * HH + i];
        else          for (int i = tid; i < HH; i += 256) shn[r][i] = 0.f;
    }
    __syncthreads();
    for (int c = tid; c < KDIM; c += 256) {
        float a0 = 0.f, a1 = 0.f, a2 = 0.f, a3 = 0.f;
        for (int i = 0; i < HH; ++i) {
            float wv = Wq[(size_t)i * KDIM + c];
            a0 = fmaf(shn[0][i], wv, a0);
            a1 = fmaf(shn[1][i], wv, a1);
            a2 = fmaf(shn[2][i], wv, a2);
            a3 = fmaf(shn[3][i], wv, a3);
        }
        float acc = a0 * cw[c * 4 + 3] + a1 * cw[c * 4 + 2] + a2 * cw[c * 4 + 1] + a3 * cw[c * 4 + 0];
        sq[c] = acc * sigmoidf_(acc);
    }
    __syncthreads();
    int w = tid >> 5, lane = tid & 31;
    for (int h = w; h < NHH; h += 8) {
        float ssq = 0.f;
        for (int i = lane; i < HKD; i += 32) { float v = sq[h * HKD + i]; ssq = fmaf(v, v, ssq); }
#pragma unroll
        for (int off = 16; off; off >>= 1) ssq += __shfl_xor_sync(0xffffffffu, ssq, off);
        float r = rsqrtf(ssq + 1e-6f) * 0.125f;
        for (int i = lane; i < HKD; i += 32)
            d_q[s * KDIM + h * HKD + i] = sq[h * HKD + i] * r;
    }
}

// ---------------- segment-parallel scan ----------------
__global__ void __launch_bounds__(256) k_scan(const int* __restrict__ cu) {
    __shared__ float  sk[2][SCH][64];
    __shared__ float  svv[2][SCH][64];
    __shared__ float2 sdb[2][SCH];
    __shared__ int    sfl[2][SCH];

    int half = blockIdx.x;
    int h    = blockIdx.y;
    int s    = blockIdx.z;
    int tid  = threadIdx.x;
    int colL = tid >> 2;
    int e    = tid & 3;
    int col  = half * 64 + colL;

    int start = cu[s];
    int end   = cu[s + 1];
    int len   = end - start;

    auto load_chunk = [&](int buf, int c0) {
        int rem = len - c0; if (rem > SCH) rem = SCH;
        for (int idx = tid; idx < rem * 16; idx += 256) {
            int i = idx >> 4, j = idx & 15;
            cpa16(&sk[buf][i][j * 4], d_k + (size_t)(start + c0 + i) * KDIM + h * HKD + j * 4);
        }
        for (int idx = tid; idx < rem * 16; idx += 256) {
            int i = idx >> 4, j = idx & 15;
            cpa16(&svv[buf][i][j * 4], d_v + (size_t)(start + c0 + i) * VDIM + h * HVD + half * 64 + j * 4);
        }
        if (tid < rem)
            cpa8(&sdb[buf][tid], d_db + (size_t)(start + c0 + tid) * NHH + h);
        if (tid >= 64 && tid - 64 < rem)
            cpa4(&sfl[buf][tid - 64], d_flags + start + c0 + tid - 64);
    };

    float S[16];
#pragma unroll
    for (int i = 0; i < 16; ++i) S[i] = 0.f;

    load_chunk(0, 0);
    CPA_COMMIT;

    int buf = 0;
    for (int c0 = 0; c0 < len; c0 += SCH, buf ^= 1) {
        __syncthreads();
        if (c0 + SCH < len) load_chunk(buf ^ 1, c0 + SCH);
        CPA_COMMIT;
        CPA_WAIT1;
        __syncthreads();

        int rem = len - c0; if (rem > SCH) rem = SCH;

        float4 nk0 = *(const float4*)&sk[buf][0][e * 16 + 0];
        float4 nk1 = *(const float4*)&sk[buf][0][e * 16 + 4];
        float4 nk2 = *(const float4*)&sk[buf][0][e * 16 + 8];
        float4 nk3 = *(const float4*)&sk[buf][0][e * 16 + 12];
        float  nv  = svv[buf][0][colL];
        float2 ndb = sdb[buf][0];
        int    nfl = sfl[buf][0];

        for (int i = 0; i < rem; ++i) {
            float4 k0 = nk0, k1 = nk1, k2 = nk2, k3 = nk3;
            float  vv = nv;
            float2 db = ndb;
            int    fl = nfl;
            int ip = (i + 1 < rem) ? i + 1 : i;
            nk0 = *(const float4*)&sk[buf][ip][e * 16 + 0];
            nk1 = *(const float4*)&sk[buf][ip][e * 16 + 4];
            nk2 = *(const float4*)&sk[buf][ip][e * 16 + 8];
            nk3 = *(const float4*)&sk[buf][ip][e * 16 + 12];
            nv  = svv[buf][ip][colL];
            ndb = sdb[buf][ip];
            nfl = sfl[buf][ip];

            float lam = (fl & 1) ? 0.f : db.x;

            float a0 = S[0]  * k0.x;
            a0 = fmaf(S[1],  k0.y, a0);
            a0 = fmaf(S[2],  k0.z, a0);
            a0 = fmaf(S[3],  k0.w, a0);
            float a1 = S[4]  * k1.x;
            a1 = fmaf(S[5],  k1.y, a1);
            a1 = fmaf(S[6],  k1.z, a1);
            a1 = fmaf(S[7],  k1.w, a1);
            float a2 = S[8]  * k2.x;
            a2 = fmaf(S[9],  k2.y, a2);
            a2 = fmaf(S[10], k2.z, a2);
            a2 = fmaf(S[11], k2.w, a2);
            float a3 = S[12] * k3.x;
            a3 = fmaf(S[13], k3.y, a3);
            a3 = fmaf(S[14], k3.z, a3);
            a3 = fmaf(S[15], k3.w, a3);
            float dot = (a0 + a1) + (a2 + a3);
            dot += __shfl_xor_sync(0xffffffffu, dot, 1);
            dot += __shfl_xor_sync(0xffffffffu, dot, 2);

            float delta = db.y * fmaf(-lam, dot, vv);

            S[0]  = fmaf(lam, S[0],  k0.x * delta);
            S[1]  = fmaf(lam, S[1],  k0.y * delta);
            S[2]  = fmaf(lam, S[2],  k0.z * delta);
            S[3]  = fmaf(lam, S[3],  k0.w * delta);
            S[4]  = fmaf(lam, S[4],  k1.x * delta);
            S[5]  = fmaf(lam, S[5],  k1.y * delta);
            S[6]  = fmaf(lam, S[6],  k1.z * delta);
            S[7]  = fmaf(lam, S[7],  k1.w * delta);
            S[8]  = fmaf(lam, S[8],  k2.x * delta);
            S[9]  = fmaf(lam, S[9],  k2.y * delta);
            S[10] = fmaf(lam, S[10], k2.z * delta);
            S[11] = fmaf(lam, S[11], k2.w * delta);
            S[12] = fmaf(lam, S[12], k3.x * delta);
            S[13] = fmaf(lam, S[13], k3.y * delta);
            S[14] = fmaf(lam, S[14], k3.z * delta);
            S[15] = fmaf(lam, S[15], k3.w * delta);

            int need = fl >> 1;
            if (need) {
                const float* qp = d_q + (size_t)(need - 1) * KDIM + h * HKD + e * 16;
                float4 q0 = *(const float4*)(qp + 0);
                float4 q1 = *(const float4*)(qp + 4);
                float4 q2 = *(const float4*)(qp + 8);
                float4 q3 = *(const float4*)(qp + 12);
                float od = S[0] * q0.x;
                od = fmaf(S[1],  q0.y, od);
                od = fmaf(S[2],  q0.z, od);
                od = fmaf(S[3],  q0.w, od);
                od = fmaf(S[4],  q1.x, od);
                od = fmaf(S[5],  q1.y, od);
                od = fmaf(S[6],  q1.z, od);
                od = fmaf(S[7],  q1.w, od);
                od = fmaf(S[8],  q2.x, od);
                od = fmaf(S[9],  q2.y, od);
                od = fmaf(S[10], q2.z, od);
                od = fmaf(S[11], q2.w, od);
                od = fmaf(S[12], q3.x, od);
                od = fmaf(S[13], q3.y, od);
                od = fmaf(S[14], q3.z, od);
                od = fmaf(S[15], q3.w, od);
                od += __shfl_xor_sync(0xffffffffu, od, 1);
                od += __shfl_xor_sync(0xffffffffu, od, 2);
                if (e == 0) d_o[(need - 1) * VDIM + h * HVD + col] = od;
            }
        }
    }
}

// ---------------- Wo @ W_head ----------------
__global__ void k_wowh(const float* __restrict__ Wo, const float* __restrict__ Wh) {
    int j = blockIdx.x * 8 + (threadIdx.x >> 5);
    int lane = threadIdx.x & 31;
    float a = 0.f;
    for (int k = lane; k < HH; k += 32) a = fmaf(Wo[(size_t)j * HH + k], Wh[k], a);
#pragma unroll
    for (int off = 16; off; off >>= 1) a += __shfl_xor_sync(0xffffffffu, a, off);
    if (lane == 0) d_wowh[j] = a;
}

// ---------------- gating at pooled positions ----------------
__global__ void k_gate(const int* __restrict__ cu, const float* __restrict__ Wg,
                       const float* __restrict__ onw) {
    __shared__ float shn[HH];
    __shared__ float sred[128];
    int hd = blockIdx.x;
    int s = blockIdx.y;
    int pos = cu[s + 1] - 1;
    int tid = threadIdx.x;
    for (int i = tid; i < HH; i += 128) shn[i] = d_hn[(size_t)pos * HH + i];
    __syncthreads();
    float gate = 0.f;
    for (int i = 0; i < HH; ++i)
        gate = fmaf(shn[i], Wg[(size_t)i * VDIM + hd * HVD + tid], gate);
    float ov = d_o[s * VDIM + hd * HVD + tid];
    sred[tid] = ov * ov;
    __syncthreads();
    for (int st = 64; st; st >>= 1) {
        if (tid < st) sred[tid] += sred[tid + st];
        __syncthreads();
    }
    float rms = rsqrtf(sred[0] / (float)HVD + 1e-5f);
    float gs = gate * sigmoidf_(gate);
    d_og[s * VDIM + hd * HVD + tid] = ov * rms * onw[tid] * gs;
}

// ---------------- final head ----------------
__global__ void k_final(const float* __restrict__ Wh, const float* __restrict__ bh,
                        float* __restrict__ out) {
    __shared__ float sred[256];
    int s = blockIdx.x;
    int tid = threadIdx.x;
    float a = 0.f;
    for (int j = tid; j < VDIM; j += 256) a = fmaf(d_og[s * VDIM + j], d_wowh[j], a);
    for (int k = tid; k < HH; k += 256) a = fmaf(d_hrows[s * HH + k], Wh[k], a);
    sred[tid] = a;
    __syncthreads();
    for (int st = 128; st; st >>= 1) {
        if (tid < st) sred[tid] += sred[tid + st];
        __syncthreads();
    }
    if (tid == 0) out[s] = sred[0] + bh[0];
}

// ---------------- launch ----------------
extern "C" void kernel_launch(void* const* d_in, const int* in_sizes, int n_in,
                              void* d_out, int out_size) {
    const float* x     = (const float*)d_in[0];
    const int*   cu    = (const int*)d_in[1];
    const int*   acidx = (const int*)d_in[2];
    const float* actab = (const float*)d_in[3];
    const float* Win   = (const float*)d_in[4];
    const float* bin   = (const float*)d_in[5];
    const float* nw    = (const float*)d_in[6];
    const float* Wq    = (const float*)d_in[7];
    const float* Wk    = (const float*)d_in[8];
    const float* Wv    = (const float*)d_in[9];
    const float* cqw   = (const float*)d_in[10];
    const float* ckw   = (const float*)d_in[11];
    const float* cvw   = (const float*)d_in[12];
    const float* Wb    = (const float*)d_in[13];
    const float* Wa    = (const float*)d_in[14];
    const float* Alog  = (const float*)d_in[15];
    const float* dtb   = (const float*)d_in[16];
    const float* Wg    = (const float*)d_in[17];
    const float* onw   = (const float*)d_in[18];
    const float* Wo    = (const float*)d_in[19];
    const float* Wh    = (const float*)d_in[20];
    const float* bh    = (const float*)d_in[21];
    float* out = (float*)d_out;

    cudaFuncSetAttribute(k_mma, cudaFuncAttributeMaxDynamicSharedMemorySize, MM_SMEM);

    __nv_bfloat16 *wk_hi, *wk_lo, *wv_hi, *wv_lo, *hn_hi, *hn_lo;
    cudaGetSymbolAddress((void**)&wk_hi, d_wk_hi);
    cudaGetSymbolAddress((void**)&wk_lo, d_wk_lo);
    cudaGetSymbolAddress((void**)&wv_hi, d_wv_hi);
    cudaGetSymbolAddress((void**)&wv_lo, d_wv_lo);
    cudaGetSymbolAddress((void**)&hn_hi, d_hnb_hi);
    cudaGetSymbolAddress((void**)&hn_lo, d_hnb_lo);
    float *kpre, *vpre;
    cudaGetSymbolAddress((void**)&kpre, d_kpre);
    cudaGetSymbolAddress((void**)&vpre, d_vpre);

    k_prep<<<TT / 256, 256>>>(cu);
    k_embed<<<TT / 8, 256>>>(x, acidx, actab, Win, bin, nw);

    k_wcvt<<<dim3(KDIM / 32, HH / 32), dim3(32, 8)>>>(Wk, wk_hi, wk_lo, KDIM);
    k_wcvt<<<dim3(VDIM / 32, HH / 32), dim3(32, 8)>>>(Wv, wv_hi, wv_lo, VDIM);

    k_mma<<<dim3(KDIM / 128, TT / 128), 256, MM_SMEM>>>(hn_hi, hn_lo, wk_hi, wk_lo, kpre, KDIM);
    k_mma<<<dim3(VDIM / 128, TT / 128), 256, MM_SMEM>>>(hn_hi, hn_lo, wv_hi, wv_lo, vpre, VDIM);

    k_ab<<<TT / 8, 256>>>(Wa, Wb, Alog, dtb);
    k_conv<<<TT, 256>>>(ckw);
    k_conv2<<<dim3(VDIM / 256, TT / VTCH), 256>>>(cvw);
    k_q16<<<NSEG, 256>>>(cu, Wq, cqw);

    k_scan<<<dim3(2, NHH, NSEG), 256>>>(cu);

    k_wowh<<<VDIM / 8, 256>>>(Wo, Wh);
    k_gate<<<dim3(NHH, NSEG), 128>>>(cu, Wg, onw);
    k_final<<<NSEG, 256>>>(Wh, bh, out);
}

// round 5
// speedup vs baseline: 5.5423x; 1.0126x over previous
#include <cuda_runtime.h>
#include <cuda_bf16.h>
#include <math.h>
#include <stdint.h>

#define TT   32768
#define HH   1024
#define DIN  16
#define ACD  32
#define NHH  12
#define KDIM 768
#define VDIM 1536
#define HKD  64
#define HVD  128
#define NSEG 16
#define SCH  40

// ---------------- scratch ----------------
static __device__ float  d_hn   [TT * HH];
static __device__ __nv_bfloat16 d_hnb_hi[TT * HH];
static __device__ __nv_bfloat16 d_hnb_lo[TT * HH];
static __device__ __nv_bfloat16 d_wk_hi[KDIM * HH];
static __device__ __nv_bfloat16 d_wk_lo[KDIM * HH];
static __device__ __nv_bfloat16 d_wv_hi[VDIM * HH];
static __device__ __nv_bfloat16 d_wv_lo[VDIM * HH];
static __device__ float  d_kpre [TT * KDIM];
static __device__ float  d_vpre [TT * VDIM];
static __device__ float  d_k    [TT * KDIM];
static __device__ float  d_v    [TT * VDIM];
static __device__ float2 d_db   [TT * NHH];
static __device__ int    d_seg  [TT];
static __device__ int    d_flags[TT];
static __device__ float  d_hrows[NSEG * HH];
static __device__ float  d_q    [NSEG * KDIM];
static __device__ float  d_o    [NSEG * VDIM];
static __device__ float  d_og   [NSEG * VDIM];
static __device__ float  d_wowh [VDIM];

__device__ __forceinline__ float sigmoidf_(float x) { return 1.f / (1.f + expf(-x)); }

// ---------------- PTX helpers (base sm_103 features only) ----------------
__device__ __forceinline__ uint32_t smem_u32(const void* p) {
    uint32_t a;
    asm("{ .reg .u64 t; cvta.to.shared.u64 t, %1; cvt.u32.u64 %0, t; }" : "=r"(a) : "l"(p));
    return a;
}
__device__ __forceinline__ void cpa16s(uint32_t s, const void* g) {
    asm volatile("cp.async.cg.shared.global [%0], [%1], 16;" :: "r"(s), "l"(g));
}
__device__ __forceinline__ void cpa16(void* s, const void* g) { cpa16s(smem_u32(s), g); }
__device__ __forceinline__ void cpa8(void* s, const void* g) {
    asm volatile("cp.async.ca.shared.global [%0], [%1], 8;" :: "r"(smem_u32(s)), "l"(g));
}
__device__ __forceinline__ void cpa4(void* s, const void* g) {
    asm volatile("cp.async.ca.shared.global [%0], [%1], 4;" :: "r"(smem_u32(s)), "l"(g));
}
#define CPA_COMMIT asm volatile("cp.async.commit_group;")
#define CPA_WAIT0  asm volatile("cp.async.wait_group 0;")
#define CPA_WAIT1  asm volatile("cp.async.wait_group 1;")

#define LDM4(r, addr) \
    asm volatile("ldmatrix.sync.aligned.m8n8.x4.shared.b16 {%0,%1,%2,%3}, [%4];" \
        : "=r"((r)[0]), "=r"((r)[1]), "=r"((r)[2]), "=r"((r)[3]) : "r"(addr))

#define MMA16816(d, a, b0, b1) \
    asm volatile("mma.sync.aligned.m16n8k16.row.col.f32.bf16.bf16.f32 " \
        "{%0,%1,%2,%3}, {%4,%5,%6,%7}, {%8,%9}, {%0,%1,%2,%3};" \
        : "+f"((d)[0]), "+f"((d)[1]), "+f"((d)[2]), "+f"((d)[3]) \
        : "r"((a)[0]), "r"((a)[1]), "r"((a)[2]), "r"((a)[3]), "r"(b0), "r"(b1))

// ---------------- seg ids + flags ----------------
__global__ void k_prep(const int* __restrict__ cu) {
    int t = blockIdx.x * 256 + threadIdx.x;
    if (t >= TT) return;
    int seg = 0;
#pragma unroll
    for (int s = 1; s <= NSEG; ++s) if (t >= cu[s]) seg = s;
    d_seg[t] = seg;
    int fl = (t == cu[seg]) ? 1 : 0;
#pragma unroll
    for (int s = 0; s < NSEG; ++s) if (t == cu[s + 1] - 1) fl |= ((s + 1) << 1);
    d_flags[t] = fl;
}

// ---------------- embed + rmsnorm + bf16 hi/lo ----------------
__global__ void k_embed(const float* __restrict__ x, const int* __restrict__ acidx,
                        const float* __restrict__ actab, const float* __restrict__ Win,
                        const float* __restrict__ bin, const float* __restrict__ nw) {
    __shared__ float sx[8][48];
    __shared__ float sps[8][256];
    __shared__ float srms[8];
    int t0 = blockIdx.x * 8;
    int tid = threadIdx.x;
    for (int idx = tid; idx < 8 * 48; idx += 256) {
        int r = idx / 48, i = idx % 48;
        int t = t0 + r;
        float v;
        if (i < DIN) v = x[t * DIN + i];
        else v = actab[acidx[d_seg[t]] * ACD + (i - DIN)];
        sx[r][i] = v;
    }
    __syncthreads();

    float hreg[4][8];
    float ps[8];
#pragma unroll
    for (int r = 0; r < 8; ++r) ps[r] = 0.f;

#pragma unroll
    for (int jj = 0; jj < 4; ++jj) {
        int j = tid + jj * 256;
        float acc[8];
        float bb = bin[j];
#pragma unroll
        for (int r = 0; r < 8; ++r) acc[r] = bb;
        for (int i = 0; i < 48; ++i) {
            float w = Win[i * HH + j];
#pragma unroll
            for (int r = 0; r < 8; ++r) acc[r] = fmaf(sx[r][i], w, acc[r]);
        }
#pragma unroll
        for (int r = 0; r < 8; ++r) { hreg[jj][r] = acc[r]; ps[r] = fmaf(acc[r], acc[r], ps[r]); }
    }
#pragma unroll
    for (int r = 0; r < 8; ++r) sps[r][tid] = ps[r];
    __syncthreads();
    int w = tid >> 5, lane = tid & 31;
    float s = sps[w][lane];
#pragma unroll
    for (int i = 1; i < 8; ++i) s += sps[w][lane + 32 * i];
#pragma unroll
    for (int off = 16; off; off >>= 1) s += __shfl_xor_sync(0xffffffffu, s, off);
    if (lane == 0) srms[w] = rsqrtf(s / (float)HH + 1e-6f);
    __syncthreads();

    int needr[8];
#pragma unroll
    for (int r = 0; r < 8; ++r) needr[r] = d_flags[t0 + r] >> 1;

#pragma unroll
    for (int jj = 0; jj < 4; ++jj) {
        int j = tid + jj * 256;
        float nwj = 1.0f + nw[j];
#pragma unroll
        for (int r = 0; r < 8; ++r) {
            int t = t0 + r;
            float val = hreg[jj][r] * srms[r] * nwj;
            d_hn[t * HH + j] = val;
            __nv_bfloat16 h = __float2bfloat16(val);
            d_hnb_hi[(size_t)t * HH + j] = h;
            d_hnb_lo[(size_t)t * HH + j] = __float2bfloat16(val - __bfloat162float(h));
            if (needr[r]) d_hrows[(needr[r] - 1) * HH + j] = hreg[jj][r];
        }
    }
}

// ---------------- weight transpose + bf16 hi/lo split ----------------
__global__ void k_wcvt(const float* __restrict__ W, __nv_bfloat16* __restrict__ hi,
                       __nv_bfloat16* __restrict__ lo, int N) {
    __shared__ float tile[32][33];
    int n0 = blockIdx.x * 32, k0 = blockIdx.y * 32;
    int tx = threadIdx.x, ty = threadIdx.y;
    for (int i = ty; i < 32; i += 8)
        tile[i][tx] = W[(size_t)(k0 + i) * N + n0 + tx];
    __syncthreads();
    for (int i = ty; i < 32; i += 8) {
        float v = tile[tx][i];
        __nv_bfloat16 h = __float2bfloat16(v);
        size_t o = (size_t)(n0 + i) * HH + k0 + tx;
        hi[o] = h;
        lo[o] = __float2bfloat16(v - __bfloat162float(h));
    }
}

// ---------------- mma.sync bf16-split GEMM: C[T x N] = hn @ W ----------------
// BM=128, BN=256, BK=32, 8 warps (2x4), warp tile 64x64, 3-stage cp.async.
#define MM_ROW   40
#define MM_ATEN  (128 * MM_ROW)                 // 5120
#define MM_BTEN  (256 * MM_ROW)                 // 10240
#define MM_STG   (2 * MM_ATEN + 2 * MM_BTEN)    // 30720 elems per stage
#define MM_AHI   0
#define MM_ALO   MM_ATEN
#define MM_BHI   (2 * MM_ATEN)
#define MM_BLO   (2 * MM_ATEN + MM_BTEN)
#define MM_NSTG  3
#define MM_SMEM  (MM_NSTG * MM_STG * 2)         // 184320 bytes
#define MM_NCH   (HH / 32)                      // 32 k-chunks

__global__ void __launch_bounds__(256, 1)
k_mma(const __nv_bfloat16* __restrict__ Ah_, const __nv_bfloat16* __restrict__ Al_,
      const __nv_bfloat16* __restrict__ Bh_, const __nv_bfloat16* __restrict__ Bl_,
      float* __restrict__ C, int N) {
    extern __shared__ __align__(128) __nv_bfloat16 sm[];
    uint32_t sb = smem_u32(sm);
    int tid = threadIdx.x, lane = tid & 31, wid = tid >> 5;
    int wm = wid & 1, wn = wid >> 1;
    int ntile = blockIdx.x, mtile = blockIdx.y;

    const __nv_bfloat16* Ah = Ah_ + (size_t)(mtile * 128) * HH;
    const __nv_bfloat16* Al = Al_ + (size_t)(mtile * 128) * HH;
    const __nv_bfloat16* Bh = Bh_ + (size_t)(ntile * 256) * HH;
    const __nv_bfloat16* Bl = Bl_ + (size_t)(ntile * 256) * HH;

    float acc[4][8][4];
#pragma unroll
    for (int m = 0; m < 4; ++m)
#pragma unroll
        for (int n = 0; n < 8; ++n)
#pragma unroll
            for (int i = 0; i < 4; ++i) acc[m][n][i] = 0.f;

    // ldmatrix element offsets within a stage
    int ab[4];
#pragma unroll
    for (int m = 0; m < 4; ++m)
        ab[m] = (wm * 64 + m * 16 + (lane & 15)) * MM_ROW + (lane >> 4) * 8;
    int bb[4];
#pragma unroll
    for (int p = 0; p < 4; ++p)
        bb[p] = (wn * 64 + p * 16 + (lane & 7) + ((lane >> 4) & 1) * 8) * MM_ROW + ((lane >> 3) & 1) * 8;

    // stage loader: A 1024 chunks + B 2048 chunks of 16B, 12 per thread
    auto load_stage = [&](int stg, int k0) {
        uint32_t base = sb + 2 * (stg * MM_STG);
#pragma unroll
        for (int it = 0; it < 4; ++it) {
            int idx = tid + it * 256;
            int tz = idx >> 9, r = (idx >> 2) & 127, cc = idx & 3;
            const __nv_bfloat16* src = (tz ? Al : Ah) + (size_t)r * HH + k0 + cc * 8;
            cpa16s(base + 2 * (tz * MM_ATEN + r * MM_ROW + cc * 8), src);
        }
#pragma unroll
        for (int it = 0; it < 8; ++it) {
            int idx = tid + it * 256;
            int tz = idx >> 10, r = (idx >> 2) & 255, cc = idx & 3;
            const __nv_bfloat16* src = (tz ? Bl : Bh) + (size_t)r * HH + k0 + cc * 8;
            cpa16s(base + 2 * (MM_BHI + tz * MM_BTEN + r * MM_ROW + cc * 8), src);
        }
    };

    load_stage(0, 0);
    CPA_COMMIT;
    load_stage(1, 32);
    CPA_COMMIT;

    for (int c = 0; c < MM_NCH; ++c) {
        int stg = c % MM_NSTG;
        if (c + 1 < MM_NCH) { CPA_WAIT1; } else { CPA_WAIT0; }
        __syncthreads();
        if (c + 2 < MM_NCH) {
            load_stage((c + 2) % MM_NSTG, (c + 2) * 32);
            CPA_COMMIT;
        }

        uint32_t base = sb + 2 * (stg * MM_STG);
#pragma unroll
        for (int ks = 0; ks < 2; ++ks) {
            uint32_t ah4[4][4], al4[4][4];
#pragma unroll
            for (int m = 0; m < 4; ++m) LDM4(ah4[m], base + 2 * (MM_AHI + ab[m] + ks * 16));
#pragma unroll
            for (int m = 0; m < 4; ++m) LDM4(al4[m], base + 2 * (MM_ALO + ab[m] + ks * 16));
#pragma unroll
            for (int p = 0; p < 4; ++p) {
                uint32_t rh[4], rl[4];
                LDM4(rh, base + 2 * (MM_BHI + bb[p] + ks * 16));
                LDM4(rl, base + 2 * (MM_BLO + bb[p] + ks * 16));
#pragma unroll
                for (int m = 0; m < 4; ++m) {
                    MMA16816(acc[m][2 * p],     ah4[m], rh[0], rh[1]);
                    MMA16816(acc[m][2 * p],     ah4[m], rl[0], rl[1]);
                    MMA16816(acc[m][2 * p],     al4[m], rh[0], rh[1]);
                    MMA16816(acc[m][2 * p + 1], ah4[m], rh[2], rh[3]);
                    MMA16816(acc[m][2 * p + 1], ah4[m], rl[2], rl[3]);
                    MMA16816(acc[m][2 * p + 1], al4[m], rh[2], rh[3]);
                }
            }
        }
        __syncthreads();
    }

    // store
#pragma unroll
    for (int m = 0; m < 4; ++m) {
        int row = mtile * 128 + wm * 64 + m * 16 + (lane >> 2);
#pragma unroll
        for (int n = 0; n < 8; ++n) {
            int col = ntile * 256 + wn * 64 + n * 8 + (lane & 3) * 2;
            float2 v0 = make_float2(acc[m][n][0], acc[m][n][1]);
            float2 v1 = make_float2(acc[m][n][2], acc[m][n][3]);
            *(float2*)&C[(size_t)row * N + col] = v0;
            *(float2*)&C[(size_t)(row + 8) * N + col] = v1;
        }
    }
}

// ---------------- hn@Wa, hn@Wb -> decay/beta ----------------
__global__ void k_ab(const float* __restrict__ Wa, const float* __restrict__ Wb,
                     const float* __restrict__ Alog, const float* __restrict__ dtb) {
    int row = blockIdx.x * 8 + (threadIdx.x >> 5);
    int lane = threadIdx.x & 31;
    float aA[NHH], aB[NHH];
#pragma unroll
    for (int c = 0; c < NHH; ++c) { aA[c] = 0.f; aB[c] = 0.f; }
    for (int kk = lane; kk < HH; kk += 32) {
        float hv = d_hn[(size_t)row * HH + kk];
        const float* wa = Wa + kk * NHH;
        const float* wb = Wb + kk * NHH;
#pragma unroll
        for (int c = 0; c < NHH; ++c) {
            aA[c] = fmaf(hv, wa[c], aA[c]);
            aB[c] = fmaf(hv, wb[c], aB[c]);
        }
    }
#pragma unroll
    for (int c = 0; c < NHH; ++c) {
#pragma unroll
        for (int off = 16; off; off >>= 1) {
            aA[c] += __shfl_xor_sync(0xffffffffu, aA[c], off);
            aB[c] += __shfl_xor_sync(0xffffffffu, aB[c], off);
        }
    }
    if (lane < NHH) {
        float xx = aA[lane] + dtb[lane];
        float sp = (xx > 20.f) ? xx : log1pf(expf(xx));
        float g = -expf(Alog[lane]) * sp;
        float2 db;
        db.x = expf(g);
        db.y = sigmoidf_(aB[lane]);
        d_db[(size_t)row * NHH + lane] = db;
    }
}

// ---------------- k-path conv + silu + per-head l2norm ----------------
__global__ void k_conv(const float* __restrict__ cw) {
    __shared__ float sv[KDIM];
    const float* in = d_kpre;
    float* out = d_k;
    int t = blockIdx.x;
    int tid = threadIdx.x;
    int seg = d_seg[t];
    int m1 = (t >= 1 && d_seg[t - 1] == seg);
    int m2 = (t >= 2 && d_seg[t - 2] == seg);
    int m3 = (t >= 3 && d_seg[t - 3] == seg);

    for (int c = tid; c < KDIM; c += 256) {
        float w0 = cw[c * 4 + 0], w1 = cw[c * 4 + 1], w2 = cw[c * 4 + 2], w3 = cw[c * 4 + 3];
        float acc = in[(size_t)t * KDIM + c] * w3;
        if (m1) acc = fmaf(in[(size_t)(t - 1) * KDIM + c], w2, acc);
        if (m2) acc = fmaf(in[(size_t)(t - 2) * KDIM + c], w1, acc);
        if (m3) acc = fmaf(in[(size_t)(t - 3) * KDIM + c], w0, acc);
        sv[c] = acc * sigmoidf_(acc);
    }
    __syncthreads();
    int w = tid >> 5, lane = tid & 31;
    for (int h = w; h < NHH; h += 8) {
        float ssq = 0.f;
        for (int i = lane; i < HKD; i += 32) { float v = sv[h * HKD + i]; ssq = fmaf(v, v, ssq); }
#pragma unroll
        for (int off = 16; off; off >>= 1) ssq += __shfl_xor_sync(0xffffffffu, ssq, off);
        float r = rsqrtf(ssq + 1e-6f);
        for (int i = lane; i < HKD; i += 32)
            out[(size_t)t * KDIM + h * HKD + i] = sv[h * HKD + i] * r;
    }
}

// ---------------- v-path streaming conv + silu ----------------
#define VTCH 16
__global__ void k_conv2(const float* __restrict__ cw) {
    int c = blockIdx.x * 256 + threadIdx.x;
    int t0 = blockIdx.y * VTCH;
    float w0 = cw[c * 4 + 0], w1 = cw[c * 4 + 1], w2 = cw[c * 4 + 2], w3 = cw[c * 4 + 3];
    float xm1 = 0.f, xm2 = 0.f, xm3 = 0.f;
    int st1 = 1, st2 = 1;
    if (t0 >= 1) { xm1 = d_vpre[(size_t)(t0 - 1) * VDIM + c]; st1 = d_flags[t0 - 1] & 1; }
    if (t0 >= 2) { xm2 = d_vpre[(size_t)(t0 - 2) * VDIM + c]; st2 = d_flags[t0 - 2] & 1; }
    if (t0 >= 3) { xm3 = d_vpre[(size_t)(t0 - 3) * VDIM + c]; }
#pragma unroll 4
    for (int t = t0; t < t0 + VTCH; ++t) {
        float xt = d_vpre[(size_t)t * VDIM + c];
        int st = d_flags[t] & 1;
        float acc = xt * w3;
        if (!st) {
            acc = fmaf(xm1, w2, acc);
            if (!st1) {
                acc = fmaf(xm2, w1, acc);
                if (!st2) acc = fmaf(xm3, w0, acc);
            }
        }
        d_v[(size_t)t * VDIM + c] = acc * sigmoidf_(acc);
        xm3 = xm2; xm2 = xm1; xm1 = xt;
        st2 = st1; st1 = st;
    }
}

// ---------------- q at the 16 pooled positions ----------------
__global__ void k_q16(const int* __restrict__ cu, const float* __restrict__ Wq,
                      const float* __restrict__ cw) {
    __shared__ float shn[4][HH];
    __shared__ float sq[KDIM];
    int s = blockIdx.x;
    int pos = cu[s + 1] - 1;
    int seg = d_seg[pos];
    int tid = threadIdx.x;
    int valid[4];
#pragma unroll
    for (int r = 0; r < 4; ++r) {
        int t = pos - r;
        valid[r] = (t >= 0 && d_seg[t] == seg);
    }
#pragma unroll
    for (int r = 0; r < 4; ++r) {
        int t = pos - r;
        if (valid[r]) for (int i = tid; i < HH; i += 256) shn[r][i] = d_hn[(size_t)t * HH + i];
        else          for (int i = tid; i < HH; i += 256) shn[r][i] = 0.f;
    }
    __syncthreads();
    for (int c = tid; c < KDIM; c += 256) {
        float a0 = 0.f, a1 = 0.f, a2 = 0.f, a3 = 0.f;
        for (int i = 0; i < HH; ++i) {
            float wv = Wq[(size_t)i * KDIM + c];
            a0 = fmaf(shn[0][i], wv, a0);
            a1 = fmaf(shn[1][i], wv, a1);
            a2 = fmaf(shn[2][i], wv, a2);
            a3 = fmaf(shn[3][i], wv, a3);
        }
        float acc = a0 * cw[c * 4 + 3] + a1 * cw[c * 4 + 2] + a2 * cw[c * 4 + 1] + a3 * cw[c * 4 + 0];
        sq[c] = acc * sigmoidf_(acc);
    }
    __syncthreads();
    int w = tid >> 5, lane = tid & 31;
    for (int h = w; h < NHH; h += 8) {
        float ssq = 0.f;
        for (int i = lane; i < HKD; i += 32) { float v = sq[h * HKD + i]; ssq = fmaf(v, v, ssq); }
#pragma unroll
        for (int off = 16; off; off >>= 1) ssq += __shfl_xor_sync(0xffffffffu, ssq, off);
        float r = rsqrtf(ssq + 1e-6f) * 0.125f;
        for (int i = lane; i < HKD; i += 32)
            d_q[s * KDIM + h * HKD + i] = sq[h * HKD + i] * r;
    }
}

// ---------------- segment-parallel scan ----------------
__global__ void __launch_bounds__(256) k_scan(const int* __restrict__ cu) {
    __shared__ float  sk[2][SCH][64];
    __shared__ float  svv[2][SCH][64];
    __shared__ float2 sdb[2][SCH];
    __shared__ int    sfl[2][SCH];

    int half = blockIdx.x;
    int h    = blockIdx.y;
    int s    = blockIdx.z;
    int tid  = threadIdx.x;
    int colL = tid >> 2;
    int e    = tid & 3;
    int col  = half * 64 + colL;

    int start = cu[s];
    int end   = cu[s + 1];
    int len   = end - start;

    auto load_chunk = [&](int buf, int c0) {
        int rem = len - c0; if (rem > SCH) rem = SCH;
        for (int idx = tid; idx < rem * 16; idx += 256) {
            int i = idx >> 4, j = idx & 15;
            cpa16(&sk[buf][i][j * 4], d_k + (size_t)(start + c0 + i) * KDIM + h * HKD + j * 4);
        }
        for (int idx = tid; idx < rem * 16; idx += 256) {
            int i = idx >> 4, j = idx & 15;
            cpa16(&svv[buf][i][j * 4], d_v + (size_t)(start + c0 + i) * VDIM + h * HVD + half * 64 + j * 4);
        }
        if (tid < rem)
            cpa8(&sdb[buf][tid], d_db + (size_t)(start + c0 + tid) * NHH + h);
        if (tid >= 64 && tid - 64 < rem)
            cpa4(&sfl[buf][tid - 64], d_flags + start + c0 + tid - 64);
    };

    float S[16];
#pragma unroll
    for (int i = 0; i < 16; ++i) S[i] = 0.f;

    load_chunk(0, 0);
    CPA_COMMIT;

    int buf = 0;
    for (int c0 = 0; c0 < len; c0 += SCH, buf ^= 1) {
        __syncthreads();
        if (c0 + SCH < len) load_chunk(buf ^ 1, c0 + SCH);
        CPA_COMMIT;
        CPA_WAIT1;
        __syncthreads();

        int rem = len - c0; if (rem > SCH) rem = SCH;

        float4 nk0 = *(const float4*)&sk[buf][0][e * 16 + 0];
        float4 nk1 = *(const float4*)&sk[buf][0][e * 16 + 4];
        float4 nk2 = *(const float4*)&sk[buf][0][e * 16 + 8];
        float4 nk3 = *(const float4*)&sk[buf][0][e * 16 + 12];
        float  nv  = svv[buf][0][colL];
        float2 ndb = sdb[buf][0];
        int    nfl = sfl[buf][0];

        for (int i = 0; i < rem; ++i) {
            float4 k0 = nk0, k1 = nk1, k2 = nk2, k3 = nk3;
            float  vv = nv;
            float2 db = ndb;
            int    fl = nfl;
            int ip = (i + 1 < rem) ? i + 1 : i;
            nk0 = *(const float4*)&sk[buf][ip][e * 16 + 0];
            nk1 = *(const float4*)&sk[buf][ip][e * 16 + 4];
            nk2 = *(const float4*)&sk[buf][ip][e * 16 + 8];
            nk3 = *(const float4*)&sk[buf][ip][e * 16 + 12];
            nv  = svv[buf][ip][colL];
            ndb = sdb[buf][ip];
            nfl = sfl[buf][ip];

            float lam = (fl & 1) ? 0.f : db.x;

            float a0 = S[0]  * k0.x;
            a0 = fmaf(S[1],  k0.y, a0);
            a0 = fmaf(S[2],  k0.z, a0);
            a0 = fmaf(S[3],  k0.w, a0);
            float a1 = S[4]  * k1.x;
            a1 = fmaf(S[5],  k1.y, a1);
            a1 = fmaf(S[6],  k1.z, a1);
            a1 = fmaf(S[7],  k1.w, a1);
            float a2 = S[8]  * k2.x;
            a2 = fmaf(S[9],  k2.y, a2);
            a2 = fmaf(S[10], k2.z, a2);
            a2 = fmaf(S[11], k2.w, a2);
            float a3 = S[12] * k3.x;
            a3 = fmaf(S[13], k3.y, a3);
            a3 = fmaf(S[14], k3.z, a3);
            a3 = fmaf(S[15], k3.w, a3);
            float dot = (a0 + a1) + (a2 + a3);
            dot += __shfl_xor_sync(0xffffffffu, dot, 1);
            dot += __shfl_xor_sync(0xffffffffu, dot, 2);

            float delta = db.y * fmaf(-lam, dot, vv);

            S[0]  = fmaf(lam, S[0],  k0.x * delta);
            S[1]  = fmaf(lam, S[1],  k0.y * delta);
            S[2]  = fmaf(lam, S[2],  k0.z * delta);
            S[3]  = fmaf(lam, S[3],  k0.w * delta);
            S[4]  = fmaf(lam, S[4],  k1.x * delta);
            S[5]  = fmaf(lam, S[5],  k1.y * delta);
            S[6]  = fmaf(lam, S[6],  k1.z * delta);
            S[7]  = fmaf(lam, S[7],  k1.w * delta);
            S[8]  = fmaf(lam, S[8],  k2.x * delta);
            S[9]  = fmaf(lam, S[9],  k2.y * delta);
            S[10] = fmaf(lam, S[10], k2.z * delta);
            S[11] = fmaf(lam, S[11], k2.w * delta);
            S[12] = fmaf(lam, S[12], k3.x * delta);
            S[13] = fmaf(lam, S[13], k3.y * delta);
            S[14] = fmaf(lam, S[14], k3.z * delta);
            S[15] = fmaf(lam, S[15], k3.w * delta);

            int need = fl >> 1;
            if (need) {
                const float* qp = d_q + (size_t)(need - 1) * KDIM + h * HKD + e * 16;
                float4 q0 = *(const float4*)(qp + 0);
                float4 q1 = *(const float4*)(qp + 4);
                float4 q2 = *(const float4*)(qp + 8);
                float4 q3 = *(const float4*)(qp + 12);
                float od = S[0] * q0.x;
                od = fmaf(S[1],  q0.y, od);
                od = fmaf(S[2],  q0.z, od);
                od = fmaf(S[3],  q0.w, od);
                od = fmaf(S[4],  q1.x, od);
                od = fmaf(S[5],  q1.y, od);
                od = fmaf(S[6],  q1.z, od);
                od = fmaf(S[7],  q1.w, od);
                od = fmaf(S[8],  q2.x, od);
                od = fmaf(S[9],  q2.y, od);
                od = fmaf(S[10], q2.z, od);
                od = fmaf(S[11], q2.w, od);
                od = fmaf(S[12], q3.x, od);
                od = fmaf(S[13], q3.y, od);
                od = fmaf(S[14], q3.z, od);
                od = fmaf(S[15], q3.w, od);
                od += __shfl_xor_sync(0xffffffffu, od, 1);
                od += __shfl_xor_sync(0xffffffffu, od, 2);
                if (e == 0) d_o[(need - 1) * VDIM + h * HVD + col] = od;
            }
        }
    }
}

// ---------------- Wo @ W_head ----------------
__global__ void k_wowh(const float* __restrict__ Wo, const float* __restrict__ Wh) {
    int j = blockIdx.x * 8 + (threadIdx.x >> 5);
    int lane = threadIdx.x & 31;
    float a = 0.f;
    for (int k = lane; k < HH; k += 32) a = fmaf(Wo[(size_t)j * HH + k], Wh[k], a);
#pragma unroll
    for (int off = 16; off; off >>= 1) a += __shfl_xor_sync(0xffffffffu, a, off);
    if (lane == 0) d_wowh[j] = a;
}

// ---------------- gating at pooled positions ----------------
__global__ void k_gate(const int* __restrict__ cu, const float* __restrict__ Wg,
                       const float* __restrict__ onw) {
    __shared__ float shn[HH];
    __shared__ float sred[128];
    int hd = blockIdx.x;
    int s = blockIdx.y;
    int pos = cu[s + 1] - 1;
    int tid = threadIdx.x;
    for (int i = tid; i < HH; i += 128) shn[i] = d_hn[(size_t)pos * HH + i];
    __syncthreads();
    float gate = 0.f;
    for (int i = 0; i < HH; ++i)
        gate = fmaf(shn[i], Wg[(size_t)i * VDIM + hd * HVD + tid], gate);
    float ov = d_o[s * VDIM + hd * HVD + tid];
    sred[tid] = ov * ov;
    __syncthreads();
    for (int st = 64; st; st >>= 1) {
        if (tid < st) sred[tid] += sred[tid + st];
        __syncthreads();
    }
    float rms = rsqrtf(sred[0] / (float)HVD + 1e-5f);
    float gs = gate * sigmoidf_(gate);
    d_og[s * VDIM + hd * HVD + tid] = ov * rms * onw[tid] * gs;
}

// ---------------- final head ----------------
__global__ void k_final(const float* __restrict__ Wh, const float* __restrict__ bh,
                        float* __restrict__ out) {
    __shared__ float sred[256];
    int s = blockIdx.x;
    int tid = threadIdx.x;
    float a = 0.f;
    for (int j = tid; j < VDIM; j += 256) a = fmaf(d_og[s * VDIM + j], d_wowh[j], a);
    for (int k = tid; k < HH; k += 256) a = fmaf(d_hrows[s * HH + k], Wh[k], a);
    sred[tid] = a;
    __syncthreads();
    for (int st = 128; st; st >>= 1) {
        if (tid < st) sred[tid] += sred[tid + st];
        __syncthreads();
    }
    if (tid == 0) out[s] = sred[0] + bh[0];
}

// ---------------- launch ----------------
extern "C" void kernel_launch(void* const* d_in, const int* in_sizes, int n_in,
                              void* d_out, int out_size) {
    const float* x     = (const float*)d_in[0];
    const int*   cu    = (const int*)d_in[1];
    const int*   acidx = (const int*)d_in[2];
    const float* actab = (const float*)d_in[3];
    const float* Win   = (const float*)d_in[4];
    const float* bin   = (const float*)d_in[5];
    const float* nw    = (const float*)d_in[6];
    const float* Wq    = (const float*)d_in[7];
    const float* Wk    = (const float*)d_in[8];
    const float* Wv    = (const float*)d_in[9];
    const float* cqw   = (const float*)d_in[10];
    const float* ckw   = (const float*)d_in[11];
    const float* cvw   = (const float*)d_in[12];
    const float* Wb    = (const float*)d_in[13];
    const float* Wa    = (const float*)d_in[14];
    const float* Alog  = (const float*)d_in[15];
    const float* dtb   = (const float*)d_in[16];
    const float* Wg    = (const float*)d_in[17];
    const float* onw   = (const float*)d_in[18];
    const float* Wo    = (const float*)d_in[19];
    const float* Wh    = (const float*)d_in[20];
    const float* bh    = (const float*)d_in[21];
    float* out = (float*)d_out;

    cudaFuncSetAttribute(k_mma, cudaFuncAttributeMaxDynamicSharedMemorySize, MM_SMEM);

    __nv_bfloat16 *wk_hi, *wk_lo, *wv_hi, *wv_lo, *hn_hi, *hn_lo;
    cudaGetSymbolAddress((void**)&wk_hi, d_wk_hi);
    cudaGetSymbolAddress((void**)&wk_lo, d_wk_lo);
    cudaGetSymbolAddress((void**)&wv_hi, d_wv_hi);
    cudaGetSymbolAddress((void**)&wv_lo, d_wv_lo);
    cudaGetSymbolAddress((void**)&hn_hi, d_hnb_hi);
    cudaGetSymbolAddress((void**)&hn_lo, d_hnb_lo);
    float *kpre, *vpre;
    cudaGetSymbolAddress((void**)&kpre, d_kpre);
    cudaGetSymbolAddress((void**)&vpre, d_vpre);

    k_prep<<<TT / 256, 256>>>(cu);
    k_embed<<<TT / 8, 256>>>(x, acidx, actab, Win, bin, nw);

    k_wcvt<<<dim3(KDIM / 32, HH / 32), dim3(32, 8)>>>(Wk, wk_hi, wk_lo, KDIM);
    k_wcvt<<<dim3(VDIM / 32, HH / 32), dim3(32, 8)>>>(Wv, wv_hi, wv_lo, VDIM);

    k_mma<<<dim3(KDIM / 256, TT / 128), 256, MM_SMEM>>>(hn_hi, hn_lo, wk_hi, wk_lo, kpre, KDIM);
    k_mma<<<dim3(VDIM / 256, TT / 128), 256, MM_SMEM>>>(hn_hi, hn_lo, wv_hi, wv_lo, vpre, VDIM);

    k_ab<<<TT / 8, 256>>>(Wa, Wb, Alog, dtb);
    k_conv<<<TT, 256>>>(ckw);
    k_conv2<<<dim3(VDIM / 256, TT / VTCH), 256>>>(cvw);
    k_q16<<<NSEG, 256>>>(cu, Wq, cqw);

    k_scan<<<dim3(2, NHH, NSEG), 256>>>(cu);

    k_wowh<<<VDIM / 8, 256>>>(Wo, Wh);
    k_gate<<<dim3(NHH, NSEG), 128>>>(cu, Wg, onw);
    k_final<<<NSEG, 256>>>(Wh, bh, out);
}

// round 6
// speedup vs baseline: 6.9061x; 1.2461x over previous
#include <cuda_runtime.h>
#include <cuda_fp16.h>
#include <math.h>
#include <stdint.h>

#define TT   32768
#define HH   1024
#define DIN  16
#define ACD  32
#define NHH  12
#define KDIM 768
#define VDIM 1536
#define HKD  64
#define HVD  128
#define NSEG 16
#define SCH  40

// ---------------- scratch ----------------
static __device__ float  d_hn   [TT * HH];
static __device__ __half d_hnf  [TT * HH];
static __device__ __half d_wkf  [KDIM * HH];
static __device__ __half d_wvf  [VDIM * HH];
static __device__ float  d_kpre [TT * KDIM];
static __device__ float  d_vpre [TT * VDIM];
static __device__ float  d_k    [TT * KDIM];
static __device__ float  d_v    [TT * VDIM];
static __device__ float2 d_db   [TT * NHH];
static __device__ int    d_seg  [TT];
static __device__ int    d_flags[TT];
static __device__ float  d_hrows[NSEG * HH];
static __device__ float  d_q    [NSEG * KDIM];
static __device__ float  d_o    [NSEG * VDIM];
static __device__ float  d_og   [NSEG * VDIM];
static __device__ float  d_wowh [VDIM];

__device__ __forceinline__ float sigmoidf_(float x) { return 1.f / (1.f + expf(-x)); }

// ---------------- PTX helpers (base sm_103 features only) ----------------
__device__ __forceinline__ uint32_t smem_u32(const void* p) {
    uint32_t a;
    asm("{ .reg .u64 t; cvta.to.shared.u64 t, %1; cvt.u32.u64 %0, t; }" : "=r"(a) : "l"(p));
    return a;
}
__device__ __forceinline__ void cpa16s(uint32_t s, const void* g) {
    asm volatile("cp.async.cg.shared.global [%0], [%1], 16;" :: "r"(s), "l"(g));
}
__device__ __forceinline__ void cpa16(void* s, const void* g) { cpa16s(smem_u32(s), g); }
__device__ __forceinline__ void cpa8(void* s, const void* g) {
    asm volatile("cp.async.ca.shared.global [%0], [%1], 8;" :: "r"(smem_u32(s)), "l"(g));
}
__device__ __forceinline__ void cpa4(void* s, const void* g) {
    asm volatile("cp.async.ca.shared.global [%0], [%1], 4;" :: "r"(smem_u32(s)), "l"(g));
}
#define CPA_COMMIT asm volatile("cp.async.commit_group;")
#define CPA_WAIT0  asm volatile("cp.async.wait_group 0;")
#define CPA_WAIT1  asm volatile("cp.async.wait_group 1;")

#define LDM4(r, addr) \
    asm volatile("ldmatrix.sync.aligned.m8n8.x4.shared.b16 {%0,%1,%2,%3}, [%4];" \
        : "=r"((r)[0]), "=r"((r)[1]), "=r"((r)[2]), "=r"((r)[3]) : "r"(addr))

#define MMAH(d, a, b0, b1) \
    asm volatile("mma.sync.aligned.m16n8k16.row.col.f32.f16.f16.f32 " \
        "{%0,%1,%2,%3}, {%4,%5,%6,%7}, {%8,%9}, {%0,%1,%2,%3};" \
        : "+f"((d)[0]), "+f"((d)[1]), "+f"((d)[2]), "+f"((d)[3]) \
        : "r"((a)[0]), "r"((a)[1]), "r"((a)[2]), "r"((a)[3]), "r"(b0), "r"(b1))

// ---------------- seg ids + flags ----------------
__global__ void k_prep(const int* __restrict__ cu) {
    int t = blockIdx.x * 256 + threadIdx.x;
    if (t >= TT) return;
    int seg = 0;
#pragma unroll
    for (int s = 1; s <= NSEG; ++s) if (t >= cu[s]) seg = s;
    d_seg[t] = seg;
    int fl = (t == cu[seg]) ? 1 : 0;
#pragma unroll
    for (int s = 0; s < NSEG; ++s) if (t == cu[s + 1] - 1) fl |= ((s + 1) << 1);
    d_flags[t] = fl;
}

// ---------------- embed + rmsnorm + fp16 conversion ----------------
__global__ void k_embed(const float* __restrict__ x, const int* __restrict__ acidx,
                        const float* __restrict__ actab, const float* __restrict__ Win,
                        const float* __restrict__ bin, const float* __restrict__ nw) {
    __shared__ float sx[8][48];
    __shared__ float sps[8][256];
    __shared__ float srms[8];
    int t0 = blockIdx.x * 8;
    int tid = threadIdx.x;
    for (int idx = tid; idx < 8 * 48; idx += 256) {
        int r = idx / 48, i = idx % 48;
        int t = t0 + r;
        float v;
        if (i < DIN) v = x[t * DIN + i];
        else v = actab[acidx[d_seg[t]] * ACD + (i - DIN)];
        sx[r][i] = v;
    }
    __syncthreads();

    float hreg[4][8];
    float ps[8];
#pragma unroll
    for (int r = 0; r < 8; ++r) ps[r] = 0.f;

#pragma unroll
    for (int jj = 0; jj < 4; ++jj) {
        int j = tid + jj * 256;
        float acc[8];
        float bb = bin[j];
#pragma unroll
        for (int r = 0; r < 8; ++r) acc[r] = bb;
        for (int i = 0; i < 48; ++i) {
            float w = Win[i * HH + j];
#pragma unroll
            for (int r = 0; r < 8; ++r) acc[r] = fmaf(sx[r][i], w, acc[r]);
        }
#pragma unroll
        for (int r = 0; r < 8; ++r) { hreg[jj][r] = acc[r]; ps[r] = fmaf(acc[r], acc[r], ps[r]); }
    }
#pragma unroll
    for (int r = 0; r < 8; ++r) sps[r][tid] = ps[r];
    __syncthreads();
    int w = tid >> 5, lane = tid & 31;
    float s = sps[w][lane];
#pragma unroll
    for (int i = 1; i < 8; ++i) s += sps[w][lane + 32 * i];
#pragma unroll
    for (int off = 16; off; off >>= 1) s += __shfl_xor_sync(0xffffffffu, s, off);
    if (lane == 0) srms[w] = rsqrtf(s / (float)HH + 1e-6f);
    __syncthreads();

    int needr[8];
#pragma unroll
    for (int r = 0; r < 8; ++r) needr[r] = d_flags[t0 + r] >> 1;

#pragma unroll
    for (int jj = 0; jj < 4; ++jj) {
        int j = tid + jj * 256;
        float nwj = 1.0f + nw[j];
#pragma unroll
        for (int r = 0; r < 8; ++r) {
            int t = t0 + r;
            float val = hreg[jj][r] * srms[r] * nwj;
            d_hn[t * HH + j] = val;
            d_hnf[(size_t)t * HH + j] = __float2half(val);
            if (needr[r]) d_hrows[(needr[r] - 1) * HH + j] = hreg[jj][r];
        }
    }
}

// ---------------- weight transpose + fp16: W[1024,N] -> out[N,1024] ----------------
__global__ void k_wcvt(const float* __restrict__ W, __half* __restrict__ outw, int N) {
    __shared__ float tile[32][33];
    int n0 = blockIdx.x * 32, k0 = blockIdx.y * 32;
    int tx = threadIdx.x, ty = threadIdx.y;
    for (int i = ty; i < 32; i += 8)
        tile[i][tx] = W[(size_t)(k0 + i) * N + n0 + tx];
    __syncthreads();
    for (int i = ty; i < 32; i += 8)
        outw[(size_t)(n0 + i) * HH + k0 + tx] = __float2half(tile[tx][i]);
}

// ---------------- fp16 single-pass mma.sync GEMM: C[T x N] = hn @ W ----------------
// BM=128, BN=256, BK=32, 8 warps (2x4), warp tile 64x64, 3-stage cp.async.
#define MM_ROW   40
#define MM_ATEN  (128 * MM_ROW)            // 5120
#define MM_BTEN  (256 * MM_ROW)            // 10240
#define MM_STG   (MM_ATEN + MM_BTEN)       // 15360 elems per stage
#define MM_NSTG  3
#define MM_SMEM  (MM_NSTG * MM_STG * 2)    // 92160 bytes
#define MM_NCH   (HH / 32)                 // 32 k-chunks

__global__ void __launch_bounds__(256, 1)
k_mma(const __half* __restrict__ A_, const __half* __restrict__ B_,
      float* __restrict__ C, int N) {
    extern __shared__ __align__(128) __half sm[];
    uint32_t sb = smem_u32(sm);
    int tid = threadIdx.x, lane = tid & 31, wid = tid >> 5;
    int wm = wid & 1, wn = wid >> 1;
    int ntile = blockIdx.x, mtile = blockIdx.y;

    const __half* Af = A_ + (size_t)(mtile * 128) * HH;
    const __half* Bf = B_ + (size_t)(ntile * 256) * HH;

    float acc[4][8][4];
#pragma unroll
    for (int m = 0; m < 4; ++m)
#pragma unroll
        for (int n = 0; n < 8; ++n)
#pragma unroll
            for (int i = 0; i < 4; ++i) acc[m][n][i] = 0.f;

    int ab[4];
#pragma unroll
    for (int m = 0; m < 4; ++m)
        ab[m] = (wm * 64 + m * 16 + (lane & 15)) * MM_ROW + (lane >> 4) * 8;
    int bb[4];
#pragma unroll
    for (int p = 0; p < 4; ++p)
        bb[p] = (wn * 64 + p * 16 + (lane & 7) + ((lane >> 4) & 1) * 8) * MM_ROW + ((lane >> 3) & 1) * 8;

    // stage loader: A 512 + B 1024 16B-chunks, 6 per thread
    auto load_stage = [&](int stg, int k0) {
        uint32_t base = sb + 2 * (stg * MM_STG);
#pragma unroll
        for (int it = 0; it < 2; ++it) {
            int idx = tid + it * 256;
            int r = idx >> 2, cc = idx & 3;
            cpa16s(base + 2 * (r * MM_ROW + cc * 8), Af + (size_t)r * HH + k0 + cc * 8);
        }
#pragma unroll
        for (int it = 0; it < 4; ++it) {
            int idx = tid + it * 256;
            int r = idx >> 2, cc = idx & 3;
            cpa16s(base + 2 * (MM_ATEN + r * MM_ROW + cc * 8), Bf + (size_t)r * HH + k0 + cc * 8);
        }
    };

    load_stage(0, 0);
    CPA_COMMIT;
    load_stage(1, 32);
    CPA_COMMIT;

    for (int c = 0; c < MM_NCH; ++c) {
        int stg = c % MM_NSTG;
        if (c + 1 < MM_NCH) { CPA_WAIT1; } else { CPA_WAIT0; }
        __syncthreads();
        if (c + 2 < MM_NCH) {
            load_stage((c + 2) % MM_NSTG, (c + 2) * 32);
            CPA_COMMIT;
        }

        uint32_t base = sb + 2 * (stg * MM_STG);
#pragma unroll
        for (int ks = 0; ks < 2; ++ks) {
            uint32_t a4[4][4];
#pragma unroll
            for (int m = 0; m < 4; ++m) LDM4(a4[m], base + 2 * (ab[m] + ks * 16));
#pragma unroll
            for (int p = 0; p < 4; ++p) {
                uint32_t rb[4];
                LDM4(rb, base + 2 * (MM_ATEN + bb[p] + ks * 16));
#pragma unroll
                for (int m = 0; m < 4; ++m) {
                    MMAH(acc[m][2 * p],     a4[m], rb[0], rb[1]);
                    MMAH(acc[m][2 * p + 1], a4[m], rb[2], rb[3]);
                }
            }
        }
        __syncthreads();
    }

    // store
#pragma unroll
    for (int m = 0; m < 4; ++m) {
        int row = mtile * 128 + wm * 64 + m * 16 + (lane >> 2);
#pragma unroll
        for (int n = 0; n < 8; ++n) {
            int col = ntile * 256 + wn * 64 + n * 8 + (lane & 3) * 2;
            float2 v0 = make_float2(acc[m][n][0], acc[m][n][1]);
            float2 v1 = make_float2(acc[m][n][2], acc[m][n][3]);
            *(float2*)&C[(size_t)row * N + col] = v0;
            *(float2*)&C[(size_t)(row + 8) * N + col] = v1;
        }
    }
}

// ---------------- hn@Wa, hn@Wb -> decay/beta ----------------
__global__ void k_ab(const float* __restrict__ Wa, const float* __restrict__ Wb,
                     const float* __restrict__ Alog, const float* __restrict__ dtb) {
    int row = blockIdx.x * 8 + (threadIdx.x >> 5);
    int lane = threadIdx.x & 31;
    float aA[NHH], aB[NHH];
#pragma unroll
    for (int c = 0; c < NHH; ++c) { aA[c] = 0.f; aB[c] = 0.f; }
    for (int kk = lane; kk < HH; kk += 32) {
        float hv = d_hn[(size_t)row * HH + kk];
        const float* wa = Wa + kk * NHH;
        const float* wb = Wb + kk * NHH;
#pragma unroll
        for (int c = 0; c < NHH; ++c) {
            aA[c] = fmaf(hv, wa[c], aA[c]);
            aB[c] = fmaf(hv, wb[c], aB[c]);
        }
    }
#pragma unroll
    for (int c = 0; c < NHH; ++c) {
#pragma unroll
        for (int off = 16; off; off >>= 1) {
            aA[c] += __shfl_xor_sync(0xffffffffu, aA[c], off);
            aB[c] += __shfl_xor_sync(0xffffffffu, aB[c], off);
        }
    }
    if (lane < NHH) {
        float xx = aA[lane] + dtb[lane];
        float sp = (xx > 20.f) ? xx : log1pf(expf(xx));
        float g = -expf(Alog[lane]) * sp;
        float2 db;
        db.x = expf(g);
        db.y = sigmoidf_(aB[lane]);
        d_db[(size_t)row * NHH + lane] = db;
    }
}

// ---------------- k-path streaming conv + silu + per-head l2norm ----------------
// grid (KDIM/256, TT/16), 256 threads; block covers 256 channels (4 heads) x 16 t.
__global__ void k_convk(const float* __restrict__ cw) {
    __shared__ float sv[16][256];
    __shared__ float sred[8][16];
    int tid = threadIdx.x;
    int c = blockIdx.x * 256 + tid;
    int t0 = blockIdx.y * 16;
    float w0 = cw[c * 4 + 0], w1 = cw[c * 4 + 1], w2 = cw[c * 4 + 2], w3 = cw[c * 4 + 3];
    float xm1 = 0.f, xm2 = 0.f, xm3 = 0.f;
    int st1 = 1, st2 = 1;
    if (t0 >= 1) { xm1 = d_kpre[(size_t)(t0 - 1) * KDIM + c]; st1 = d_flags[t0 - 1] & 1; }
    if (t0 >= 2) { xm2 = d_kpre[(size_t)(t0 - 2) * KDIM + c]; st2 = d_flags[t0 - 2] & 1; }
    if (t0 >= 3) { xm3 = d_kpre[(size_t)(t0 - 3) * KDIM + c]; }
#pragma unroll 4
    for (int tt = 0; tt < 16; ++tt) {
        int t = t0 + tt;
        float xt = d_kpre[(size_t)t * KDIM + c];
        int st = d_flags[t] & 1;
        float acc = xt * w3;
        if (!st) {
            acc = fmaf(xm1, w2, acc);
            if (!st1) {
                acc = fmaf(xm2, w1, acc);
                if (!st2) acc = fmaf(xm3, w0, acc);
            }
        }
        sv[tt][tid] = acc * sigmoidf_(acc);
        xm3 = xm2; xm2 = xm1; xm1 = xt;
        st2 = st1; st1 = st;
    }
    __syncthreads();
    int w = tid >> 5, lane = tid & 31;
#pragma unroll
    for (int tt = 0; tt < 16; ++tt) {
        float v = sv[tt][w * 32 + lane];
        float ssq = v * v;
#pragma unroll
        for (int off = 16; off; off >>= 1) ssq += __shfl_xor_sync(0xffffffffu, ssq, off);
        if (lane == 0) sred[w][tt] = ssq;
    }
    __syncthreads();
    int hl = tid >> 6;
#pragma unroll
    for (int tt = 0; tt < 16; ++tt) {
        float ss = sred[hl * 2][tt] + sred[hl * 2 + 1][tt];
        d_k[(size_t)(t0 + tt) * KDIM + c] = sv[tt][tid] * rsqrtf(ss + 1e-6f);
    }
}

// ---------------- v-path streaming conv + silu ----------------
#define VTCH 16
__global__ void k_conv2(const float* __restrict__ cw) {
    int c = blockIdx.x * 256 + threadIdx.x;
    int t0 = blockIdx.y * VTCH;
    float w0 = cw[c * 4 + 0], w1 = cw[c * 4 + 1], w2 = cw[c * 4 + 2], w3 = cw[c * 4 + 3];
    float xm1 = 0.f, xm2 = 0.f, xm3 = 0.f;
    int st1 = 1, st2 = 1;
    if (t0 >= 1) { xm1 = d_vpre[(size_t)(t0 - 1) * VDIM + c]; st1 = d_flags[t0 - 1] & 1; }
    if (t0 >= 2) { xm2 = d_vpre[(size_t)(t0 - 2) * VDIM + c]; st2 = d_flags[t0 - 2] & 1; }
    if (t0 >= 3) { xm3 = d_vpre[(size_t)(t0 - 3) * VDIM + c]; }
#pragma unroll 4
    for (int t = t0; t < t0 + VTCH; ++t) {
        float xt = d_vpre[(size_t)t * VDIM + c];
        int st = d_flags[t] & 1;
        float acc = xt * w3;
        if (!st) {
            acc = fmaf(xm1, w2, acc);
            if (!st1) {
                acc = fmaf(xm2, w1, acc);
                if (!st2) acc = fmaf(xm3, w0, acc);
            }
        }
        d_v[(size_t)t * VDIM + c] = acc * sigmoidf_(acc);
        xm3 = xm2; xm2 = xm1; xm1 = xt;
        st2 = st1; st1 = st;
    }
}

// ---------------- q at the 16 pooled positions ----------------
__global__ void k_q16(const int* __restrict__ cu, const float* __restrict__ Wq,
                      const float* __restrict__ cw) {
    __shared__ float shn[4][HH];
    __shared__ float sq[KDIM];
    int s = blockIdx.x;
    int pos = cu[s + 1] - 1;
    int seg = d_seg[pos];
    int tid = threadIdx.x;
    int valid[4];
#pragma unroll
    for (int r = 0; r < 4; ++r) {
        int t = pos - r;
        valid[r] = (t >= 0 && d_seg[t] == seg);
    }
#pragma unroll
    for (int r = 0; r < 4; ++r) {
        int t = pos - r;
        if (valid[r]) for (int i = tid; i < HH; i += 256) shn[r][i] = d_hn[(size_t)t * HH + i];
        else          for (int i = tid; i < HH; i += 256) shn[r][i] = 0.f;
    }
    __syncthreads();
    for (int c = tid; c < KDIM; c += 256) {
        float a0 = 0.f, a1 = 0.f, a2 = 0.f, a3 = 0.f;
        for (int i = 0; i < HH; ++i) {
            float wv = Wq[(size_t)i * KDIM + c];
            a0 = fmaf(shn[0][i], wv, a0);
            a1 = fmaf(shn[1][i], wv, a1);
            a2 = fmaf(shn[2][i], wv, a2);
            a3 = fmaf(shn[3][i], wv, a3);
        }
        float acc = a0 * cw[c * 4 + 3] + a1 * cw[c * 4 + 2] + a2 * cw[c * 4 + 1] + a3 * cw[c * 4 + 0];
        sq[c] = acc * sigmoidf_(acc);
    }
    __syncthreads();
    int w = tid >> 5, lane = tid & 31;
    for (int h = w; h < NHH; h += 8) {
        float ssq = 0.f;
        for (int i = lane; i < HKD; i += 32) { float v = sq[h * HKD + i]; ssq = fmaf(v, v, ssq); }
#pragma unroll
        for (int off = 16; off; off >>= 1) ssq += __shfl_xor_sync(0xffffffffu, ssq, off);
        float r = rsqrtf(ssq + 1e-6f) * 0.125f;
        for (int i = lane; i < HKD; i += 32)
            d_q[s * KDIM + h * HKD + i] = sq[h * HKD + i] * r;
    }
}

// ---------------- segment-parallel scan ----------------
__global__ void __launch_bounds__(256) k_scan(const int* __restrict__ cu) {
    __shared__ float  sk[2][SCH][64];
    __shared__ float  svv[2][SCH][64];
    __shared__ float2 sdb[2][SCH];
    __shared__ int    sfl[2][SCH];

    int half = blockIdx.x;
    int h    = blockIdx.y;
    int s    = blockIdx.z;
    int tid  = threadIdx.x;
    int colL = tid >> 2;
    int e    = tid & 3;
    int col  = half * 64 + colL;

    int start = cu[s];
    int end   = cu[s + 1];
    int len   = end - start;

    auto load_chunk = [&](int buf, int c0) {
        int rem = len - c0; if (rem > SCH) rem = SCH;
        for (int idx = tid; idx < rem * 16; idx += 256) {
            int i = idx >> 4, j = idx & 15;
            cpa16(&sk[buf][i][j * 4], d_k + (size_t)(start + c0 + i) * KDIM + h * HKD + j * 4);
        }
        for (int idx = tid; idx < rem * 16; idx += 256) {
            int i = idx >> 4, j = idx & 15;
            cpa16(&svv[buf][i][j * 4], d_v + (size_t)(start + c0 + i) * VDIM + h * HVD + half * 64 + j * 4);
        }
        if (tid < rem)
            cpa8(&sdb[buf][tid], d_db + (size_t)(start + c0 + tid) * NHH + h);
        if (tid >= 64 && tid - 64 < rem)
            cpa4(&sfl[buf][tid - 64], d_flags + start + c0 + tid - 64);
    };

    float S[16];
#pragma unroll
    for (int i = 0; i < 16; ++i) S[i] = 0.f;

    load_chunk(0, 0);
    CPA_COMMIT;

    int buf = 0;
    for (int c0 = 0; c0 < len; c0 += SCH, buf ^= 1) {
        __syncthreads();
        if (c0 + SCH < len) load_chunk(buf ^ 1, c0 + SCH);
        CPA_COMMIT;
        CPA_WAIT1;
        __syncthreads();

        int rem = len - c0; if (rem > SCH) rem = SCH;

        float4 nk0 = *(const float4*)&sk[buf][0][e * 16 + 0];
        float4 nk1 = *(const float4*)&sk[buf][0][e * 16 + 4];
        float4 nk2 = *(const float4*)&sk[buf][0][e * 16 + 8];
        float4 nk3 = *(const float4*)&sk[buf][0][e * 16 + 12];
        float  nv  = svv[buf][0][colL];
        float2 ndb = sdb[buf][0];
        int    nfl = sfl[buf][0];

        for (int i = 0; i < rem; ++i) {
            float4 k0 = nk0, k1 = nk1, k2 = nk2, k3 = nk3;
            float  vv = nv;
            float2 db = ndb;
            int    fl = nfl;
            int ip = (i + 1 < rem) ? i + 1 : i;
            nk0 = *(const float4*)&sk[buf][ip][e * 16 + 0];
            nk1 = *(const float4*)&sk[buf][ip][e * 16 + 4];
            nk2 = *(const float4*)&sk[buf][ip][e * 16 + 8];
            nk3 = *(const float4*)&sk[buf][ip][e * 16 + 12];
            nv  = svv[buf][ip][colL];
            ndb = sdb[buf][ip];
            nfl = sfl[buf][ip];

            float lam = (fl & 1) ? 0.f : db.x;

            float a0 = S[0]  * k0.x;
            a0 = fmaf(S[1],  k0.y, a0);
            a0 = fmaf(S[2],  k0.z, a0);
            a0 = fmaf(S[3],  k0.w, a0);
            float a1 = S[4]  * k1.x;
            a1 = fmaf(S[5],  k1.y, a1);
            a1 = fmaf(S[6],  k1.z, a1);
            a1 = fmaf(S[7],  k1.w, a1);
            float a2 = S[8]  * k2.x;
            a2 = fmaf(S[9],  k2.y, a2);
            a2 = fmaf(S[10], k2.z, a2);
            a2 = fmaf(S[11], k2.w, a2);
            float a3 = S[12] * k3.x;
            a3 = fmaf(S[13], k3.y, a3);
            a3 = fmaf(S[14], k3.z, a3);
            a3 = fmaf(S[15], k3.w, a3);
            float dot = (a0 + a1) + (a2 + a3);
            dot += __shfl_xor_sync(0xffffffffu, dot, 1);
            dot += __shfl_xor_sync(0xffffffffu, dot, 2);

            float delta = db.y * fmaf(-lam, dot, vv);

            S[0]  = fmaf(lam, S[0],  k0.x * delta);
            S[1]  = fmaf(lam, S[1],  k0.y * delta);
            S[2]  = fmaf(lam, S[2],  k0.z * delta);
            S[3]  = fmaf(lam, S[3],  k0.w * delta);
            S[4]  = fmaf(lam, S[4],  k1.x * delta);
            S[5]  = fmaf(lam, S[5],  k1.y * delta);
            S[6]  = fmaf(lam, S[6],  k1.z * delta);
            S[7]  = fmaf(lam, S[7],  k1.w * delta);
            S[8]  = fmaf(lam, S[8],  k2.x * delta);
            S[9]  = fmaf(lam, S[9],  k2.y * delta);
            S[10] = fmaf(lam, S[10], k2.z * delta);
            S[11] = fmaf(lam, S[11], k2.w * delta);
            S[12] = fmaf(lam, S[12], k3.x * delta);
            S[13] = fmaf(lam, S[13], k3.y * delta);
            S[14] = fmaf(lam, S[14], k3.z * delta);
            S[15] = fmaf(lam, S[15], k3.w * delta);

            int need = fl >> 1;
            if (need) {
                const float* qp = d_q + (size_t)(need - 1) * KDIM + h * HKD + e * 16;
                float4 q0 = *(const float4*)(qp + 0);
                float4 q1 = *(const float4*)(qp + 4);
                float4 q2 = *(const float4*)(qp + 8);
                float4 q3 = *(const float4*)(qp + 12);
                float od = S[0] * q0.x;
                od = fmaf(S[1],  q0.y, od);
                od = fmaf(S[2],  q0.z, od);
                od = fmaf(S[3],  q0.w, od);
                od = fmaf(S[4],  q1.x, od);
                od = fmaf(S[5],  q1.y, od);
                od = fmaf(S[6],  q1.z, od);
                od = fmaf(S[7],  q1.w, od);
                od = fmaf(S[8],  q2.x, od);
                od = fmaf(S[9],  q2.y, od);
                od = fmaf(S[10], q2.z, od);
                od = fmaf(S[11], q2.w, od);
                od = fmaf(S[12], q3.x, od);
                od = fmaf(S[13], q3.y, od);
                od = fmaf(S[14], q3.z, od);
                od = fmaf(S[15], q3.w, od);
                od += __shfl_xor_sync(0xffffffffu, od, 1);
                od += __shfl_xor_sync(0xffffffffu, od, 2);
                if (e == 0) d_o[(need - 1) * VDIM + h * HVD + col] = od;
            }
        }
    }
}

// ---------------- Wo @ W_head ----------------
__global__ void k_wowh(const float* __restrict__ Wo, const float* __restrict__ Wh) {
    int j = blockIdx.x * 8 + (threadIdx.x >> 5);
    int lane = threadIdx.x & 31;
    float a = 0.f;
    for (int k = lane; k < HH; k += 32) a = fmaf(Wo[(size_t)j * HH + k], Wh[k], a);
#pragma unroll
    for (int off = 16; off; off >>= 1) a += __shfl_xor_sync(0xffffffffu, a, off);
    if (lane == 0) d_wowh[j] = a;
}

// ---------------- gating at pooled positions ----------------
__global__ void k_gate(const int* __restrict__ cu, const float* __restrict__ Wg,
                       const float* __restrict__ onw) {
    __shared__ float shn[HH];
    __shared__ float sred[128];
    int hd = blockIdx.x;
    int s = blockIdx.y;
    int pos = cu[s + 1] - 1;
    int tid = threadIdx.x;
    for (int i = tid; i < HH; i += 128) shn[i] = d_hn[(size_t)pos * HH + i];
    __syncthreads();
    float gate = 0.f;
    for (int i = 0; i < HH; ++i)
        gate = fmaf(shn[i], Wg[(size_t)i * VDIM + hd * HVD + tid], gate);
    float ov = d_o[s * VDIM + hd * HVD + tid];
    sred[tid] = ov * ov;
    __syncthreads();
    for (int st = 64; st; st >>= 1) {
        if (tid < st) sred[tid] += sred[tid + st];
        __syncthreads();
    }
    float rms = rsqrtf(sred[0] / (float)HVD + 1e-5f);
    float gs = gate * sigmoidf_(gate);
    d_og[s * VDIM + hd * HVD + tid] = ov * rms * onw[tid] * gs;
}

// ---------------- final head ----------------
__global__ void k_final(const float* __restrict__ Wh, const float* __restrict__ bh,
                        float* __restrict__ out) {
    __shared__ float sred[256];
    int s = blockIdx.x;
    int tid = threadIdx.x;
    float a = 0.f;
    for (int j = tid; j < VDIM; j += 256) a = fmaf(d_og[s * VDIM + j], d_wowh[j], a);
    for (int k = tid; k < HH; k += 256) a = fmaf(d_hrows[s * HH + k], Wh[k], a);
    sred[tid] = a;
    __syncthreads();
    for (int st = 128; st; st >>= 1) {
        if (tid < st) sred[tid] += sred[tid + st];
        __syncthreads();
    }
    if (tid == 0) out[s] = sred[0] + bh[0];
}

// ---------------- launch ----------------
extern "C" void kernel_launch(void* const* d_in, const int* in_sizes, int n_in,
                              void* d_out, int out_size) {
    const float* x     = (const float*)d_in[0];
    const int*   cu    = (const int*)d_in[1];
    const int*   acidx = (const int*)d_in[2];
    const float* actab = (const float*)d_in[3];
    const float* Win   = (const float*)d_in[4];
    const float* bin   = (const float*)d_in[5];
    const float* nw    = (const float*)d_in[6];
    const float* Wq    = (const float*)d_in[7];
    const float* Wk    = (const float*)d_in[8];
    const float* Wv    = (const float*)d_in[9];
    const float* cqw   = (const float*)d_in[10];
    const float* ckw   = (const float*)d_in[11];
    const float* cvw   = (const float*)d_in[12];
    const float* Wb    = (const float*)d_in[13];
    const float* Wa    = (const float*)d_in[14];
    const float* Alog  = (const float*)d_in[15];
    const float* dtb   = (const float*)d_in[16];
    const float* Wg    = (const float*)d_in[17];
    const float* onw   = (const float*)d_in[18];
    const float* Wo    = (const float*)d_in[19];
    const float* Wh    = (const float*)d_in[20];
    const float* bh    = (const float*)d_in[21];
    float* out = (float*)d_out;

    cudaFuncSetAttribute(k_mma, cudaFuncAttributeMaxDynamicSharedMemorySize, MM_SMEM);

    __half *wkf, *wvf, *hnf;
    cudaGetSymbolAddress((void**)&wkf, d_wkf);
    cudaGetSymbolAddress((void**)&wvf, d_wvf);
    cudaGetSymbolAddress((void**)&hnf, d_hnf);
    float *kpre, *vpre;
    cudaGetSymbolAddress((void**)&kpre, d_kpre);
    cudaGetSymbolAddress((void**)&vpre, d_vpre);

    k_prep<<<TT / 256, 256>>>(cu);
    k_embed<<<TT / 8, 256>>>(x, acidx, actab, Win, bin, nw);

    k_wcvt<<<dim3(KDIM / 32, HH / 32), dim3(32, 8)>>>(Wk, wkf, KDIM);
    k_wcvt<<<dim3(VDIM / 32, HH / 32), dim3(32, 8)>>>(Wv, wvf, VDIM);

    k_mma<<<dim3(KDIM / 256, TT / 128), 256, MM_SMEM>>>(hnf, wkf, kpre, KDIM);
    k_mma<<<dim3(VDIM / 256, TT / 128), 256, MM_SMEM>>>(hnf, wvf, vpre, VDIM);

    k_ab<<<TT / 8, 256>>>(Wa, Wb, Alog, dtb);
    k_convk<<<dim3(KDIM / 256, TT / 16), 256>>>(ckw);
    k_conv2<<<dim3(VDIM / 256, TT / VTCH), 256>>>(cvw);
    k_q16<<<NSEG, 256>>>(cu, Wq, cqw);

    k_scan<<<dim3(2, NHH, NSEG), 256>>>(cu);

    k_wowh<<<VDIM / 8, 256>>>(Wo, Wh);
    k_gate<<<dim3(NHH, NSEG), 128>>>(cu, Wg, onw);
    k_final<<<NSEG, 256>>>(Wh, bh, out);
}

// round 7
// speedup vs baseline: 7.1026x; 1.0285x over previous
#include <cuda_runtime.h>
#include <cuda_fp16.h>
#include <math.h>
#include <stdint.h>

#define TT   32768
#define HH   1024
#define DIN  16
#define ACD  32
#define NHH  12
#define KDIM 768
#define VDIM 1536
#define HKD  64
#define HVD  128
#define NSEG 16
#define SCH  40

// ---------------- scratch ----------------
static __device__ float  d_hn   [TT * HH];
static __device__ __half d_hnf  [TT * HH];
static __device__ __half d_wkf  [KDIM * HH];
static __device__ __half d_wvf  [VDIM * HH];
static __device__ float  d_kpre [TT * KDIM];
static __device__ float  d_vpre [TT * VDIM];
static __device__ float  d_k    [TT * KDIM];
static __device__ float  d_v    [TT * VDIM];
static __device__ float2 d_db   [TT * NHH];
static __device__ int    d_seg  [TT];
static __device__ int    d_flags[TT];
static __device__ float  d_hrows[NSEG * HH];
static __device__ float  d_q    [NSEG * KDIM];
static __device__ float  d_o    [NSEG * VDIM];
static __device__ float  d_og   [NSEG * VDIM];
static __device__ float  d_wowh [VDIM];

__device__ __forceinline__ float sigmoidf_(float x) { return 1.f / (1.f + expf(-x)); }

// ---------------- PTX helpers (base sm_103 features only) ----------------
__device__ __forceinline__ uint32_t smem_u32(const void* p) {
    uint32_t a;
    asm("{ .reg .u64 t; cvta.to.shared.u64 t, %1; cvt.u32.u64 %0, t; }" : "=r"(a) : "l"(p));
    return a;
}
__device__ __forceinline__ void cpa16s(uint32_t s, const void* g) {
    asm volatile("cp.async.cg.shared.global [%0], [%1], 16;" :: "r"(s), "l"(g));
}
__device__ __forceinline__ void cpa16(void* s, const void* g) { cpa16s(smem_u32(s), g); }
__device__ __forceinline__ void cpa8(void* s, const void* g) {
    asm volatile("cp.async.ca.shared.global [%0], [%1], 8;" :: "r"(smem_u32(s)), "l"(g));
}
__device__ __forceinline__ void cpa4(void* s, const void* g) {
    asm volatile("cp.async.ca.shared.global [%0], [%1], 4;" :: "r"(smem_u32(s)), "l"(g));
}
#define CPA_COMMIT asm volatile("cp.async.commit_group;")
#define CPA_WAIT0  asm volatile("cp.async.wait_group 0;")
#define CPA_WAIT1  asm volatile("cp.async.wait_group 1;")

#define LDM4(r, addr) \
    asm volatile("ldmatrix.sync.aligned.m8n8.x4.shared.b16 {%0,%1,%2,%3}, [%4];" \
        : "=r"((r)[0]), "=r"((r)[1]), "=r"((r)[2]), "=r"((r)[3]) : "r"(addr))

#define MMAH(d, a, b0, b1) \
    asm volatile("mma.sync.aligned.m16n8k16.row.col.f32.f16.f16.f32 " \
        "{%0,%1,%2,%3}, {%4,%5,%6,%7}, {%8,%9}, {%0,%1,%2,%3};" \
        : "+f"((d)[0]), "+f"((d)[1]), "+f"((d)[2]), "+f"((d)[3]) \
        : "r"((a)[0]), "r"((a)[1]), "r"((a)[2]), "r"((a)[3]), "r"(b0), "r"(b1))

// ---------------- seg ids + flags ----------------
__global__ void k_prep(const int* __restrict__ cu) {
    int t = blockIdx.x * 256 + threadIdx.x;
    if (t >= TT) return;
    int seg = 0;
#pragma unroll
    for (int s = 1; s <= NSEG; ++s) if (t >= cu[s]) seg = s;
    d_seg[t] = seg;
    int fl = (t == cu[seg]) ? 1 : 0;
#pragma unroll
    for (int s = 0; s < NSEG; ++s) if (t == cu[s + 1] - 1) fl |= ((s + 1) << 1);
    d_flags[t] = fl;
}

// ---------------- embed + rmsnorm + fp16 conversion ----------------
__global__ void k_embed(const float* __restrict__ x, const int* __restrict__ acidx,
                        const float* __restrict__ actab, const float* __restrict__ Win,
                        const float* __restrict__ bin, const float* __restrict__ nw) {
    __shared__ float sx[8][48];
    __shared__ float sps[8][256];
    __shared__ float srms[8];
    int t0 = blockIdx.x * 8;
    int tid = threadIdx.x;
    for (int idx = tid; idx < 8 * 48; idx += 256) {
        int r = idx / 48, i = idx % 48;
        int t = t0 + r;
        float v;
        if (i < DIN) v = x[t * DIN + i];
        else v = actab[acidx[d_seg[t]] * ACD + (i - DIN)];
        sx[r][i] = v;
    }
    __syncthreads();

    float hreg[4][8];
    float ps[8];
#pragma unroll
    for (int r = 0; r < 8; ++r) ps[r] = 0.f;

#pragma unroll
    for (int jj = 0; jj < 4; ++jj) {
        int j = tid + jj * 256;
        float acc[8];
        float bb = bin[j];
#pragma unroll
        for (int r = 0; r < 8; ++r) acc[r] = bb;
        for (int i = 0; i < 48; ++i) {
            float w = Win[i * HH + j];
#pragma unroll
            for (int r = 0; r < 8; ++r) acc[r] = fmaf(sx[r][i], w, acc[r]);
        }
#pragma unroll
        for (int r = 0; r < 8; ++r) { hreg[jj][r] = acc[r]; ps[r] = fmaf(acc[r], acc[r], ps[r]); }
    }
#pragma unroll
    for (int r = 0; r < 8; ++r) sps[r][tid] = ps[r];
    __syncthreads();
    int w = tid >> 5, lane = tid & 31;
    float s = sps[w][lane];
#pragma unroll
    for (int i = 1; i < 8; ++i) s += sps[w][lane + 32 * i];
#pragma unroll
    for (int off = 16; off; off >>= 1) s += __shfl_xor_sync(0xffffffffu, s, off);
    if (lane == 0) srms[w] = rsqrtf(s / (float)HH + 1e-6f);
    __syncthreads();

    int needr[8];
#pragma unroll
    for (int r = 0; r < 8; ++r) needr[r] = d_flags[t0 + r] >> 1;

#pragma unroll
    for (int jj = 0; jj < 4; ++jj) {
        int j = tid + jj * 256;
        float nwj = 1.0f + nw[j];
#pragma unroll
        for (int r = 0; r < 8; ++r) {
            int t = t0 + r;
            float val = hreg[jj][r] * srms[r] * nwj;
            d_hn[t * HH + j] = val;
            d_hnf[(size_t)t * HH + j] = __float2half(val);
            if (needr[r]) d_hrows[(needr[r] - 1) * HH + j] = hreg[jj][r];
        }
    }
}

// ---------------- weight transpose + fp16: W[1024,N] -> out[N,1024] ----------------
__global__ void k_wcvt(const float* __restrict__ W, __half* __restrict__ outw, int N) {
    __shared__ float tile[32][33];
    int n0 = blockIdx.x * 32, k0 = blockIdx.y * 32;
    int tx = threadIdx.x, ty = threadIdx.y;
    for (int i = ty; i < 32; i += 8)
        tile[i][tx] = W[(size_t)(k0 + i) * N + n0 + tx];
    __syncthreads();
    for (int i = ty; i < 32; i += 8)
        outw[(size_t)(n0 + i) * HH + k0 + tx] = __float2half(tile[tx][i]);
}

// ---------------- fp16 mma.sync GEMM: C[T x N] = hn @ W ----------------
// BM=128, BN=128, BK=32, 8 warps (2x4), warp tile 64x32, 3-stage cp.async,
// 2 CTAs/SM (4 warps/SMSP) for HMMA latency hiding.
#define MM_ROW   40
#define MM_ATEN  (128 * MM_ROW)            // 5120
#define MM_BTEN  (128 * MM_ROW)            // 5120
#define MM_STG   (MM_ATEN + MM_BTEN)       // 10240 elems per stage
#define MM_NSTG  3
#define MM_SMEM  (MM_NSTG * MM_STG * 2)    // 61440 bytes
#define MM_NCH   (HH / 32)                 // 32 k-chunks

__global__ void __launch_bounds__(256, 2)
k_mma(const __half* __restrict__ A_, const __half* __restrict__ B_,
      float* __restrict__ C, int N) {
    extern __shared__ __align__(128) __half sm[];
    uint32_t sb = smem_u32(sm);
    int tid = threadIdx.x, lane = tid & 31, wid = tid >> 5;
    int wm = wid & 1, wn = wid >> 1;
    int ntile = blockIdx.x, mtile = blockIdx.y;

    const __half* Af = A_ + (size_t)(mtile * 128) * HH;
    const __half* Bf = B_ + (size_t)(ntile * 128) * HH;

    float acc[4][4][4];
#pragma unroll
    for (int m = 0; m < 4; ++m)
#pragma unroll
        for (int n = 0; n < 4; ++n)
#pragma unroll
            for (int i = 0; i < 4; ++i) acc[m][n][i] = 0.f;

    int ab[4];
#pragma unroll
    for (int m = 0; m < 4; ++m)
        ab[m] = (wm * 64 + m * 16 + (lane & 15)) * MM_ROW + (lane >> 4) * 8;
    int bb[2];
#pragma unroll
    for (int p = 0; p < 2; ++p)
        bb[p] = (wn * 32 + p * 16 + (lane & 7) + ((lane >> 4) & 1) * 8) * MM_ROW + ((lane >> 3) & 1) * 8;

    // stage loader: A 512 + B 512 16B-chunks, 4 per thread
    auto load_stage = [&](int stg, int k0) {
        uint32_t base = sb + 2 * (stg * MM_STG);
#pragma unroll
        for (int it = 0; it < 2; ++it) {
            int idx = tid + it * 256;
            int r = idx >> 2, cc = idx & 3;
            cpa16s(base + 2 * (r * MM_ROW + cc * 8), Af + (size_t)r * HH + k0 + cc * 8);
        }
#pragma unroll
        for (int it = 0; it < 2; ++it) {
            int idx = tid + it * 256;
            int r = idx >> 2, cc = idx & 3;
            cpa16s(base + 2 * (MM_ATEN + r * MM_ROW + cc * 8), Bf + (size_t)r * HH + k0 + cc * 8);
        }
    };

    load_stage(0, 0);
    CPA_COMMIT;
    load_stage(1, 32);
    CPA_COMMIT;

    for (int c = 0; c < MM_NCH; ++c) {
        int stg = c % MM_NSTG;
        if (c + 1 < MM_NCH) { CPA_WAIT1; } else { CPA_WAIT0; }
        __syncthreads();
        if (c + 2 < MM_NCH) {
            load_stage((c + 2) % MM_NSTG, (c + 2) * 32);
            CPA_COMMIT;
        }

        uint32_t base = sb + 2 * (stg * MM_STG);
#pragma unroll
        for (int ks = 0; ks < 2; ++ks) {
            uint32_t a4[4][4];
#pragma unroll
            for (int m = 0; m < 4; ++m) LDM4(a4[m], base + 2 * (ab[m] + ks * 16));
#pragma unroll
            for (int p = 0; p < 2; ++p) {
                uint32_t rb[4];
                LDM4(rb, base + 2 * (MM_ATEN + bb[p] + ks * 16));
#pragma unroll
                for (int m = 0; m < 4; ++m) {
                    MMAH(acc[m][2 * p],     a4[m], rb[0], rb[1]);
                    MMAH(acc[m][2 * p + 1], a4[m], rb[2], rb[3]);
                }
            }
        }
        __syncthreads();
    }

    // store
#pragma unroll
    for (int m = 0; m < 4; ++m) {
        int row = mtile * 128 + wm * 64 + m * 16 + (lane >> 2);
#pragma unroll
        for (int n = 0; n < 4; ++n) {
            int col = ntile * 128 + wn * 32 + n * 8 + (lane & 3) * 2;
            float2 v0 = make_float2(acc[m][n][0], acc[m][n][1]);
            float2 v1 = make_float2(acc[m][n][2], acc[m][n][3]);
            *(float2*)&C[(size_t)row * N + col] = v0;
            *(float2*)&C[(size_t)(row + 8) * N + col] = v1;
        }
    }
}

// ---------------- hn@Wa, hn@Wb -> decay/beta ----------------
__global__ void k_ab(const float* __restrict__ Wa, const float* __restrict__ Wb,
                     const float* __restrict__ Alog, const float* __restrict__ dtb) {
    int row = blockIdx.x * 8 + (threadIdx.x >> 5);
    int lane = threadIdx.x & 31;
    float aA[NHH], aB[NHH];
#pragma unroll
    for (int c = 0; c < NHH; ++c) { aA[c] = 0.f; aB[c] = 0.f; }
    for (int kk = lane; kk < HH; kk += 32) {
        float hv = d_hn[(size_t)row * HH + kk];
        const float* wa = Wa + kk * NHH;
        const float* wb = Wb + kk * NHH;
#pragma unroll
        for (int c = 0; c < NHH; ++c) {
            aA[c] = fmaf(hv, wa[c], aA[c]);
            aB[c] = fmaf(hv, wb[c], aB[c]);
        }
    }
#pragma unroll
    for (int c = 0; c < NHH; ++c) {
#pragma unroll
        for (int off = 16; off; off >>= 1) {
            aA[c] += __shfl_xor_sync(0xffffffffu, aA[c], off);
            aB[c] += __shfl_xor_sync(0xffffffffu, aB[c], off);
        }
    }
    if (lane < NHH) {
        float xx = aA[lane] + dtb[lane];
        float sp = (xx > 20.f) ? xx : log1pf(expf(xx));
        float g = -expf(Alog[lane]) * sp;
        float2 db;
        db.x = expf(g);
        db.y = sigmoidf_(aB[lane]);
        d_db[(size_t)row * NHH + lane] = db;
    }
}

// ---------------- k-path streaming conv + silu + per-head l2norm ----------------
__global__ void k_convk(const float* __restrict__ cw) {
    __shared__ float sv[16][256];
    __shared__ float sred[8][16];
    int tid = threadIdx.x;
    int c = blockIdx.x * 256 + tid;
    int t0 = blockIdx.y * 16;
    float w0 = cw[c * 4 + 0], w1 = cw[c * 4 + 1], w2 = cw[c * 4 + 2], w3 = cw[c * 4 + 3];
    float xm1 = 0.f, xm2 = 0.f, xm3 = 0.f;
    int st1 = 1, st2 = 1;
    if (t0 >= 1) { xm1 = d_kpre[(size_t)(t0 - 1) * KDIM + c]; st1 = d_flags[t0 - 1] & 1; }
    if (t0 >= 2) { xm2 = d_kpre[(size_t)(t0 - 2) * KDIM + c]; st2 = d_flags[t0 - 2] & 1; }
    if (t0 >= 3) { xm3 = d_kpre[(size_t)(t0 - 3) * KDIM + c]; }
#pragma unroll 4
    for (int tt = 0; tt < 16; ++tt) {
        int t = t0 + tt;
        float xt = d_kpre[(size_t)t * KDIM + c];
        int st = d_flags[t] & 1;
        float acc = xt * w3;
        if (!st) {
            acc = fmaf(xm1, w2, acc);
            if (!st1) {
                acc = fmaf(xm2, w1, acc);
                if (!st2) acc = fmaf(xm3, w0, acc);
            }
        }
        sv[tt][tid] = acc * sigmoidf_(acc);
        xm3 = xm2; xm2 = xm1; xm1 = xt;
        st2 = st1; st1 = st;
    }
    __syncthreads();
    int w = tid >> 5, lane = tid & 31;
#pragma unroll
    for (int tt = 0; tt < 16; ++tt) {
        float v = sv[tt][w * 32 + lane];
        float ssq = v * v;
#pragma unroll
        for (int off = 16; off; off >>= 1) ssq += __shfl_xor_sync(0xffffffffu, ssq, off);
        if (lane == 0) sred[w][tt] = ssq;
    }
    __syncthreads();
    int hl = tid >> 6;
#pragma unroll
    for (int tt = 0; tt < 16; ++tt) {
        float ss = sred[hl * 2][tt] + sred[hl * 2 + 1][tt];
        d_k[(size_t)(t0 + tt) * KDIM + c] = sv[tt][tid] * rsqrtf(ss + 1e-6f);
    }
}

// ---------------- v-path streaming conv + silu ----------------
#define VTCH 16
__global__ void k_conv2(const float* __restrict__ cw) {
    int c = blockIdx.x * 256 + threadIdx.x;
    int t0 = blockIdx.y * VTCH;
    float w0 = cw[c * 4 + 0], w1 = cw[c * 4 + 1], w2 = cw[c * 4 + 2], w3 = cw[c * 4 + 3];
    float xm1 = 0.f, xm2 = 0.f, xm3 = 0.f;
    int st1 = 1, st2 = 1;
    if (t0 >= 1) { xm1 = d_vpre[(size_t)(t0 - 1) * VDIM + c]; st1 = d_flags[t0 - 1] & 1; }
    if (t0 >= 2) { xm2 = d_vpre[(size_t)(t0 - 2) * VDIM + c]; st2 = d_flags[t0 - 2] & 1; }
    if (t0 >= 3) { xm3 = d_vpre[(size_t)(t0 - 3) * VDIM + c]; }
#pragma unroll 4
    for (int t = t0; t < t0 + VTCH; ++t) {
        float xt = d_vpre[(size_t)t * VDIM + c];
        int st = d_flags[t] & 1;
        float acc = xt * w3;
        if (!st) {
            acc = fmaf(xm1, w2, acc);
            if (!st1) {
                acc = fmaf(xm2, w1, acc);
                if (!st2) acc = fmaf(xm3, w0, acc);
            }
        }
        d_v[(size_t)t * VDIM + c] = acc * sigmoidf_(acc);
        xm3 = xm2; xm2 = xm1; xm1 = xt;
        st2 = st1; st1 = st;
    }
}

// ---------------- q at the 16 pooled positions ----------------
__global__ void k_q16(const int* __restrict__ cu, const float* __restrict__ Wq,
                      const float* __restrict__ cw) {
    __shared__ float shn[4][HH];
    __shared__ float sq[KDIM];
    int s = blockIdx.x;
    int pos = cu[s + 1] - 1;
    int seg = d_seg[pos];
    int tid = threadIdx.x;
    int valid[4];
#pragma unroll
    for (int r = 0; r < 4; ++r) {
        int t = pos - r;
        valid[r] = (t >= 0 && d_seg[t] == seg);
    }
#pragma unroll
    for (int r = 0; r < 4; ++r) {
        int t = pos - r;
        if (valid[r]) for (int i = tid; i < HH; i += 256) shn[r][i] = d_hn[(size_t)t * HH + i];
        else          for (int i = tid; i < HH; i += 256) shn[r][i] = 0.f;
    }
    __syncthreads();
    for (int c = tid; c < KDIM; c += 256) {
        float a0 = 0.f, a1 = 0.f, a2 = 0.f, a3 = 0.f;
        for (int i = 0; i < HH; ++i) {
            float wv = Wq[(size_t)i * KDIM + c];
            a0 = fmaf(shn[0][i], wv, a0);
            a1 = fmaf(shn[1][i], wv, a1);
            a2 = fmaf(shn[2][i], wv, a2);
            a3 = fmaf(shn[3][i], wv, a3);
        }
        float acc = a0 * cw[c * 4 + 3] + a1 * cw[c * 4 + 2] + a2 * cw[c * 4 + 1] + a3 * cw[c * 4 + 0];
        sq[c] = acc * sigmoidf_(acc);
    }
    __syncthreads();
    int w = tid >> 5, lane = tid & 31;
    for (int h = w; h < NHH; h += 8) {
        float ssq = 0.f;
        for (int i = lane; i < HKD; i += 32) { float v = sq[h * HKD + i]; ssq = fmaf(v, v, ssq); }
#pragma unroll
        for (int off = 16; off; off >>= 1) ssq += __shfl_xor_sync(0xffffffffu, ssq, off);
        float r = rsqrtf(ssq + 1e-6f) * 0.125f;
        for (int i = lane; i < HKD; i += 32)
            d_q[s * KDIM + h * HKD + i] = sq[h * HKD + i] * r;
    }
}

// ---------------- segment-parallel scan ----------------
__global__ void __launch_bounds__(256) k_scan(const int* __restrict__ cu) {
    __shared__ float  sk[2][SCH][64];
    __shared__ float  svv[2][SCH][64];
    __shared__ float2 sdb[2][SCH];
    __shared__ int    sfl[2][SCH];

    int half = blockIdx.x;
    int h    = blockIdx.y;
    int s    = blockIdx.z;
    int tid  = threadIdx.x;
    int colL = tid >> 2;
    int e    = tid & 3;
    int col  = half * 64 + colL;

    int start = cu[s];
    int end   = cu[s + 1];
    int len   = end - start;

    auto load_chunk = [&](int buf, int c0) {
        int rem = len - c0; if (rem > SCH) rem = SCH;
        for (int idx = tid; idx < rem * 16; idx += 256) {
            int i = idx >> 4, j = idx & 15;
            cpa16(&sk[buf][i][j * 4], d_k + (size_t)(start + c0 + i) * KDIM + h * HKD + j * 4);
        }
        for (int idx = tid; idx < rem * 16; idx += 256) {
            int i = idx >> 4, j = idx & 15;
            cpa16(&svv[buf][i][j * 4], d_v + (size_t)(start + c0 + i) * VDIM + h * HVD + half * 64 + j * 4);
        }
        if (tid < rem)
            cpa8(&sdb[buf][tid], d_db + (size_t)(start + c0 + tid) * NHH + h);
        if (tid >= 64 && tid - 64 < rem)
            cpa4(&sfl[buf][tid - 64], d_flags + start + c0 + tid - 64);
    };

    float S[16];
#pragma unroll
    for (int i = 0; i < 16; ++i) S[i] = 0.f;

    load_chunk(0, 0);
    CPA_COMMIT;

    int buf = 0;
    for (int c0 = 0; c0 < len; c0 += SCH, buf ^= 1) {
        __syncthreads();
        if (c0 + SCH < len) load_chunk(buf ^ 1, c0 + SCH);
        CPA_COMMIT;
        CPA_WAIT1;
        __syncthreads();

        int rem = len - c0; if (rem > SCH) rem = SCH;

        float4 nk0 = *(const float4*)&sk[buf][0][e * 16 + 0];
        float4 nk1 = *(const float4*)&sk[buf][0][e * 16 + 4];
        float4 nk2 = *(const float4*)&sk[buf][0][e * 16 + 8];
        float4 nk3 = *(const float4*)&sk[buf][0][e * 16 + 12];
        float  nv  = svv[buf][0][colL];
        float2 ndb = sdb[buf][0];
        int    nfl = sfl[buf][0];

        for (int i = 0; i < rem; ++i) {
            float4 k0 = nk0, k1 = nk1, k2 = nk2, k3 = nk3;
            float  vv = nv;
            float2 db = ndb;
            int    fl = nfl;
            int ip = (i + 1 < rem) ? i + 1 : i;
            nk0 = *(const float4*)&sk[buf][ip][e * 16 + 0];
            nk1 = *(const float4*)&sk[buf][ip][e * 16 + 4];
            nk2 = *(const float4*)&sk[buf][ip][e * 16 + 8];
            nk3 = *(const float4*)&sk[buf][ip][e * 16 + 12];
            nv  = svv[buf][ip][colL];
            ndb = sdb[buf][ip];
            nfl = sfl[buf][ip];

            float lam = (fl & 1) ? 0.f : db.x;

            float a0 = S[0]  * k0.x;
            a0 = fmaf(S[1],  k0.y, a0);
            a0 = fmaf(S[2],  k0.z, a0);
            a0 = fmaf(S[3],  k0.w, a0);
            float a1 = S[4]  * k1.x;
            a1 = fmaf(S[5],  k1.y, a1);
            a1 = fmaf(S[6],  k1.z, a1);
            a1 = fmaf(S[7],  k1.w, a1);
            float a2 = S[8]  * k2.x;
            a2 = fmaf(S[9],  k2.y, a2);
            a2 = fmaf(S[10], k2.z, a2);
            a2 = fmaf(S[11], k2.w, a2);
            float a3 = S[12] * k3.x;
            a3 = fmaf(S[13], k3.y, a3);
            a3 = fmaf(S[14], k3.z, a3);
            a3 = fmaf(S[15], k3.w, a3);
            float dot = (a0 + a1) + (a2 + a3);
            dot += __shfl_xor_sync(0xffffffffu, dot, 1);
            dot += __shfl_xor_sync(0xffffffffu, dot, 2);

            float delta = db.y * fmaf(-lam, dot, vv);

            S[0]  = fmaf(lam, S[0],  k0.x * delta);
            S[1]  = fmaf(lam, S[1],  k0.y * delta);
            S[2]  = fmaf(lam, S[2],  k0.z * delta);
            S[3]  = fmaf(lam, S[3],  k0.w * delta);
            S[4]  = fmaf(lam, S[4],  k1.x * delta);
            S[5]  = fmaf(lam, S[5],  k1.y * delta);
            S[6]  = fmaf(lam, S[6],  k1.z * delta);
            S[7]  = fmaf(lam, S[7],  k1.w * delta);
            S[8]  = fmaf(lam, S[8],  k2.x * delta);
            S[9]  = fmaf(lam, S[9],  k2.y * delta);
            S[10] = fmaf(lam, S[10], k2.z * delta);
            S[11] = fmaf(lam, S[11], k2.w * delta);
            S[12] = fmaf(lam, S[12], k3.x * delta);
            S[13] = fmaf(lam, S[13], k3.y * delta);
            S[14] = fmaf(lam, S[14], k3.z * delta);
            S[15] = fmaf(lam, S[15], k3.w * delta);

            int need = fl >> 1;
            if (need) {
                const float* qp = d_q + (size_t)(need - 1) * KDIM + h * HKD + e * 16;
                float4 q0 = *(const float4*)(qp + 0);
                float4 q1 = *(const float4*)(qp + 4);
                float4 q2 = *(const float4*)(qp + 8);
                float4 q3 = *(const float4*)(qp + 12);
                float od = S[0] * q0.x;
                od = fmaf(S[1],  q0.y, od);
                od = fmaf(S[2],  q0.z, od);
                od = fmaf(S[3],  q0.w, od);
                od = fmaf(S[4],  q1.x, od);
                od = fmaf(S[5],  q1.y, od);
                od = fmaf(S[6],  q1.z, od);
                od = fmaf(S[7],  q1.w, od);
                od = fmaf(S[8],  q2.x, od);
                od = fmaf(S[9],  q2.y, od);
                od = fmaf(S[10], q2.z, od);
                od = fmaf(S[11], q2.w, od);
                od = fmaf(S[12], q3.x, od);
                od = fmaf(S[13], q3.y, od);
                od = fmaf(S[14], q3.z, od);
                od = fmaf(S[15], q3.w, od);
                od += __shfl_xor_sync(0xffffffffu, od, 1);
                od += __shfl_xor_sync(0xffffffffu, od, 2);
                if (e == 0) d_o[(need - 1) * VDIM + h * HVD + col] = od;
            }
        }
    }
}

// ---------------- Wo @ W_head ----------------
__global__ void k_wowh(const float* __restrict__ Wo, const float* __restrict__ Wh) {
    int j = blockIdx.x * 8 + (threadIdx.x >> 5);
    int lane = threadIdx.x & 31;
    float a = 0.f;
    for (int k = lane; k < HH; k += 32) a = fmaf(Wo[(size_t)j * HH + k], Wh[k], a);
#pragma unroll
    for (int off = 16; off; off >>= 1) a += __shfl_xor_sync(0xffffffffu, a, off);
    if (lane == 0) d_wowh[j] = a;
}

// ---------------- gating at pooled positions ----------------
__global__ void k_gate(const int* __restrict__ cu, const float* __restrict__ Wg,
                       const float* __restrict__ onw) {
    __shared__ float shn[HH];
    __shared__ float sred[128];
    int hd = blockIdx.x;
    int s = blockIdx.y;
    int pos = cu[s + 1] - 1;
    int tid = threadIdx.x;
    for (int i = tid; i < HH; i += 128) shn[i] = d_hn[(size_t)pos * HH + i];
    __syncthreads();
    float gate = 0.f;
    for (int i = 0; i < HH; ++i)
        gate = fmaf(shn[i], Wg[(size_t)i * VDIM + hd * HVD + tid], gate);
    float ov = d_o[s * VDIM + hd * HVD + tid];
    sred[tid] = ov * ov;
    __syncthreads();
    for (int st = 64; st; st >>= 1) {
        if (tid < st) sred[tid] += sred[tid + st];
        __syncthreads();
    }
    float rms = rsqrtf(sred[0] / (float)HVD + 1e-5f);
    float gs = gate * sigmoidf_(gate);
    d_og[s * VDIM + hd * HVD + tid] = ov * rms * onw[tid] * gs;
}

// ---------------- final head ----------------
__global__ void k_final(const float* __restrict__ Wh, const float* __restrict__ bh,
                        float* __restrict__ out) {
    __shared__ float sred[256];
    int s = blockIdx.x;
    int tid = threadIdx.x;
    float a = 0.f;
    for (int j = tid; j < VDIM; j += 256) a = fmaf(d_og[s * VDIM + j], d_wowh[j], a);
    for (int k = tid; k < HH; k += 256) a = fmaf(d_hrows[s * HH + k], Wh[k], a);
    sred[tid] = a;
    __syncthreads();
    for (int st = 128; st; st >>= 1) {
        if (tid < st) sred[tid] += sred[tid + st];
        __syncthreads();
    }
    if (tid == 0) out[s] = sred[0] + bh[0];
}

// ---------------- launch ----------------
extern "C" void kernel_launch(void* const* d_in, const int* in_sizes, int n_in,
                              void* d_out, int out_size) {
    const float* x     = (const float*)d_in[0];
    const int*   cu    = (const int*)d_in[1];
    const int*   acidx = (const int*)d_in[2];
    const float* actab = (const float*)d_in[3];
    const float* Win   = (const float*)d_in[4];
    const float* bin   = (const float*)d_in[5];
    const float* nw    = (const float*)d_in[6];
    const float* Wq    = (const float*)d_in[7];
    const float* Wk    = (const float*)d_in[8];
    const float* Wv    = (const float*)d_in[9];
    const float* cqw   = (const float*)d_in[10];
    const float* ckw   = (const float*)d_in[11];
    const float* cvw   = (const float*)d_in[12];
    const float* Wb    = (const float*)d_in[13];
    const float* Wa    = (const float*)d_in[14];
    const float* Alog  = (const float*)d_in[15];
    const float* dtb   = (const float*)d_in[16];
    const float* Wg    = (const float*)d_in[17];
    const float* onw   = (const float*)d_in[18];
    const float* Wo    = (const float*)d_in[19];
    const float* Wh    = (const float*)d_in[20];
    const float* bh    = (const float*)d_in[21];
    float* out = (float*)d_out;

    cudaFuncSetAttribute(k_mma, cudaFuncAttributeMaxDynamicSharedMemorySize, MM_SMEM);

    __half *wkf, *wvf, *hnf;
    cudaGetSymbolAddress((void**)&wkf, d_wkf);
    cudaGetSymbolAddress((void**)&wvf, d_wvf);
    cudaGetSymbolAddress((void**)&hnf, d_hnf);
    float *kpre, *vpre;
    cudaGetSymbolAddress((void**)&kpre, d_kpre);
    cudaGetSymbolAddress((void**)&vpre, d_vpre);

    k_prep<<<TT / 256, 256>>>(cu);
    k_embed<<<TT / 8, 256>>>(x, acidx, actab, Win, bin, nw);

    k_wcvt<<<dim3(KDIM / 32, HH / 32), dim3(32, 8)>>>(Wk, wkf, KDIM);
    k_wcvt<<<dim3(VDIM / 32, HH / 32), dim3(32, 8)>>>(Wv, wvf, VDIM);

    k_mma<<<dim3(KDIM / 128, TT / 128), 256, MM_SMEM>>>(hnf, wkf, kpre, KDIM);
    k_mma<<<dim3(VDIM / 128, TT / 128), 256, MM_SMEM>>>(hnf, wvf, vpre, VDIM);

    k_ab<<<TT / 8, 256>>>(Wa, Wb, Alog, dtb);
    k_convk<<<dim3(KDIM / 256, TT / 16), 256>>>(ckw);
    k_conv2<<<dim3(VDIM / 256, TT / VTCH), 256>>>(cvw);
    k_q16<<<NSEG, 256>>>(cu, Wq, cqw);

    k_scan<<<dim3(2, NHH, NSEG), 256>>>(cu);

    k_wowh<<<VDIM / 8, 256>>>(Wo, Wh);
    k_gate<<<dim3(NHH, NSEG), 128>>>(cu, Wg, onw);
    k_final<<<NSEG, 256>>>(Wh, bh, out);
}

// round 8
// speedup vs baseline: 7.9844x; 1.1242x over previous
#include <cuda_runtime.h>
#include <cuda_fp16.h>
#include <math.h>
#include <stdint.h>

#define TT   32768
#define HH   1024
#define DIN  16
#define ACD  32
#define NHH  12
#define KDIM 768
#define VDIM 1536
#define HKD  64
#define HVD  128
#define NSEG 16
#define SCH  40

// ---------------- scratch ----------------
static __device__ float  d_hn   [TT * HH];
static __device__ __half d_hnf  [TT * HH];
static __device__ __half d_wkf  [KDIM * HH];
static __device__ __half d_wvf  [VDIM * HH];
static __device__ float  d_kpre [TT * KDIM];
static __device__ float  d_vpre [TT * VDIM];
static __device__ float  d_k    [TT * KDIM];
static __device__ float  d_v    [TT * VDIM];
static __device__ float4 d_scd  [TT * NHH];     // (lam, beta, needf, 0)
static __device__ int    d_seg  [TT];
static __device__ int    d_flags[TT];
static __device__ float  d_hrows[NSEG * HH];
static __device__ float  d_q    [NSEG * KDIM];
static __device__ float  d_o    [NSEG * VDIM];
static __device__ float  d_og   [NSEG * VDIM];
static __device__ float  d_wowh [VDIM];

__device__ __forceinline__ float sigmoidf_(float x) { return 1.f / (1.f + expf(-x)); }

// ---------------- PTX helpers (base sm_103 features only) ----------------
__device__ __forceinline__ uint32_t smem_u32(const void* p) {
    uint32_t a;
    asm("{ .reg .u64 t; cvta.to.shared.u64 t, %1; cvt.u32.u64 %0, t; }" : "=r"(a) : "l"(p));
    return a;
}
__device__ __forceinline__ void cpa16s(uint32_t s, const void* g) {
    asm volatile("cp.async.cg.shared.global [%0], [%1], 16;" :: "r"(s), "l"(g));
}
__device__ __forceinline__ void cpa16(void* s, const void* g) { cpa16s(smem_u32(s), g); }
#define CPA_COMMIT asm volatile("cp.async.commit_group;")
#define CPA_WAIT0  asm volatile("cp.async.wait_group 0;")
#define CPA_WAIT1  asm volatile("cp.async.wait_group 1;")

#define LDM4(r, addr) \
    asm volatile("ldmatrix.sync.aligned.m8n8.x4.shared.b16 {%0,%1,%2,%3}, [%4];" \
        : "=r"((r)[0]), "=r"((r)[1]), "=r"((r)[2]), "=r"((r)[3]) : "r"(addr))

#define MMAH(d, a, b0, b1) \
    asm volatile("mma.sync.aligned.m16n8k16.row.col.f32.f16.f16.f32 " \
        "{%0,%1,%2,%3}, {%4,%5,%6,%7}, {%8,%9}, {%0,%1,%2,%3};" \
        : "+f"((d)[0]), "+f"((d)[1]), "+f"((d)[2]), "+f"((d)[3]) \
        : "r"((a)[0]), "r"((a)[1]), "r"((a)[2]), "r"((a)[3]), "r"(b0), "r"(b1))

// packed fp32x2 (Blackwell base ISA, sm_100+)
#define FMA2(d, a, b, c) asm("fma.rn.f32x2 %0, %1, %2, %3;" : "=l"(d) : "l"(a), "l"(b), "l"(c))
#define MUL2(d, a, b)    asm("mul.rn.f32x2 %0, %1, %2;" : "=l"(d) : "l"(a), "l"(b))
#define ADD2(d, a, b)    asm("add.rn.f32x2 %0, %1, %2;" : "=l"(d) : "l"(a), "l"(b))
#define PACKF2(d, lo, hi) asm("mov.b64 %0, {%1, %2};" : "=l"(d) : "f"(lo), "f"(hi))
#define UNPACKF2(lo, hi, s) asm("mov.b64 {%0, %1}, %2;" : "=f"(lo), "=f"(hi) : "l"(s))
#define LDSV2U64(a, b, addr) \
    asm volatile("ld.shared.v2.b64 {%0, %1}, [%2];" : "=l"(a), "=l"(b) : "r"(addr))

// ---------------- seg ids + flags ----------------
__global__ void k_prep(const int* __restrict__ cu) {
    int t = blockIdx.x * 256 + threadIdx.x;
    if (t >= TT) return;
    int seg = 0;
#pragma unroll
    for (int s = 1; s <= NSEG; ++s) if (t >= cu[s]) seg = s;
    d_seg[t] = seg;
    int fl = (t == cu[seg]) ? 1 : 0;
#pragma unroll
    for (int s = 0; s < NSEG; ++s) if (t == cu[s + 1] - 1) fl |= ((s + 1) << 1);
    d_flags[t] = fl;
}

// ---------------- embed + rmsnorm + fp16 conversion ----------------
__global__ void k_embed(const float* __restrict__ x, const int* __restrict__ acidx,
                        const float* __restrict__ actab, const float* __restrict__ Win,
                        const float* __restrict__ bin, const float* __restrict__ nw) {
    __shared__ float sx[8][48];
    __shared__ float sps[8][256];
    __shared__ float srms[8];
    int t0 = blockIdx.x * 8;
    int tid = threadIdx.x;
    for (int idx = tid; idx < 8 * 48; idx += 256) {
        int r = idx / 48, i = idx % 48;
        int t = t0 + r;
        float v;
        if (i < DIN) v = x[t * DIN + i];
        else v = actab[acidx[d_seg[t]] * ACD + (i - DIN)];
        sx[r][i] = v;
    }
    __syncthreads();

    float hreg[4][8];
    float ps[8];
#pragma unroll
    for (int r = 0; r < 8; ++r) ps[r] = 0.f;

#pragma unroll
    for (int jj = 0; jj < 4; ++jj) {
        int j = tid + jj * 256;
        float acc[8];
        float bb = bin[j];
#pragma unroll
        for (int r = 0; r < 8; ++r) acc[r] = bb;
        for (int i = 0; i < 48; ++i) {
            float w = Win[i * HH + j];
#pragma unroll
            for (int r = 0; r < 8; ++r) acc[r] = fmaf(sx[r][i], w, acc[r]);
        }
#pragma unroll
        for (int r = 0; r < 8; ++r) { hreg[jj][r] = acc[r]; ps[r] = fmaf(acc[r], acc[r], ps[r]); }
    }
#pragma unroll
    for (int r = 0; r < 8; ++r) sps[r][tid] = ps[r];
    __syncthreads();
    int w = tid >> 5, lane = tid & 31;
    float s = sps[w][lane];
#pragma unroll
    for (int i = 1; i < 8; ++i) s += sps[w][lane + 32 * i];
#pragma unroll
    for (int off = 16; off; off >>= 1) s += __shfl_xor_sync(0xffffffffu, s, off);
    if (lane == 0) srms[w] = rsqrtf(s / (float)HH + 1e-6f);
    __syncthreads();

    int needr[8];
#pragma unroll
    for (int r = 0; r < 8; ++r) needr[r] = d_flags[t0 + r] >> 1;

#pragma unroll
    for (int jj = 0; jj < 4; ++jj) {
        int j = tid + jj * 256;
        float nwj = 1.0f + nw[j];
#pragma unroll
        for (int r = 0; r < 8; ++r) {
            int t = t0 + r;
            float val = hreg[jj][r] * srms[r] * nwj;
            d_hn[t * HH + j] = val;
            d_hnf[(size_t)t * HH + j] = __float2half(val);
            if (needr[r]) d_hrows[(needr[r] - 1) * HH + j] = hreg[jj][r];
        }
    }
}

// ---------------- weight transpose + fp16 ----------------
__global__ void k_wcvt(const float* __restrict__ W, __half* __restrict__ outw, int N) {
    __shared__ float tile[32][33];
    int n0 = blockIdx.x * 32, k0 = blockIdx.y * 32;
    int tx = threadIdx.x, ty = threadIdx.y;
    for (int i = ty; i < 32; i += 8)
        tile[i][tx] = W[(size_t)(k0 + i) * N + n0 + tx];
    __syncthreads();
    for (int i = ty; i < 32; i += 8)
        outw[(size_t)(n0 + i) * HH + k0 + tx] = __float2half(tile[tx][i]);
}

// ---------------- fp16 mma.sync GEMM ----------------
#define MM_ROW   40
#define MM_ATEN  (128 * MM_ROW)
#define MM_BTEN  (128 * MM_ROW)
#define MM_STG   (MM_ATEN + MM_BTEN)
#define MM_NSTG  3
#define MM_SMEM  (MM_NSTG * MM_STG * 2)
#define MM_NCH   (HH / 32)

__global__ void __launch_bounds__(256, 2)
k_mma(const __half* __restrict__ A_, const __half* __restrict__ B_,
      float* __restrict__ C, int N) {
    extern __shared__ __align__(128) __half sm[];
    uint32_t sb = smem_u32(sm);
    int tid = threadIdx.x, lane = tid & 31, wid = tid >> 5;
    int wm = wid & 1, wn = wid >> 1;
    int ntile = blockIdx.x, mtile = blockIdx.y;

    const __half* Af = A_ + (size_t)(mtile * 128) * HH;
    const __half* Bf = B_ + (size_t)(ntile * 128) * HH;

    float acc[4][4][4];
#pragma unroll
    for (int m = 0; m < 4; ++m)
#pragma unroll
        for (int n = 0; n < 4; ++n)
#pragma unroll
            for (int i = 0; i < 4; ++i) acc[m][n][i] = 0.f;

    int ab[4];
#pragma unroll
    for (int m = 0; m < 4; ++m)
        ab[m] = (wm * 64 + m * 16 + (lane & 15)) * MM_ROW + (lane >> 4) * 8;
    int bb[2];
#pragma unroll
    for (int p = 0; p < 2; ++p)
        bb[p] = (wn * 32 + p * 16 + (lane & 7) + ((lane >> 4) & 1) * 8) * MM_ROW + ((lane >> 3) & 1) * 8;

    auto load_stage = [&](int stg, int k0) {
        uint32_t base = sb + 2 * (stg * MM_STG);
#pragma unroll
        for (int it = 0; it < 2; ++it) {
            int idx = tid + it * 256;
            int r = idx >> 2, cc = idx & 3;
            cpa16s(base + 2 * (r * MM_ROW + cc * 8), Af + (size_t)r * HH + k0 + cc * 8);
        }
#pragma unroll
        for (int it = 0; it < 2; ++it) {
            int idx = tid + it * 256;
            int r = idx >> 2, cc = idx & 3;
            cpa16s(base + 2 * (MM_ATEN + r * MM_ROW + cc * 8), Bf + (size_t)r * HH + k0 + cc * 8);
        }
    };

    load_stage(0, 0);
    CPA_COMMIT;
    load_stage(1, 32);
    CPA_COMMIT;

    for (int c = 0; c < MM_NCH; ++c) {
        int stg = c % MM_NSTG;
        if (c + 1 < MM_NCH) { CPA_WAIT1; } else { CPA_WAIT0; }
        __syncthreads();
        if (c + 2 < MM_NCH) {
            load_stage((c + 2) % MM_NSTG, (c + 2) * 32);
            CPA_COMMIT;
        }

        uint32_t base = sb + 2 * (stg * MM_STG);
#pragma unroll
        for (int ks = 0; ks < 2; ++ks) {
            uint32_t a4[4][4];
#pragma unroll
            for (int m = 0; m < 4; ++m) LDM4(a4[m], base + 2 * (ab[m] + ks * 16));
#pragma unroll
            for (int p = 0; p < 2; ++p) {
                uint32_t rb[4];
                LDM4(rb, base + 2 * (MM_ATEN + bb[p] + ks * 16));
#pragma unroll
                for (int m = 0; m < 4; ++m) {
                    MMAH(acc[m][2 * p],     a4[m], rb[0], rb[1]);
                    MMAH(acc[m][2 * p + 1], a4[m], rb[2], rb[3]);
                }
            }
        }
        __syncthreads();
    }

#pragma unroll
    for (int m = 0; m < 4; ++m) {
        int row = mtile * 128 + wm * 64 + m * 16 + (lane >> 2);
#pragma unroll
        for (int n = 0; n < 4; ++n) {
            int col = ntile * 128 + wn * 32 + n * 8 + (lane & 3) * 2;
            float2 v0 = make_float2(acc[m][n][0], acc[m][n][1]);
            float2 v1 = make_float2(acc[m][n][2], acc[m][n][3]);
            *(float2*)&C[(size_t)row * N + col] = v0;
            *(float2*)&C[(size_t)(row + 8) * N + col] = v1;
        }
    }
}

// ---------------- hn@Wa, hn@Wb -> (lam, beta, need) ----------------
__global__ void k_ab(const float* __restrict__ Wa, const float* __restrict__ Wb,
                     const float* __restrict__ Alog, const float* __restrict__ dtb) {
    int row = blockIdx.x * 8 + (threadIdx.x >> 5);
    int lane = threadIdx.x & 31;
    float aA[NHH], aB[NHH];
#pragma unroll
    for (int c = 0; c < NHH; ++c) { aA[c] = 0.f; aB[c] = 0.f; }
    for (int kk = lane; kk < HH; kk += 32) {
        float hv = d_hn[(size_t)row * HH + kk];
        const float* wa = Wa + kk * NHH;
        const float* wb = Wb + kk * NHH;
#pragma unroll
        for (int c = 0; c < NHH; ++c) {
            aA[c] = fmaf(hv, wa[c], aA[c]);
            aB[c] = fmaf(hv, wb[c], aB[c]);
        }
    }
#pragma unroll
    for (int c = 0; c < NHH; ++c) {
#pragma unroll
        for (int off = 16; off; off >>= 1) {
            aA[c] += __shfl_xor_sync(0xffffffffu, aA[c], off);
            aB[c] += __shfl_xor_sync(0xffffffffu, aB[c], off);
        }
    }
    if (lane < NHH) {
        float xx = aA[lane] + dtb[lane];
        float sp = (xx > 20.f) ? xx : log1pf(expf(xx));
        float g = -expf(Alog[lane]) * sp;
        int fl = d_flags[row];
        float4 o;
        o.x = (fl & 1) ? 0.f : expf(g);          // lam (start folded)
        o.y = sigmoidf_(aB[lane]);               // beta
        o.z = (float)(fl >> 1);                  // need index + 1 (0 = none)
        o.w = 0.f;
        d_scd[(size_t)row * NHH + lane] = o;
    }
}

// ---------------- k-path streaming conv + silu + per-head l2norm ----------------
__global__ void k_convk(const float* __restrict__ cw) {
    __shared__ float sv[16][256];
    __shared__ float sred[8][16];
    int tid = threadIdx.x;
    int c = blockIdx.x * 256 + tid;
    int t0 = blockIdx.y * 16;
    float w0 = cw[c * 4 + 0], w1 = cw[c * 4 + 1], w2 = cw[c * 4 + 2], w3 = cw[c * 4 + 3];
    float xm1 = 0.f, xm2 = 0.f, xm3 = 0.f;
    int st1 = 1, st2 = 1;
    if (t0 >= 1) { xm1 = d_kpre[(size_t)(t0 - 1) * KDIM + c]; st1 = d_flags[t0 - 1] & 1; }
    if (t0 >= 2) { xm2 = d_kpre[(size_t)(t0 - 2) * KDIM + c]; st2 = d_flags[t0 - 2] & 1; }
    if (t0 >= 3) { xm3 = d_kpre[(size_t)(t0 - 3) * KDIM + c]; }
#pragma unroll 4
    for (int tt = 0; tt < 16; ++tt) {
        int t = t0 + tt;
        float xt = d_kpre[(size_t)t * KDIM + c];
        int st = d_flags[t] & 1;
        float acc = xt * w3;
        if (!st) {
            acc = fmaf(xm1, w2, acc);
            if (!st1) {
                acc = fmaf(xm2, w1, acc);
                if (!st2) acc = fmaf(xm3, w0, acc);
            }
        }
        sv[tt][tid] = acc * sigmoidf_(acc);
        xm3 = xm2; xm2 = xm1; xm1 = xt;
        st2 = st1; st1 = st;
    }
    __syncthreads();
    int w = tid >> 5, lane = tid & 31;
#pragma unroll
    for (int tt = 0; tt < 16; ++tt) {
        float v = sv[tt][w * 32 + lane];
        float ssq = v * v;
#pragma unroll
        for (int off = 16; off; off >>= 1) ssq += __shfl_xor_sync(0xffffffffu, ssq, off);
        if (lane == 0) sred[w][tt] = ssq;
    }
    __syncthreads();
    int hl = tid >> 6;
#pragma unroll
    for (int tt = 0; tt < 16; ++tt) {
        float ss = sred[hl * 2][tt] + sred[hl * 2 + 1][tt];
        d_k[(size_t)(t0 + tt) * KDIM + c] = sv[tt][tid] * rsqrtf(ss + 1e-6f);
    }
}

// ---------------- v-path streaming conv + silu ----------------
#define VTCH 16
__global__ void k_conv2(const float* __restrict__ cw) {
    int c = blockIdx.x * 256 + threadIdx.x;
    int t0 = blockIdx.y * VTCH;
    float w0 = cw[c * 4 + 0], w1 = cw[c * 4 + 1], w2 = cw[c * 4 + 2], w3 = cw[c * 4 + 3];
    float xm1 = 0.f, xm2 = 0.f, xm3 = 0.f;
    int st1 = 1, st2 = 1;
    if (t0 >= 1) { xm1 = d_vpre[(size_t)(t0 - 1) * VDIM + c]; st1 = d_flags[t0 - 1] & 1; }
    if (t0 >= 2) { xm2 = d_vpre[(size_t)(t0 - 2) * VDIM + c]; st2 = d_flags[t0 - 2] & 1; }
    if (t0 >= 3) { xm3 = d_vpre[(size_t)(t0 - 3) * VDIM + c]; }
#pragma unroll 4
    for (int t = t0; t < t0 + VTCH; ++t) {
        float xt = d_vpre[(size_t)t * VDIM + c];
        int st = d_flags[t] & 1;
        float acc = xt * w3;
        if (!st) {
            acc = fmaf(xm1, w2, acc);
            if (!st1) {
                acc = fmaf(xm2, w1, acc);
                if (!st2) acc = fmaf(xm3, w0, acc);
            }
        }
        d_v[(size_t)t * VDIM + c] = acc * sigmoidf_(acc);
        xm3 = xm2; xm2 = xm1; xm1 = xt;
        st2 = st1; st1 = st;
    }
}

// ---------------- q at the 16 pooled positions ----------------
__global__ void k_q16(const int* __restrict__ cu, const float* __restrict__ Wq,
                      const float* __restrict__ cw) {
    __shared__ float shn[4][HH];
    __shared__ float sq[KDIM];
    int s = blockIdx.x;
    int pos = cu[s + 1] - 1;
    int seg = d_seg[pos];
    int tid = threadIdx.x;
    int valid[4];
#pragma unroll
    for (int r = 0; r < 4; ++r) {
        int t = pos - r;
        valid[r] = (t >= 0 && d_seg[t] == seg);
    }
#pragma unroll
    for (int r = 0; r < 4; ++r) {
        int t = pos - r;
        if (valid[r]) for (int i = tid; i < HH; i += 256) shn[r][i] = d_hn[(size_t)t * HH + i];
        else          for (int i = tid; i < HH; i += 256) shn[r][i] = 0.f;
    }
    __syncthreads();
    for (int c = tid; c < KDIM; c += 256) {
        float a0 = 0.f, a1 = 0.f, a2 = 0.f, a3 = 0.f;
        for (int i = 0; i < HH; ++i) {
            float wv = Wq[(size_t)i * KDIM + c];
            a0 = fmaf(shn[0][i], wv, a0);
            a1 = fmaf(shn[1][i], wv, a1);
            a2 = fmaf(shn[2][i], wv, a2);
            a3 = fmaf(shn[3][i], wv, a3);
        }
        float acc = a0 * cw[c * 4 + 3] + a1 * cw[c * 4 + 2] + a2 * cw[c * 4 + 1] + a3 * cw[c * 4 + 0];
        sq[c] = acc * sigmoidf_(acc);
    }
    __syncthreads();
    int w = tid >> 5, lane = tid & 31;
    for (int h = w; h < NHH; h += 8) {
        float ssq = 0.f;
        for (int i = lane; i < HKD; i += 32) { float v = sq[h * HKD + i]; ssq = fmaf(v, v, ssq); }
#pragma unroll
        for (int off = 16; off; off >>= 1) ssq += __shfl_xor_sync(0xffffffffu, ssq, off);
        float r = rsqrtf(ssq + 1e-6f) * 0.125f;
        for (int i = lane; i < HKD; i += 32)
            d_q[s * KDIM + h * HKD + i] = sq[h * HKD + i] * r;
    }
}

// ---------------- segment-parallel scan, packed f32x2 ----------------
// grid (2, 12, 16) = (col-half, head, seg), 128 threads = 64 cols x 2 lanes.
// Each lane owns 32 of 64 k-elems (16 packed pairs).
__global__ void __launch_bounds__(128) k_scan(const int* __restrict__ cu) {
    __shared__ float  sk[2][SCH][64];
    __shared__ float  svv[2][SCH][64];
    __shared__ float4 scd[2][SCH];

    int half = blockIdx.x;
    int h    = blockIdx.y;
    int s    = blockIdx.z;
    int tid  = threadIdx.x;
    int colL = tid >> 1;        // 0..63
    int e    = tid & 1;         // lane within column
    int col  = half * 64 + colL;

    int start = cu[s];
    int end   = cu[s + 1];
    int len   = end - start;

    auto load_chunk = [&](int buf, int c0) {
        int rem = len - c0; if (rem > SCH) rem = SCH;
        for (int idx = tid; idx < rem * 16; idx += 128) {
            int i = idx >> 4, j = idx & 15;
            cpa16(&sk[buf][i][j * 4], d_k + (size_t)(start + c0 + i) * KDIM + h * HKD + j * 4);
        }
        for (int idx = tid; idx < rem * 16; idx += 128) {
            int i = idx >> 4, j = idx & 15;
            cpa16(&svv[buf][i][j * 4], d_v + (size_t)(start + c0 + i) * VDIM + h * HVD + half * 64 + j * 4);
        }
        if (tid < rem)
            cpa16(&scd[buf][tid], d_scd + (size_t)(start + c0 + tid) * NHH + h);
    };

    uint64_t S2[16];
#pragma unroll
    for (int i = 0; i < 16; ++i) S2[i] = 0ull;

    load_chunk(0, 0);
    CPA_COMMIT;

    int buf = 0;
    for (int c0 = 0; c0 < len; c0 += SCH, buf ^= 1) {
        __syncthreads();
        if (c0 + SCH < len) load_chunk(buf ^ 1, c0 + SCH);
        CPA_COMMIT;
        CPA_WAIT1;
        __syncthreads();

        int rem = len - c0; if (rem > SCH) rem = SCH;

        // prime step 0
        uint64_t nk[16];
#pragma unroll
        for (int j = 0; j < 8; ++j) {
            uint32_t addr = smem_u32(&sk[buf][0][e * 32 + j * 4]);
            LDSV2U64(nk[2 * j], nk[2 * j + 1], addr);
        }
        float  nv  = svv[buf][0][colL];
        float4 ncd = scd[buf][0];

        for (int i = 0; i < rem; ++i) {
            uint64_t K2[16];
#pragma unroll
            for (int j = 0; j < 16; ++j) K2[j] = nk[j];
            float  vv = nv;
            float4 cd = ncd;
            int ip = (i + 1 < rem) ? i + 1 : i;
#pragma unroll
            for (int j = 0; j < 8; ++j) {
                uint32_t addr = smem_u32(&sk[buf][ip][e * 32 + j * 4]);
                LDSV2U64(nk[2 * j], nk[2 * j + 1], addr);
            }
            nv  = svv[buf][ip][colL];
            ncd = scd[buf][ip];

            // dot = k . S (this lane's 32 elems), packed
            uint64_t a0 = 0ull, a1 = 0ull;
#pragma unroll
            for (int j = 0; j < 16; j += 2) {
                FMA2(a0, S2[j],     K2[j],     a0);
                FMA2(a1, S2[j + 1], K2[j + 1], a1);
            }
            ADD2(a0, a0, a1);
            float lo, hi;
            UNPACKF2(lo, hi, a0);
            float dot = lo + hi;
            dot += __shfl_xor_sync(0xffffffffu, dot, 1);

            float lam = cd.x;
            float delta = cd.y * fmaf(-lam, dot, vv);
            uint64_t lam2, d2;
            PACKF2(lam2, lam, lam);
            PACKF2(d2, delta, delta);
#pragma unroll
            for (int j = 0; j < 16; ++j) {
                uint64_t t;
                MUL2(t, K2[j], d2);
                FMA2(S2[j], lam2, S2[j], t);
            }

            if (cd.z != 0.f) {
                int need = (int)cd.z - 1;
                const float4* qp = (const float4*)(d_q + (size_t)need * KDIM + h * HKD + e * 32);
                uint64_t oa = 0ull;
#pragma unroll
                for (int j = 0; j < 8; ++j) {
                    float4 qv = qp[j];
                    uint64_t q0, q1;
                    PACKF2(q0, qv.x, qv.y);
                    PACKF2(q1, qv.z, qv.w);
                    FMA2(oa, S2[2 * j],     q0, oa);
                    FMA2(oa, S2[2 * j + 1], q1, oa);
                }
                float olo, ohi;
                UNPACKF2(olo, ohi, oa);
                float od = olo + ohi;
                od += __shfl_xor_sync(0xffffffffu, od, 1);
                if (e == 0) d_o[need * VDIM + h * HVD + col] = od;
            }
        }
    }
}

// ---------------- Wo @ W_head ----------------
__global__ void k_wowh(const float* __restrict__ Wo, const float* __restrict__ Wh) {
    int j = blockIdx.x * 8 + (threadIdx.x >> 5);
    int lane = threadIdx.x & 31;
    float a = 0.f;
    for (int k = lane; k < HH; k += 32) a = fmaf(Wo[(size_t)j * HH + k], Wh[k], a);
#pragma unroll
    for (int off = 16; off; off >>= 1) a += __shfl_xor_sync(0xffffffffu, a, off);
    if (lane == 0) d_wowh[j] = a;
}

// ---------------- gating at pooled positions ----------------
__global__ void k_gate(const int* __restrict__ cu, const float* __restrict__ Wg,
                       const float* __restrict__ onw) {
    __shared__ float shn[HH];
    __shared__ float sred[128];
    int hd = blockIdx.x;
    int s = blockIdx.y;
    int pos = cu[s + 1] - 1;
    int tid = threadIdx.x;
    for (int i = tid; i < HH; i += 128) shn[i] = d_hn[(size_t)pos * HH + i];
    __syncthreads();
    float gate = 0.f;
    for (int i = 0; i < HH; ++i)
        gate = fmaf(shn[i], Wg[(size_t)i * VDIM + hd * HVD + tid], gate);
    float ov = d_o[s * VDIM + hd * HVD + tid];
    sred[tid] = ov * ov;
    __syncthreads();
    for (int st = 64; st; st >>= 1) {
        if (tid < st) sred[tid] += sred[tid + st];
        __syncthreads();
    }
    float rms = rsqrtf(sred[0] / (float)HVD + 1e-5f);
    float gs = gate * sigmoidf_(gate);
    d_og[s * VDIM + hd * HVD + tid] = ov * rms * onw[tid] * gs;
}

// ---------------- final head ----------------
__global__ void k_final(const float* __restrict__ Wh, const float* __restrict__ bh,
                        float* __restrict__ out) {
    __shared__ float sred[256];
    int s = blockIdx.x;
    int tid = threadIdx.x;
    float a = 0.f;
    for (int j = tid; j < VDIM; j += 256) a = fmaf(d_og[s * VDIM + j], d_wowh[j], a);
    for (int k = tid; k < HH; k += 256) a = fmaf(d_hrows[s * HH + k], Wh[k], a);
    sred[tid] = a;
    __syncthreads();
    for (int st = 128; st; st >>= 1) {
        if (tid < st) sred[tid] += sred[tid + st];
        __syncthreads();
    }
    if (tid == 0) out[s] = sred[0] + bh[0];
}

// ---------------- launch ----------------
extern "C" void kernel_launch(void* const* d_in, const int* in_sizes, int n_in,
                              void* d_out, int out_size) {
    const float* x     = (const float*)d_in[0];
    const int*   cu    = (const int*)d_in[1];
    const int*   acidx = (const int*)d_in[2];
    const float* actab = (const float*)d_in[3];
    const float* Win   = (const float*)d_in[4];
    const float* bin   = (const float*)d_in[5];
    const float* nw    = (const float*)d_in[6];
    const float* Wq    = (const float*)d_in[7];
    const float* Wk    = (const float*)d_in[8];
    const float* Wv    = (const float*)d_in[9];
    const float* cqw   = (const float*)d_in[10];
    const float* ckw   = (const float*)d_in[11];
    const float* cvw   = (const float*)d_in[12];
    const float* Wb    = (const float*)d_in[13];
    const float* Wa    = (const float*)d_in[14];
    const float* Alog  = (const float*)d_in[15];
    const float* dtb   = (const float*)d_in[16];
    const float* Wg    = (const float*)d_in[17];
    const float* onw   = (const float*)d_in[18];
    const float* Wo    = (const float*)d_in[19];
    const float* Wh    = (const float*)d_in[20];
    const float* bh    = (const float*)d_in[21];
    float* out = (float*)d_out;

    cudaFuncSetAttribute(k_mma, cudaFuncAttributeMaxDynamicSharedMemorySize, MM_SMEM);

    __half *wkf, *wvf, *hnf;
    cudaGetSymbolAddress((void**)&wkf, d_wkf);
    cudaGetSymbolAddress((void**)&wvf, d_wvf);
    cudaGetSymbolAddress((void**)&hnf, d_hnf);
    float *kpre, *vpre;
    cudaGetSymbolAddress((void**)&kpre, d_kpre);
    cudaGetSymbolAddress((void**)&vpre, d_vpre);

    k_prep<<<TT / 256, 256>>>(cu);
    k_embed<<<TT / 8, 256>>>(x, acidx, actab, Win, bin, nw);

    // V path first so k_mma(V) lands at the ncu capture slot
    k_wcvt<<<dim3(VDIM / 32, HH / 32), dim3(32, 8)>>>(Wv, wvf, VDIM);
    k_mma<<<dim3(VDIM / 128, TT / 128), 256, MM_SMEM>>>(hnf, wvf, vpre, VDIM);
    k_wcvt<<<dim3(KDIM / 32, HH / 32), dim3(32, 8)>>>(Wk, wkf, KDIM);
    k_mma<<<dim3(KDIM / 128, TT / 128), 256, MM_SMEM>>>(hnf, wkf, kpre, KDIM);

    k_ab<<<TT / 8, 256>>>(Wa, Wb, Alog, dtb);
    k_convk<<<dim3(KDIM / 256, TT / 16), 256>>>(ckw);
    k_conv2<<<dim3(VDIM / 256, TT / VTCH), 256>>>(cvw);
    k_q16<<<NSEG, 256>>>(cu, Wq, cqw);

    k_scan<<<dim3(2, NHH, NSEG), 128>>>(cu);

    k_wowh<<<VDIM / 8, 256>>>(Wo, Wh);
    k_gate<<<dim3(NHH, NSEG), 128>>>(cu, Wg, onw);
    k_final<<<NSEG, 256>>>(Wh, bh, out);
}